// round 2
// baseline (speedup 1.0000x reference)
#include <cuda_runtime.h>
#include <cuda_bf16.h>
#include <cstdint>

#define NNODE 4096
#define FIN   4096
#define H1    120
#define HEADS 4
#define H1P   30
#define H2    50

// ---------------- scratch (static device globals; no allocation) ----------------
__device__ float g_wh1[NNODE * H1];
__device__ float g_hmid[NNODE * H1];
__device__ float g_wh2[NNODE * H2];
__device__ float g_h2[NNODE * H2];
__device__ float g_f1a[HEADS * NNODE], g_f2a[HEADS * NNODE];
__device__ float g_Ca[HEADS * NNODE], g_Ba[HEADS * NNODE], g_Da[HEADS * NNODE];
__device__ float g_f1b[NNODE], g_f2b[NNODE];
__device__ float g_Cb[NNODE], g_Bb[NNODE], g_Db[NNODE];

__device__ __forceinline__ float leakyf(float x) { return fmaxf(x, 0.1f * x); }

// ---------------- GEMM1: wh1[n][c] = sum_f x[n][f] * W1[h][f][o], c=h*30+o ----
// M=4096, N=120 (padded 128), K=4096.  BM=32, BN=128, BK=32, 256 thr, 4x4 tiles.
__global__ void gemm1_kernel(const float* __restrict__ x,
                             const float* __restrict__ W1,
                             float* __restrict__ wh) {
    __shared__ float As[32][36];   // [k][m], padded for LDS.128 alignment
    __shared__ float Bs[32][128];  // [k][c]
    const int tid = threadIdx.x;
    const int m0 = blockIdx.x * 32;
    const int tx = tid & 31, ty = tid >> 5;

    float acc[4][4];
#pragma unroll
    for (int i = 0; i < 4; i++)
#pragma unroll
        for (int j = 0; j < 4; j++) acc[i][j] = 0.f;

    // B-load mapping: each thread owns one padded column, 16 k's
    const int cB = tid & 127;
    const int kB = (tid >> 7) << 4;  // 0 or 16
    const int hB = cB / 30, oB = cB % 30;
    const bool cOK = (cB < 120);
    const float* wbase = W1 + (size_t)hB * FIN * H1P + oB;

    // A-load mapping
    const int rA = tid >> 3;
    const int cA = (tid & 7) * 4;

    for (int k0 = 0; k0 < FIN; k0 += 32) {
        float4 av = *(const float4*)(x + (size_t)(m0 + rA) * FIN + k0 + cA);
        As[cA + 0][rA] = av.x; As[cA + 1][rA] = av.y;
        As[cA + 2][rA] = av.z; As[cA + 3][rA] = av.w;
#pragma unroll
        for (int q = 0; q < 16; q++) {
            float v = 0.f;
            if (cOK) v = wbase[(size_t)(k0 + kB + q) * H1P];
            Bs[kB + q][cB] = v;
        }
        __syncthreads();
#pragma unroll
        for (int k = 0; k < 32; k++) {
            float4 a = *(const float4*)&As[k][ty * 4];
            float4 b = *(const float4*)&Bs[k][tx * 4];
            float aa[4] = {a.x, a.y, a.z, a.w};
            float bb[4] = {b.x, b.y, b.z, b.w};
#pragma unroll
            for (int i = 0; i < 4; i++)
#pragma unroll
                for (int j = 0; j < 4; j++) acc[i][j] = fmaf(aa[i], bb[j], acc[i][j]);
        }
        __syncthreads();
    }
#pragma unroll
    for (int i = 0; i < 4; i++)
#pragma unroll
        for (int j = 0; j < 4; j++) {
            int c = tx * 4 + j;
            if (c < 120) wh[(size_t)(m0 + ty * 4 + i) * H1 + c] = acc[i][j];
        }
}

// ---------------- f1/f2 + factored exponentials ----------------
__global__ void fcalc_kernel(const float* __restrict__ wh, int ldwh, int ncol,
                             const float* __restrict__ asrc, const float* __restrict__ adst,
                             int total,
                             float* __restrict__ f1r, float* __restrict__ f2r,
                             float* __restrict__ Cb, float* __restrict__ Bb,
                             float* __restrict__ Db) {
    int g = blockIdx.x * blockDim.x + threadIdx.x;
    if (g >= total) return;
    int h = g >> 12;
    int n = g & 4095;
    const float* base = wh + (size_t)n * ldwh + h * ncol;
    const float* as_ = asrc + h * ncol;
    const float* ad_ = adst + h * ncol;
    float f1 = 0.f, f2 = 0.f;
    for (int o = 0; o < ncol; o++) {
        float v = base[o];
        f1 = fmaf(v, as_[o], f1);
        f2 = fmaf(v, ad_[o], f2);
    }
    f1r[g] = f1;
    f2r[g] = f2;
    // clamps only guard against pathological overflow; never hit for this data
    Cb[g] = expf(fminf(-0.9f * f1, 70.f));
    Bb[g] = expf(fminf(f2, 70.f));
    Db[g] = expf(0.1f * fminf(f2, 70.f));
}

// ---------------- fused masked-softmax attention (exact softmax via factored p) --
// out[i][colofs+c] = leaky( (sum_j p_ij wh[j][colofs+c]) / (sum_j p_ij) + bias[colofs+c] )
// p_ij = adj_ij ? ( (f1_i+f2_j >= 0) ? B_j : C_i * D_j ) : 0
template <int NCOL, int CXN, int TY, int RPT>
__global__ void attn_kernel(const float* __restrict__ wh, int ldwh,
                            const float* __restrict__ f1r, const float* __restrict__ f2r,
                            const float* __restrict__ Cb, const float* __restrict__ Bb,
                            const float* __restrict__ Db,
                            const int* __restrict__ adj,
                            const float* __restrict__ bias,
                            float* __restrict__ out, int ldout) {
    constexpr int TI = TY * RPT;
    constexpr int TJ = 32;
    constexpr int NTHR = CXN * TY;
    constexpr int HCOL = NCOL / 2;

    const int h = blockIdx.y;
    const int i0 = blockIdx.x * TI;
    const int colofs = h * NCOL;
    const int fo = h * NNODE;

    __shared__ float ps[TI][TJ + 1];
    __shared__ float whs[TJ][NCOL];
    __shared__ float f1s[TI], Cs[TI], zsh[TI];
    __shared__ float Bsh[TJ], Dsh[TJ], f2sh[TJ];

    const int tid = threadIdx.x;
    const int cx = tid % CXN;
    const int ty = tid / CXN;

    if (tid < TI) {
        f1s[tid] = f1r[fo + i0 + tid];
        Cs[tid] = Cb[fo + i0 + tid];
    }

    float acc0[RPT], acc1[RPT];
#pragma unroll
    for (int r = 0; r < RPT; r++) { acc0[r] = 0.f; acc1[r] = 0.f; }

    for (int j0 = 0; j0 < NNODE; j0 += TJ) {
        __syncthreads();
        if (tid < TJ) {
            Bsh[tid] = Bb[fo + j0 + tid];
            Dsh[tid] = Db[fo + j0 + tid];
            f2sh[tid] = f2r[fo + j0 + tid];
        }
        for (int idx = tid; idx < TJ * NCOL; idx += NTHR) {
            int jj = idx / NCOL, o = idx % NCOL;
            whs[jj][o] = wh[(size_t)(j0 + jj) * ldwh + colofs + o];
        }
        __syncthreads();
        for (int idx = tid; idx < TI * TJ; idx += NTHR) {
            int jj = idx & (TJ - 1);
            int ii = idx >> 5;
            int a = adj[(size_t)(i0 + ii) * NNODE + j0 + jj];
            float s = f1s[ii] + f2sh[jj];
            float v = (s >= 0.f) ? Bsh[jj] : Cs[ii] * Dsh[jj];
            ps[ii][jj] = (a > 0) ? v : 0.f;
        }
        __syncthreads();
#pragma unroll 4
        for (int jj = 0; jj < TJ; jj++) {
            float w0, w1;
            if (cx < HCOL) {
                float2 w = *(const float2*)&whs[jj][2 * cx];
                w0 = w.x; w1 = w.y;
            } else {
                w0 = (cx == HCOL) ? 1.f : 0.f;  // Z accumulator column
                w1 = 0.f;
            }
#pragma unroll
            for (int r = 0; r < RPT; r++) {
                float p = ps[ty * RPT + r][jj];
                acc0[r] = fmaf(p, w0, acc0[r]);
                acc1[r] = fmaf(p, w1, acc1[r]);
            }
        }
    }
    __syncthreads();
    if (cx == HCOL) {
#pragma unroll
        for (int r = 0; r < RPT; r++) zsh[ty * RPT + r] = acc0[r];
    }
    __syncthreads();
    if (cx < HCOL) {
        float b0 = bias[colofs + 2 * cx];
        float b1 = bias[colofs + 2 * cx + 1];
#pragma unroll
        for (int r = 0; r < RPT; r++) {
            int lr = ty * RPT + r;
            int row = i0 + lr;
            float invz = 1.f / zsh[lr];
            float v0 = leakyf(fmaf(acc0[r], invz, b0));
            float v1 = leakyf(fmaf(acc1[r], invz, b1));
            out[(size_t)row * ldout + colofs + 2 * cx] = v0;
            out[(size_t)row * ldout + colofs + 2 * cx + 1] = v1;
        }
    }
}

// ---------------- GEMM2: wh2 = hmid(4096x120) @ W2(120x50) ----------------
__global__ void gemm2_kernel(const float* __restrict__ hmid,
                             const float* __restrict__ W2,
                             float* __restrict__ wh2) {
    __shared__ float hs[4][120];
    const int n0 = blockIdx.x * 4;
    const int tid = threadIdx.x;
    for (int idx = tid; idx < 4 * 120; idx += blockDim.x)
        hs[idx / 120][idx % 120] = hmid[(size_t)(n0 + idx / 120) * H1 + (idx % 120)];
    __syncthreads();
    if (tid < 200) {
        int r = tid / 50, c = tid % 50;
        float acc = 0.f;
#pragma unroll 8
        for (int k = 0; k < 120; k++) acc = fmaf(hs[r][k], W2[k * 50 + c], acc);
        wh2[(size_t)(n0 + r) * H2 + c] = acc;
    }
}

// ---------------- FiLM + gating + classifier logits ----------------
__global__ void film_kernel(const float* __restrict__ h2,
                            const float* __restrict__ lloc,
                            const float* __restrict__ Wl1, const float* __restrict__ bl1,
                            const float* __restrict__ Wl2, const float* __restrict__ bl2,
                            const float* __restrict__ Wg, const float* __restrict__ bg,
                            const float* __restrict__ Wb, const float* __restrict__ bb,
                            const float* __restrict__ Wgate, const float* __restrict__ bgate,
                            const float* __restrict__ Wc,
                            float* __restrict__ outlogits) {
    int n = blockIdx.x * blockDim.x + threadIdx.x;
    if (n >= NNODE) return;
    float l[16];
#pragma unroll
    for (int k = 0; k < 16; k++) l[k] = lloc[n * 16 + k];
    float z1[32];
#pragma unroll
    for (int j = 0; j < 32; j++) {
        float a = bl1[j];
#pragma unroll
        for (int k = 0; k < 16; k++) a = fmaf(l[k], Wl1[j * 16 + k], a);
        z1[j] = leakyf(a);
    }
    float z2[32];
#pragma unroll
    for (int j = 0; j < 32; j++) {
        float a = bl2[j];
#pragma unroll
        for (int k = 0; k < 32; k++) a = fmaf(z1[k], Wl2[j * 32 + k], a);
        z2[j] = leakyf(a);
    }
    float ga = bgate[0];
#pragma unroll
    for (int k = 0; k < 32; k++) ga = fmaf(z2[k], Wgate[k], ga);
    float g = 1.f / (1.f + expf(-ga));
    float cov = fminf(fmaxf(l[15], 0.f), 1.f);
    g *= cov;

    float l0 = 0.f, l1 = 0.f;
    for (int c = 0; c < 50; c++) {
        float gm = bg[c], bt = bb[c];
#pragma unroll
        for (int k = 0; k < 32; k++) {
            gm = fmaf(z2[k], Wg[c * 32 + k], gm);
            bt = fmaf(z2[k], Wb[c * 32 + k], bt);
        }
        float hv = h2[(size_t)n * H2 + c];
        float hf = hv + g * fmaf(gm, hv, bt);
        l0 = fmaf(hf, Wc[c], l0);
        l1 = fmaf(hf, Wc[50 + c], l1);
    }
    outlogits[n * 2 + 0] = leakyf(l0);
    outlogits[n * 2 + 1] = leakyf(l1);
}

// ---------------- hemisphere SSDB: single block, warp-cooperative dots ----------
__global__ void hemi_kernel(float* __restrict__ out,
                            const float* __restrict__ Ws1, const float* __restrict__ bs1,
                            const float* __restrict__ Ws2, const float* __restrict__ bs2) {
    __shared__ float hs[240];
    __shared__ float bsm[4];
    const int tid = threadIdx.x;
    const int lane = tid & 31;
    const int wrp = tid >> 5;
    const int nw = blockDim.x >> 5;

    for (int oidx = wrp; oidx < 240; oidx += nw) {
        int hemi = oidx / 120;
        int cls = (oidx / 60) % 2;
        int k = oidx % 60;
        const float* lg = out + (size_t)hemi * 2048 * 2 + cls;
        const float* w = Ws1 + (size_t)k * 2048;
        float acc = 0.f;
        for (int m = lane; m < 2048; m += 32) acc = fmaf(lg[m * 2], w[m], acc);
#pragma unroll
        for (int off = 16; off; off >>= 1) acc += __shfl_xor_sync(0xffffffffu, acc, off);
        if (lane == 0) hs[oidx] = leakyf(acc + bs1[k]);
    }
    __syncthreads();
    if (tid < 4) {
        int hemi = tid >> 1, cls = tid & 1;
        float acc = bs2[0];
#pragma unroll
        for (int k = 0; k < 60; k++) acc = fmaf(hs[hemi * 120 + cls * 60 + k], Ws2[k], acc);
        bsm[hemi * 2 + cls] = leakyf(acc);
    }
    __syncthreads();
    for (int idx = tid; idx < NNODE * 2; idx += blockDim.x) {
        int n = idx >> 1, cls = idx & 1;
        int hemi = (n >= 2048) ? 1 : 0;
        out[idx] += bsm[hemi * 2 + cls];
    }
    if (tid < 2) out[NNODE * 2 + tid] = 0.5f * (bsm[tid] + bsm[2 + tid]);
}

// ---------------- host launch ----------------
extern "C" void kernel_launch(void* const* d_in, const int* in_sizes, int n_in,
                              void* d_out, int out_size) {
    const float* x_fc  = (const float*)d_in[0];
    const int*   adj   = (const int*)d_in[1];
    const float* lloc  = (const float*)d_in[2];
    const float* W1    = (const float*)d_in[3];
    const float* a1s   = (const float*)d_in[4];
    const float* a1d   = (const float*)d_in[5];
    const float* b1    = (const float*)d_in[6];
    const float* W2    = (const float*)d_in[7];
    const float* a2s   = (const float*)d_in[8];
    const float* a2d   = (const float*)d_in[9];
    const float* b2    = (const float*)d_in[10];
    const float* Wc    = (const float*)d_in[11];
    const float* Wl1   = (const float*)d_in[12];
    const float* bl1   = (const float*)d_in[13];
    const float* Wl2   = (const float*)d_in[14];
    const float* bl2   = (const float*)d_in[15];
    const float* Wg    = (const float*)d_in[16];
    const float* bg    = (const float*)d_in[17];
    const float* Wb    = (const float*)d_in[18];
    const float* bb    = (const float*)d_in[19];
    const float* Wgate = (const float*)d_in[20];
    const float* bgate = (const float*)d_in[21];
    const float* Ws1   = (const float*)d_in[22];
    const float* bs1   = (const float*)d_in[23];
    const float* Ws2   = (const float*)d_in[24];
    const float* bs2   = (const float*)d_in[25];
    float* outp = (float*)d_out;

    float *wh1, *hmid, *wh2, *h2;
    float *f1a, *f2a, *Ca, *Ba, *Da, *f1b, *f2b, *Cb2, *Bb2, *Db2;
    cudaGetSymbolAddress((void**)&wh1, g_wh1);
    cudaGetSymbolAddress((void**)&hmid, g_hmid);
    cudaGetSymbolAddress((void**)&wh2, g_wh2);
    cudaGetSymbolAddress((void**)&h2, g_h2);
    cudaGetSymbolAddress((void**)&f1a, g_f1a);
    cudaGetSymbolAddress((void**)&f2a, g_f2a);
    cudaGetSymbolAddress((void**)&Ca, g_Ca);
    cudaGetSymbolAddress((void**)&Ba, g_Ba);
    cudaGetSymbolAddress((void**)&Da, g_Da);
    cudaGetSymbolAddress((void**)&f1b, g_f1b);
    cudaGetSymbolAddress((void**)&f2b, g_f2b);
    cudaGetSymbolAddress((void**)&Cb2, g_Cb);
    cudaGetSymbolAddress((void**)&Bb2, g_Bb);
    cudaGetSymbolAddress((void**)&Db2, g_Db);

    // 1) wh1 = x @ W1cat
    gemm1_kernel<<<NNODE / 32, 256>>>(x_fc, W1, wh1);
    // 2) attention-1 features
    fcalc_kernel<<<(HEADS * NNODE + 255) / 256, 256>>>(wh1, H1, H1P, a1s, a1d,
                                                       HEADS * NNODE, f1a, f2a, Ca, Ba, Da);
    // 3) GAT1 fused attention -> hmid = leaky(out + b1)
    attn_kernel<30, 16, 8, 8><<<dim3(NNODE / 64, HEADS), 128>>>(
        wh1, H1, f1a, f2a, Ca, Ba, Da, adj, b1, hmid, H1);
    // 4) wh2 = hmid @ W2
    gemm2_kernel<<<NNODE / 4, 256>>>(hmid, W2, wh2);
    // 5) attention-2 features
    fcalc_kernel<<<(NNODE + 255) / 256, 256>>>(wh2, H2, H2, a2s, a2d,
                                               NNODE, f1b, f2b, Cb2, Bb2, Db2);
    // 6) GAT2 fused attention -> h2 = leaky(out + b2)
    attn_kernel<50, 32, 8, 4><<<dim3(NNODE / 32, 1), 256>>>(
        wh2, H2, f1b, f2b, Cb2, Bb2, Db2, adj, b2, h2, H2);
    // 7) FiLM + classifier -> logits in d_out[0..8191]
    film_kernel<<<NNODE / 128, 128>>>(h2, lloc, Wl1, bl1, Wl2, bl2,
                                      Wg, bg, Wb, bb, Wgate, bgate, Wc, outp);
    // 8) hemisphere bias + bias_avg -> d_out[8192..8193]
    hemi_kernel<<<1, 256>>>(outp, Ws1, bs1, Ws2, bs2);
}

// round 5
// speedup vs baseline: 2.1746x; 2.1746x over previous
#include <cuda_runtime.h>
#include <cuda_bf16.h>
#include <cstdint>

#define NNODE 4096
#define FIN   4096
#define H1    120
#define HEADS 4
#define H1P   30
#define H2    50

// ---------------- scratch (static device globals; no allocation) ----------------
__device__ float g_wh1[NNODE * H1];
__device__ float g_hmid[NNODE * H1];
__device__ float g_wh2[NNODE * H2];
__device__ float g_h2[NNODE * H2];
__device__ float g_f1a[HEADS * NNODE], g_f2a[HEADS * NNODE];
__device__ float g_Ca[HEADS * NNODE], g_Ba[HEADS * NNODE], g_Da[HEADS * NNODE];
__device__ float g_f1b[NNODE], g_f2b[NNODE];
__device__ float g_Cb[NNODE], g_Bb[NNODE], g_Db[NNODE];
__device__ unsigned char g_adj8[NNODE * NNODE];   // 16MB packed adjacency
__device__ float g_part[2 * NNODE * 64];          // attn2 j-split partials
__device__ float g_hs[240];                       // hemi hidden

__device__ __forceinline__ float leakyf(float x) { return fmaxf(x, 0.1f * x); }

// ---------------- pack adj int32 -> uint8 ----------------
__global__ void pack_adj_kernel(const int4* __restrict__ adj, uchar4* __restrict__ out, int n4) {
    int i = blockIdx.x * blockDim.x + threadIdx.x;
    if (i >= n4) return;
    int4 v = adj[i];
    out[i] = make_uchar4(v.x ? 1 : 0, v.y ? 1 : 0, v.z ? 1 : 0, v.w ? 1 : 0);
}

// ---------------- GEMM1: wh1[n][c] = sum_f x[n][f] * W1[h][f][o], c=h*30+o ----
// BM=32, BN=64, BK=32, 128 threads, 4x4 microtile, reg-staged double buffer.
__global__ void gemm1_kernel(const float* __restrict__ x,
                             const float* __restrict__ W1,
                             float* __restrict__ wh) {
    __shared__ float As[32][36];   // [k][m]
    __shared__ float Bs[32][64];   // [k][c]
    const int tid = threadIdx.x;
    const int m0 = blockIdx.x * 32;
    const int n0 = blockIdx.y * 64;
    const int tx = tid & 15, ty = tid >> 4;

    // A loader: rows rA, rA+16; cols cA..cA+3
    const int rA = tid >> 3;
    const int cA = (tid & 7) * 4;
    // B loader: one column, 16 k's
    const int cB = tid & 63;
    const int kB = (tid >> 6) << 4;  // 0 or 16
    const int c = n0 + cB;
    const bool cOK = (c < H1);
    const int hB = cOK ? (c / 30) : 0;
    const int oB = cOK ? (c % 30) : 0;
    const float* wbase = W1 + (size_t)hB * FIN * H1P + oB;

    float acc[4][4];
#pragma unroll
    for (int i = 0; i < 4; i++)
#pragma unroll
        for (int j = 0; j < 4; j++) acc[i][j] = 0.f;

    // stage k0 = 0
    float4 aP0 = *(const float4*)(x + (size_t)(m0 + rA) * FIN + cA);
    float4 aP1 = *(const float4*)(x + (size_t)(m0 + rA + 16) * FIN + cA);
    float bP[16];
#pragma unroll
    for (int q = 0; q < 16; q++)
        bP[q] = cOK ? wbase[(size_t)(kB + q) * H1P] : 0.f;

    for (int k0 = 0; k0 < FIN; k0 += 32) {
        As[cA + 0][rA] = aP0.x; As[cA + 1][rA] = aP0.y;
        As[cA + 2][rA] = aP0.z; As[cA + 3][rA] = aP0.w;
        As[cA + 0][rA + 16] = aP1.x; As[cA + 1][rA + 16] = aP1.y;
        As[cA + 2][rA + 16] = aP1.z; As[cA + 3][rA + 16] = aP1.w;
#pragma unroll
        for (int q = 0; q < 16; q++) Bs[kB + q][cB] = bP[q];
        __syncthreads();

        if (k0 + 32 < FIN) {
            aP0 = *(const float4*)(x + (size_t)(m0 + rA) * FIN + k0 + 32 + cA);
            aP1 = *(const float4*)(x + (size_t)(m0 + rA + 16) * FIN + k0 + 32 + cA);
#pragma unroll
            for (int q = 0; q < 16; q++)
                bP[q] = cOK ? wbase[(size_t)(k0 + 32 + kB + q) * H1P] : 0.f;
        }
#pragma unroll
        for (int k = 0; k < 32; k++) {
            float4 a = *(const float4*)&As[k][ty * 4];
            float4 b = *(const float4*)&Bs[k][tx * 4];
            float aa[4] = {a.x, a.y, a.z, a.w};
            float bb[4] = {b.x, b.y, b.z, b.w};
#pragma unroll
            for (int i = 0; i < 4; i++)
#pragma unroll
                for (int j = 0; j < 4; j++) acc[i][j] = fmaf(aa[i], bb[j], acc[i][j]);
        }
        __syncthreads();
    }
#pragma unroll
    for (int i = 0; i < 4; i++)
#pragma unroll
        for (int j = 0; j < 4; j++) {
            int cc = n0 + tx * 4 + j;
            if (cc < H1) wh[(size_t)(m0 + ty * 4 + i) * H1 + cc] = acc[i][j];
        }
}

// ---------------- f1/f2 + factored exponentials ----------------
__global__ void fcalc_kernel(const float* __restrict__ wh, int ldwh, int ncol,
                             const float* __restrict__ asrc, const float* __restrict__ adst,
                             int total,
                             float* __restrict__ f1r, float* __restrict__ f2r,
                             float* __restrict__ Cb, float* __restrict__ Bb,
                             float* __restrict__ Db) {
    int g = blockIdx.x * blockDim.x + threadIdx.x;
    if (g >= total) return;
    int h = g >> 12;
    int n = g & 4095;
    const float* base = wh + (size_t)n * ldwh + h * ncol;
    const float* as_ = asrc + h * ncol;
    const float* ad_ = adst + h * ncol;
    float f1 = 0.f, f2 = 0.f;
    for (int o = 0; o < ncol; o++) {
        float v = base[o];
        f1 = fmaf(v, as_[o], f1);
        f2 = fmaf(v, ad_[o], f2);
    }
    f1r[g] = f1;
    f2r[g] = f2;
    Cb[g] = expf(fminf(-0.9f * f1, 70.f));
    Bb[g] = expf(fminf(f2, 70.f));
    Db[g] = expf(0.1f * fminf(f2, 70.f));
}

// ---------------- fused masked-softmax attention (factored exact softmax) -------
// p_ij = adj_ij ? ( (f1_i+f2_j >= 0) ? B_j : C_i * D_j ) : 0
// Each thread: RPT rows x 4 cols. Z column (=1) accumulates the normalizer.
template <int NCOL, int CXN, int TY, int RPT, int JS>
__global__ void attn_kernel(const float* __restrict__ wh, int ldwh,
                            const float* __restrict__ f1r, const float* __restrict__ f2r,
                            const float* __restrict__ Cb, const float* __restrict__ Bb,
                            const float* __restrict__ Db,
                            const unsigned char* __restrict__ adj8,
                            const float* __restrict__ bias,
                            float* __restrict__ dst, int lddst) {
    constexpr int TI = TY * RPT;
    constexpr int TJ = 32;
    constexpr int NTHR = CXN * TY;
    constexpr int CP4 = CXN * 4;
    constexpr int ZCOL = NCOL;

    const int h = blockIdx.y;
    const int i0 = blockIdx.x * TI;
    const int js = blockIdx.z;
    const int jbeg = js * (NNODE / JS);
    const int jend = jbeg + NNODE / JS;
    const int fo = h * NNODE;
    const int colofs = h * NCOL;

    __shared__ float ps[TI][TJ + 1];
    __shared__ float whs[TJ][CP4];
    __shared__ float f1s[TI], Cs[TI], zsh[TI];

    const int tid = threadIdx.x;
    const int cx = tid % CXN;
    const int ty = tid / CXN;

    if (tid < TI) {
        f1s[tid] = f1r[fo + i0 + tid];
        Cs[tid] = Cb[fo + i0 + tid];
    }

    float acc[RPT][4];
#pragma unroll
    for (int r = 0; r < RPT; r++)
#pragma unroll
        for (int k = 0; k < 4; k++) acc[r][k] = 0.f;

    for (int j0 = jbeg; j0 < jend; j0 += TJ) {
        __syncthreads();  // prev gemm done; first iter: f1s/Cs visible
        // load wh tile (Z column = 1, pad = 0)
        for (int idx = tid; idx < TJ * CP4; idx += NTHR) {
            int jj = idx / CP4, o = idx % CP4;
            float v;
            if (o < NCOL) v = wh[(size_t)(j0 + jj) * ldwh + colofs + o];
            else v = (o == ZCOL) ? 1.f : 0.f;
            whs[jj][o] = v;
        }
        // build p tile (quads: uchar4 adj + float4 B/D/f2)
        for (int q = tid; q < TI * (TJ / 4); q += NTHR) {
            int ii = q / (TJ / 4);
            int jq = q % (TJ / 4);
            int j = j0 + jq * 4;
            uchar4 a = *(const uchar4*)(adj8 + (size_t)(i0 + ii) * NNODE + j);
            float4 Bv = *(const float4*)(Bb + fo + j);
            float4 Dv = *(const float4*)(Db + fo + j);
            float4 f2v = *(const float4*)(f2r + fo + j);
            float f1 = f1s[ii], C = Cs[ii];
            ps[ii][jq * 4 + 0] = a.x ? ((f1 + f2v.x >= 0.f) ? Bv.x : C * Dv.x) : 0.f;
            ps[ii][jq * 4 + 1] = a.y ? ((f1 + f2v.y >= 0.f) ? Bv.y : C * Dv.y) : 0.f;
            ps[ii][jq * 4 + 2] = a.z ? ((f1 + f2v.z >= 0.f) ? Bv.z : C * Dv.z) : 0.f;
            ps[ii][jq * 4 + 3] = a.w ? ((f1 + f2v.w >= 0.f) ? Bv.w : C * Dv.w) : 0.f;
        }
        __syncthreads();
#pragma unroll 8
        for (int jj = 0; jj < TJ; jj++) {
            float4 w = *(const float4*)&whs[jj][cx * 4];
#pragma unroll
            for (int r = 0; r < RPT; r++) {
                float p = ps[ty * RPT + r][jj];
                acc[r][0] = fmaf(p, w.x, acc[r][0]);
                acc[r][1] = fmaf(p, w.y, acc[r][1]);
                acc[r][2] = fmaf(p, w.z, acc[r][2]);
                acc[r][3] = fmaf(p, w.w, acc[r][3]);
            }
        }
    }

    if (JS == 1) {
        __syncthreads();
        if (cx == ZCOL / 4) {
#pragma unroll
            for (int r = 0; r < RPT; r++) zsh[ty * RPT + r] = acc[r][ZCOL % 4];
        }
        __syncthreads();
#pragma unroll
        for (int r = 0; r < RPT; r++) {
            int lr = ty * RPT + r;
            int row = i0 + lr;
            float invz = 1.f / zsh[lr];
#pragma unroll
            for (int k = 0; k < 4; k++) {
                int cc = cx * 4 + k;
                if (cc < NCOL)
                    dst[(size_t)row * lddst + colofs + cc] =
                        leakyf(fmaf(acc[r][k], invz, bias[colofs + cc]));
            }
        }
    } else {
        // write raw partials (incl. Z) to part buffer [js][row][CP4]
#pragma unroll
        for (int r = 0; r < RPT; r++) {
            int row = i0 + ty * RPT + r;
            float* p = dst + ((size_t)js * NNODE + row) * CP4 + cx * 4;
            p[0] = acc[r][0]; p[1] = acc[r][1]; p[2] = acc[r][2]; p[3] = acc[r][3];
        }
    }
}

// ---------------- combine attn2 partials ----------------
__global__ void combine2_kernel(const float* __restrict__ part,
                                const float* __restrict__ bias,
                                float* __restrict__ h2out) {
    int idx = blockIdx.x * blockDim.x + threadIdx.x;
    if (idx >= NNODE * H2) return;
    int row = idx / H2, c = idx % H2;
    const float* p0 = part + (size_t)row * 64;
    const float* p1 = part + ((size_t)NNODE + row) * 64;
    float z = p0[50] + p1[50];
    float v = (p0[c] + p1[c]) / z + bias[c];
    h2out[(size_t)row * H2 + c] = leakyf(v);
}

// ---------------- GEMM2: wh2 = hmid(4096x120) @ W2(120x50) ----------------
__global__ void gemm2_kernel(const float* __restrict__ hmid,
                             const float* __restrict__ W2,
                             float* __restrict__ wh2) {
    __shared__ float hs[4][120];
    const int n0 = blockIdx.x * 4;
    const int tid = threadIdx.x;
    for (int idx = tid; idx < 4 * 120; idx += blockDim.x)
        hs[idx / 120][idx % 120] = hmid[(size_t)(n0 + idx / 120) * H1 + (idx % 120)];
    __syncthreads();
    if (tid < 200) {
        int r = tid / 50, c = tid % 50;
        float acc = 0.f;
#pragma unroll 8
        for (int k = 0; k < 120; k++) acc = fmaf(hs[r][k], W2[k * 50 + c], acc);
        wh2[(size_t)(n0 + r) * H2 + c] = acc;
    }
}

// ---------------- FiLM + gating + classifier logits ----------------
__global__ void film_kernel(const float* __restrict__ h2,
                            const float* __restrict__ lloc,
                            const float* __restrict__ Wl1, const float* __restrict__ bl1,
                            const float* __restrict__ Wl2, const float* __restrict__ bl2,
                            const float* __restrict__ Wg, const float* __restrict__ bg,
                            const float* __restrict__ Wb, const float* __restrict__ bb,
                            const float* __restrict__ Wgate, const float* __restrict__ bgate,
                            const float* __restrict__ Wc,
                            float* __restrict__ outlogits) {
    int n = blockIdx.x * blockDim.x + threadIdx.x;
    if (n >= NNODE) return;
    float l[16];
#pragma unroll
    for (int k = 0; k < 16; k++) l[k] = lloc[n * 16 + k];
    float z1[32];
#pragma unroll
    for (int j = 0; j < 32; j++) {
        float a = bl1[j];
#pragma unroll
        for (int k = 0; k < 16; k++) a = fmaf(l[k], Wl1[j * 16 + k], a);
        z1[j] = leakyf(a);
    }
    float z2[32];
#pragma unroll
    for (int j = 0; j < 32; j++) {
        float a = bl2[j];
#pragma unroll
        for (int k = 0; k < 32; k++) a = fmaf(z1[k], Wl2[j * 32 + k], a);
        z2[j] = leakyf(a);
    }
    float ga = bgate[0];
#pragma unroll
    for (int k = 0; k < 32; k++) ga = fmaf(z2[k], Wgate[k], ga);
    float g = 1.f / (1.f + expf(-ga));
    float cov = fminf(fmaxf(l[15], 0.f), 1.f);
    g *= cov;

    float l0 = 0.f, l1 = 0.f;
    for (int c = 0; c < 50; c++) {
        float gm = bg[c], bt = bb[c];
#pragma unroll
        for (int k = 0; k < 32; k++) {
            gm = fmaf(z2[k], Wg[c * 32 + k], gm);
            bt = fmaf(z2[k], Wb[c * 32 + k], bt);
        }
        float hv = h2[(size_t)n * H2 + c];
        float hf = hv + g * fmaf(gm, hv, bt);
        l0 = fmaf(hf, Wc[c], l0);
        l1 = fmaf(hf, Wc[50 + c], l1);
    }
    outlogits[n * 2 + 0] = leakyf(l0);
    outlogits[n * 2 + 1] = leakyf(l1);
}

// ---------------- hemisphere SSDB ----------------
__global__ void hemi_dots_kernel(const float* __restrict__ out,
                                 const float* __restrict__ Ws1,
                                 const float* __restrict__ bs1,
                                 float* __restrict__ hs) {
    const int b = blockIdx.x;                // 0..239
    const int hemi = b / 120;
    const int cls = (b / 60) % 2;
    const int k = b % 60;
    const int tid = threadIdx.x;
    const float* lg = out + (size_t)hemi * 2048 * 2 + cls;
    const float* w = Ws1 + (size_t)k * 2048;
    float acc = 0.f;
    for (int m = tid; m < 2048; m += 128) acc = fmaf(lg[2 * m], w[m], acc);
#pragma unroll
    for (int off = 16; off; off >>= 1) acc += __shfl_xor_sync(0xffffffffu, acc, off);
    __shared__ float red[4];
    if ((tid & 31) == 0) red[tid >> 5] = acc;
    __syncthreads();
    if (tid == 0)
        hs[b] = leakyf(red[0] + red[1] + red[2] + red[3] + bs1[k]);
}

__global__ void hemi_fin_kernel(float* __restrict__ out,
                                const float* __restrict__ hs,
                                const float* __restrict__ Ws2,
                                const float* __restrict__ bs2) {
    __shared__ float bsm[4];
    const int tid = threadIdx.x;
    if (tid < 4) {
        int hemi = tid >> 1, cls = tid & 1;
        float acc = bs2[0];
#pragma unroll
        for (int k = 0; k < 60; k++) acc = fmaf(hs[hemi * 120 + cls * 60 + k], Ws2[k], acc);
        bsm[hemi * 2 + cls] = leakyf(acc);
    }
    __syncthreads();
    for (int idx = tid; idx < NNODE * 2; idx += blockDim.x) {
        int n = idx >> 1, cls = idx & 1;
        int hemi = (n >= 2048) ? 1 : 0;
        out[idx] += bsm[hemi * 2 + cls];
    }
    if (tid < 2) out[NNODE * 2 + tid] = 0.5f * (bsm[tid] + bsm[2 + tid]);
}

// ---------------- host launch ----------------
extern "C" void kernel_launch(void* const* d_in, const int* in_sizes, int n_in,
                              void* d_out, int out_size) {
    const float* x_fc  = (const float*)d_in[0];
    const int*   adj   = (const int*)d_in[1];
    const float* lloc  = (const float*)d_in[2];
    const float* W1    = (const float*)d_in[3];
    const float* a1s   = (const float*)d_in[4];
    const float* a1d   = (const float*)d_in[5];
    const float* b1    = (const float*)d_in[6];
    const float* W2    = (const float*)d_in[7];
    const float* a2s   = (const float*)d_in[8];
    const float* a2d   = (const float*)d_in[9];
    const float* b2    = (const float*)d_in[10];
    const float* Wc    = (const float*)d_in[11];
    const float* Wl1   = (const float*)d_in[12];
    const float* bl1   = (const float*)d_in[13];
    const float* Wl2   = (const float*)d_in[14];
    const float* bl2   = (const float*)d_in[15];
    const float* Wg    = (const float*)d_in[16];
    const float* bg    = (const float*)d_in[17];
    const float* Wb    = (const float*)d_in[18];
    const float* bb    = (const float*)d_in[19];
    const float* Wgate = (const float*)d_in[20];
    const float* bgate = (const float*)d_in[21];
    const float* Ws1   = (const float*)d_in[22];
    const float* bs1   = (const float*)d_in[23];
    const float* Ws2   = (const float*)d_in[24];
    const float* bs2   = (const float*)d_in[25];
    float* outp = (float*)d_out;

    float *wh1, *hmid, *wh2, *h2, *part, *hsb;
    float *f1a, *f2a, *Ca, *Ba, *Da, *f1b, *f2b, *Cb2, *Bb2, *Db2;
    unsigned char* adj8;
    cudaGetSymbolAddress((void**)&wh1, g_wh1);
    cudaGetSymbolAddress((void**)&hmid, g_hmid);
    cudaGetSymbolAddress((void**)&wh2, g_wh2);
    cudaGetSymbolAddress((void**)&h2, g_h2);
    cudaGetSymbolAddress((void**)&f1a, g_f1a);
    cudaGetSymbolAddress((void**)&f2a, g_f2a);
    cudaGetSymbolAddress((void**)&Ca, g_Ca);
    cudaGetSymbolAddress((void**)&Ba, g_Ba);
    cudaGetSymbolAddress((void**)&Da, g_Da);
    cudaGetSymbolAddress((void**)&f1b, g_f1b);
    cudaGetSymbolAddress((void**)&f2b, g_f2b);
    cudaGetSymbolAddress((void**)&Cb2, g_Cb);
    cudaGetSymbolAddress((void**)&Bb2, g_Bb);
    cudaGetSymbolAddress((void**)&Db2, g_Db);
    cudaGetSymbolAddress((void**)&adj8, g_adj8);
    cudaGetSymbolAddress((void**)&part, g_part);
    cudaGetSymbolAddress((void**)&hsb, g_hs);

    // 0) pack adjacency to bytes (L2-resident afterwards)
    pack_adj_kernel<<<NNODE * NNODE / 4 / 256, 256>>>((const int4*)adj, (uchar4*)adj8,
                                                      NNODE * NNODE / 4);
    // 1) wh1 = x @ W1cat
    gemm1_kernel<<<dim3(NNODE / 32, 2), 128>>>(x_fc, W1, wh1);
    // 2) attention-1 features
    fcalc_kernel<<<(HEADS * NNODE) / 256, 256>>>(wh1, H1, H1P, a1s, a1d,
                                                 HEADS * NNODE, f1a, f2a, Ca, Ba, Da);
    // 3) GAT1 fused attention -> hmid
    attn_kernel<30, 8, 16, 4, 1><<<dim3(NNODE / 64, HEADS, 1), 128>>>(
        wh1, H1, f1a, f2a, Ca, Ba, Da, adj8, b1, hmid, H1);
    // 4) wh2 = hmid @ W2
    gemm2_kernel<<<NNODE / 4, 256>>>(hmid, W2, wh2);
    // 5) attention-2 features
    fcalc_kernel<<<NNODE / 256, 256>>>(wh2, H2, H2, a2s, a2d,
                                       NNODE, f1b, f2b, Cb2, Bb2, Db2);
    // 6) GAT2 fused attention (j-split 2) -> partials
    attn_kernel<50, 16, 8, 4, 2><<<dim3(NNODE / 32, 1, 2), 128>>>(
        wh2, H2, f1b, f2b, Cb2, Bb2, Db2, adj8, b2, part, 64);
    // 7) combine partials -> h2
    combine2_kernel<<<(NNODE * H2 + 255) / 256, 256>>>(part, b2, h2);
    // 8) FiLM + classifier -> logits in d_out[0..8191]
    film_kernel<<<NNODE / 128, 128>>>(h2, lloc, Wl1, bl1, Wl2, bl2,
                                      Wg, bg, Wb, bb, Wgate, bgate, Wc, outp);
    // 9) hemisphere bias
    hemi_dots_kernel<<<240, 128>>>(outp, Ws1, bs1, hsb);
    hemi_fin_kernel<<<1, 256>>>(outp, hsb, Ws2, bs2);
}

// round 6
// speedup vs baseline: 3.4951x; 1.6072x over previous
#include <cuda_runtime.h>
#include <cuda_bf16.h>
#include <cstdint>

#define NNODE 4096
#define FIN   4096
#define H1    120
#define HEADS 4
#define H1P   30
#define H2    50

// ---------------- scratch (static device globals; no allocation) ----------------
__device__ float g_wh1[NNODE * H1];
__device__ float g_hmid[NNODE * H1];
__device__ float g_wh2[NNODE * H2];
__device__ float g_h2[NNODE * H2];
__device__ float g_f1a[HEADS * NNODE], g_f2a[HEADS * NNODE];
__device__ float g_Ca[HEADS * NNODE], g_Ba[HEADS * NNODE], g_Da[HEADS * NNODE];
__device__ float g_f1b[NNODE], g_f2b[NNODE];
__device__ float g_Cb[NNODE], g_Bb[NNODE], g_Db[NNODE];
__device__ unsigned char g_adj8[NNODE * NNODE];     // 16MB packed adjacency
__device__ float g_part[4 * 8 * NNODE * 32];        // 16MB partials (attn1: 4h*8js*32c; attn2: 16js*64c)
__device__ float g_hs[240];                         // hemi hidden

__device__ __forceinline__ float leakyf(float x) { return fmaxf(x, 0.1f * x); }

// ---------------- pack adj int32 -> uint8 ----------------
__global__ void pack_adj_kernel(const int4* __restrict__ adj, uchar4* __restrict__ out, int n4) {
    int i = blockIdx.x * blockDim.x + threadIdx.x;
    if (i >= n4) return;
    int4 v = adj[i];
    out[i] = make_uchar4(v.x ? 1 : 0, v.y ? 1 : 0, v.z ? 1 : 0, v.w ? 1 : 0);
}

// ---------------- GEMM1: wh1[n][c] = sum_f x[n][f] * W1[h][f][o], c=h*30+o ----
// BM=32, BN=64, BK=32, 128 threads, 4x4 microtile, reg-staged double buffer.
__global__ void gemm1_kernel(const float* __restrict__ x,
                             const float* __restrict__ W1,
                             float* __restrict__ wh) {
    __shared__ float As[32][36];   // [k][m]
    __shared__ float Bs[32][64];   // [k][c]
    const int tid = threadIdx.x;
    const int m0 = blockIdx.x * 32;
    const int n0 = blockIdx.y * 64;
    const int tx = tid & 15, ty = tid >> 4;

    const int rA = tid >> 3;
    const int cA = (tid & 7) * 4;
    const int cB = tid & 63;
    const int kB = (tid >> 6) << 4;  // 0 or 16
    const int c = n0 + cB;
    const bool cOK = (c < H1);
    const int hB = cOK ? (c / 30) : 0;
    const int oB = cOK ? (c % 30) : 0;
    const float* wbase = W1 + (size_t)hB * FIN * H1P + oB;

    float acc[4][4];
#pragma unroll
    for (int i = 0; i < 4; i++)
#pragma unroll
        for (int j = 0; j < 4; j++) acc[i][j] = 0.f;

    float4 aP0 = *(const float4*)(x + (size_t)(m0 + rA) * FIN + cA);
    float4 aP1 = *(const float4*)(x + (size_t)(m0 + rA + 16) * FIN + cA);
    float bP[16];
#pragma unroll
    for (int q = 0; q < 16; q++)
        bP[q] = cOK ? wbase[(size_t)(kB + q) * H1P] : 0.f;

    for (int k0 = 0; k0 < FIN; k0 += 32) {
        As[cA + 0][rA] = aP0.x; As[cA + 1][rA] = aP0.y;
        As[cA + 2][rA] = aP0.z; As[cA + 3][rA] = aP0.w;
        As[cA + 0][rA + 16] = aP1.x; As[cA + 1][rA + 16] = aP1.y;
        As[cA + 2][rA + 16] = aP1.z; As[cA + 3][rA + 16] = aP1.w;
#pragma unroll
        for (int q = 0; q < 16; q++) Bs[kB + q][cB] = bP[q];
        __syncthreads();

        if (k0 + 32 < FIN) {
            aP0 = *(const float4*)(x + (size_t)(m0 + rA) * FIN + k0 + 32 + cA);
            aP1 = *(const float4*)(x + (size_t)(m0 + rA + 16) * FIN + k0 + 32 + cA);
#pragma unroll
            for (int q = 0; q < 16; q++)
                bP[q] = cOK ? wbase[(size_t)(k0 + 32 + kB + q) * H1P] : 0.f;
        }
#pragma unroll
        for (int k = 0; k < 32; k++) {
            float4 a = *(const float4*)&As[k][ty * 4];
            float4 b = *(const float4*)&Bs[k][tx * 4];
            float aa[4] = {a.x, a.y, a.z, a.w};
            float bb[4] = {b.x, b.y, b.z, b.w};
#pragma unroll
            for (int i = 0; i < 4; i++)
#pragma unroll
                for (int j = 0; j < 4; j++) acc[i][j] = fmaf(aa[i], bb[j], acc[i][j]);
        }
        __syncthreads();
    }
#pragma unroll
    for (int i = 0; i < 4; i++)
#pragma unroll
        for (int j = 0; j < 4; j++) {
            int cc = n0 + tx * 4 + j;
            if (cc < H1) wh[(size_t)(m0 + ty * 4 + i) * H1 + cc] = acc[i][j];
        }
}

// ---------------- f1/f2 + factored exponentials ----------------
__global__ void fcalc_kernel(const float* __restrict__ wh, int ldwh, int ncol,
                             const float* __restrict__ asrc, const float* __restrict__ adst,
                             int total,
                             float* __restrict__ f1r, float* __restrict__ f2r,
                             float* __restrict__ Cb, float* __restrict__ Bb,
                             float* __restrict__ Db) {
    int g = blockIdx.x * blockDim.x + threadIdx.x;
    if (g >= total) return;
    int h = g >> 12;
    int n = g & 4095;
    const float* base = wh + (size_t)n * ldwh + h * ncol;
    const float* as_ = asrc + h * ncol;
    const float* ad_ = adst + h * ncol;
    float f1 = 0.f, f2 = 0.f;
    for (int o = 0; o < ncol; o++) {
        float v = base[o];
        f1 = fmaf(v, as_[o], f1);
        f2 = fmaf(v, ad_[o], f2);
    }
    f1r[g] = f1;
    f2r[g] = f2;
    Cb[g] = expf(fminf(-0.9f * f1, 70.f));
    Bb[g] = expf(fminf(f2, 70.f));
    Db[g] = expf(0.1f * fminf(f2, 70.f));
}

// ---------------- fused masked-softmax attention (factored exact softmax) -------
// p_ij = adj_ij ? ( (f1_i+f2_j >= 0) ? B_j : C_i * D_j ) : 0
// Each thread: RPT rows (row = ty + TY*r, bank-conflict-free) x 8 cols.
// Z column (=1) accumulates the softmax normalizer; partials are exact.
template <int NCOL, int CXN, int TY, int RPT, int JS>
__global__ void __launch_bounds__(CXN* TY, 3)
attn_kernel(const float* __restrict__ wh, int ldwh,
            const float* __restrict__ f1r,
            const float* __restrict__ Cb, const float* __restrict__ Bb,
            const float* __restrict__ Db, const float* __restrict__ f2r,
            const unsigned char* __restrict__ adj8,
            float* __restrict__ dst) {
    constexpr int TI = TY * RPT;
    constexpr int TJ = 32;
    constexpr int NTHR = CXN * TY;
    constexpr int CP4 = CXN * 8;
    constexpr int ZCOL = NCOL;
    constexpr int JQ = TJ / 4;           // 8 quad-columns
    constexpr int RSTEP = NTHR / JQ;     // rows in parallel during p-build

    const int h = blockIdx.y;
    const int i0 = blockIdx.x * TI;
    const int js = blockIdx.z;
    const int jbeg = js * (NNODE / JS);
    const int jend = jbeg + NNODE / JS;
    const int fo = h * NNODE;
    const int colofs = h * NCOL;

    __shared__ float ps[TI][TJ + 1];
    __shared__ float whs[TJ][CP4];
    __shared__ float f1s[TI], Cs[TI];

    const int tid = threadIdx.x;
    const int cx = tid % CXN;
    const int ty = tid / CXN;
    const int jq = tid % JQ;
    const int iofs = tid / JQ;

    for (int i = tid; i < TI; i += NTHR) {
        f1s[i] = f1r[fo + i0 + i];
        Cs[i] = Cb[fo + i0 + i];
    }

    float acc[RPT][8];
#pragma unroll
    for (int r = 0; r < RPT; r++)
#pragma unroll
        for (int k = 0; k < 8; k++) acc[r][k] = 0.f;

    for (int j0 = jbeg; j0 < jend; j0 += TJ) {
        __syncthreads();  // prev gemm done; first iter: f1s/Cs visible
        // load wh tile (Z column = 1, pad = 0)
        for (int idx = tid; idx < TJ * CP4; idx += NTHR) {
            int jj = idx / CP4, o = idx % CP4;
            float v;
            if (o < NCOL) v = wh[(size_t)(j0 + jj) * ldwh + colofs + o];
            else v = (o == ZCOL) ? 1.f : 0.f;
            whs[jj][o] = v;
        }
        // build p tile: thread owns quad-column jq, B/D/f2 cached in registers
        {
            const int j = j0 + jq * 4;
            const float4 Bv = *(const float4*)(Bb + fo + j);
            const float4 Dv = *(const float4*)(Db + fo + j);
            const float4 f2v = *(const float4*)(f2r + fo + j);
#pragma unroll 4
            for (int ii = iofs; ii < TI; ii += RSTEP) {
                uchar4 a = *(const uchar4*)(adj8 + (size_t)(i0 + ii) * NNODE + j);
                float f1 = f1s[ii], C = Cs[ii];
                ps[ii][jq * 4 + 0] = a.x ? ((f1 + f2v.x >= 0.f) ? Bv.x : C * Dv.x) : 0.f;
                ps[ii][jq * 4 + 1] = a.y ? ((f1 + f2v.y >= 0.f) ? Bv.y : C * Dv.y) : 0.f;
                ps[ii][jq * 4 + 2] = a.z ? ((f1 + f2v.z >= 0.f) ? Bv.z : C * Dv.z) : 0.f;
                ps[ii][jq * 4 + 3] = a.w ? ((f1 + f2v.w >= 0.f) ? Bv.w : C * Dv.w) : 0.f;
            }
        }
        __syncthreads();
#pragma unroll 4
        for (int jj = 0; jj < TJ; jj++) {
            float4 wA = *(const float4*)&whs[jj][cx * 8];
            float4 wB = *(const float4*)&whs[jj][cx * 8 + 4];
#pragma unroll
            for (int r = 0; r < RPT; r++) {
                float p = ps[ty + TY * r][jj];
                acc[r][0] = fmaf(p, wA.x, acc[r][0]);
                acc[r][1] = fmaf(p, wA.y, acc[r][1]);
                acc[r][2] = fmaf(p, wA.z, acc[r][2]);
                acc[r][3] = fmaf(p, wA.w, acc[r][3]);
                acc[r][4] = fmaf(p, wB.x, acc[r][4]);
                acc[r][5] = fmaf(p, wB.y, acc[r][5]);
                acc[r][6] = fmaf(p, wB.z, acc[r][6]);
                acc[r][7] = fmaf(p, wB.w, acc[r][7]);
            }
        }
    }

    // write raw partials (incl. Z) to part buffer [(h*JS+js)][row][CP4]
#pragma unroll
    for (int r = 0; r < RPT; r++) {
        int row = i0 + ty + TY * r;
        float* p = dst + ((size_t)(h * JS + js) * NNODE + row) * CP4 + cx * 8;
        *(float4*)(p) = make_float4(acc[r][0], acc[r][1], acc[r][2], acc[r][3]);
        *(float4*)(p + 4) = make_float4(acc[r][4], acc[r][5], acc[r][6], acc[r][7]);
    }
}

// ---------------- combine partials -> leaky(sum/z + bias) ----------------
template <int NCOL, int CP4, int JS, int NH>
__global__ void combine_kernel(const float* __restrict__ part,
                               const float* __restrict__ bias,
                               float* __restrict__ out, int ldout) {
    int idx = blockIdx.x * blockDim.x + threadIdx.x;
    if (idx >= NNODE * NH * NCOL) return;
    int row = idx / (NH * NCOL);
    int rem = idx % (NH * NCOL);
    int h = rem / NCOL;
    int c = rem % NCOL;
    float s = 0.f, z = 0.f;
#pragma unroll
    for (int js = 0; js < JS; js++) {
        const float* p = part + ((size_t)(h * JS + js) * NNODE + row) * CP4;
        s += p[c];
        z += p[NCOL];
    }
    out[(size_t)row * ldout + h * NCOL + c] = leakyf(s / z + bias[h * NCOL + c]);
}

// ---------------- GEMM2: wh2 = hmid(4096x120) @ W2(120x50) ----------------
__global__ void gemm2_kernel(const float* __restrict__ hmid,
                             const float* __restrict__ W2,
                             float* __restrict__ wh2) {
    __shared__ float hs[4][120];
    const int n0 = blockIdx.x * 4;
    const int tid = threadIdx.x;
    for (int idx = tid; idx < 4 * 120; idx += blockDim.x)
        hs[idx / 120][idx % 120] = hmid[(size_t)(n0 + idx / 120) * H1 + (idx % 120)];
    __syncthreads();
    if (tid < 200) {
        int r = tid / 50, c = tid % 50;
        float acc = 0.f;
#pragma unroll 8
        for (int k = 0; k < 120; k++) acc = fmaf(hs[r][k], W2[k * 50 + c], acc);
        wh2[(size_t)(n0 + r) * H2 + c] = acc;
    }
}

// ---------------- FiLM + gating + classifier logits ----------------
__global__ void film_kernel(const float* __restrict__ h2,
                            const float* __restrict__ lloc,
                            const float* __restrict__ Wl1, const float* __restrict__ bl1,
                            const float* __restrict__ Wl2, const float* __restrict__ bl2,
                            const float* __restrict__ Wg, const float* __restrict__ bg,
                            const float* __restrict__ Wb, const float* __restrict__ bb,
                            const float* __restrict__ Wgate, const float* __restrict__ bgate,
                            const float* __restrict__ Wc,
                            float* __restrict__ outlogits) {
    int n = blockIdx.x * blockDim.x + threadIdx.x;
    if (n >= NNODE) return;
    float l[16];
#pragma unroll
    for (int k = 0; k < 16; k++) l[k] = lloc[n * 16 + k];
    float z1[32];
#pragma unroll
    for (int j = 0; j < 32; j++) {
        float a = bl1[j];
#pragma unroll
        for (int k = 0; k < 16; k++) a = fmaf(l[k], Wl1[j * 16 + k], a);
        z1[j] = leakyf(a);
    }
    float z2[32];
#pragma unroll
    for (int j = 0; j < 32; j++) {
        float a = bl2[j];
#pragma unroll
        for (int k = 0; k < 32; k++) a = fmaf(z1[k], Wl2[j * 32 + k], a);
        z2[j] = leakyf(a);
    }
    float ga = bgate[0];
#pragma unroll
    for (int k = 0; k < 32; k++) ga = fmaf(z2[k], Wgate[k], ga);
    float g = 1.f / (1.f + expf(-ga));
    float cov = fminf(fmaxf(l[15], 0.f), 1.f);
    g *= cov;

    float l0 = 0.f, l1 = 0.f;
    for (int c = 0; c < 50; c++) {
        float gm = bg[c], bt = bb[c];
#pragma unroll
        for (int k = 0; k < 32; k++) {
            gm = fmaf(z2[k], Wg[c * 32 + k], gm);
            bt = fmaf(z2[k], Wb[c * 32 + k], bt);
        }
        float hv = h2[(size_t)n * H2 + c];
        float hf = hv + g * fmaf(gm, hv, bt);
        l0 = fmaf(hf, Wc[c], l0);
        l1 = fmaf(hf, Wc[50 + c], l1);
    }
    outlogits[n * 2 + 0] = leakyf(l0);
    outlogits[n * 2 + 1] = leakyf(l1);
}

// ---------------- hemisphere SSDB ----------------
__global__ void hemi_dots_kernel(const float* __restrict__ out,
                                 const float* __restrict__ Ws1,
                                 const float* __restrict__ bs1,
                                 float* __restrict__ hs) {
    const int b = blockIdx.x;                // 0..239
    const int hemi = b / 120;
    const int cls = (b / 60) % 2;
    const int k = b % 60;
    const int tid = threadIdx.x;
    const float* lg = out + (size_t)hemi * 2048 * 2 + cls;
    const float* w = Ws1 + (size_t)k * 2048;
    float acc = 0.f;
    for (int m = tid; m < 2048; m += 128) acc = fmaf(lg[2 * m], w[m], acc);
#pragma unroll
    for (int off = 16; off; off >>= 1) acc += __shfl_xor_sync(0xffffffffu, acc, off);
    __shared__ float red[4];
    if ((tid & 31) == 0) red[tid >> 5] = acc;
    __syncthreads();
    if (tid == 0)
        hs[b] = leakyf(red[0] + red[1] + red[2] + red[3] + bs1[k]);
}

__global__ void hemi_fin_kernel(float* __restrict__ out,
                                const float* __restrict__ hs,
                                const float* __restrict__ Ws2,
                                const float* __restrict__ bs2) {
    __shared__ float bsm[4];
    const int tid = threadIdx.x;
    if (tid < 4) {
        int hemi = tid >> 1, cls = tid & 1;
        float acc = bs2[0];
#pragma unroll
        for (int k = 0; k < 60; k++) acc = fmaf(hs[hemi * 120 + cls * 60 + k], Ws2[k], acc);
        bsm[hemi * 2 + cls] = leakyf(acc);
    }
    __syncthreads();
    for (int idx = tid; idx < NNODE * 2; idx += blockDim.x) {
        int n = idx >> 1, cls = idx & 1;
        int hemi = (n >= 2048) ? 1 : 0;
        out[idx] += bsm[hemi * 2 + cls];
    }
    if (tid < 2) out[NNODE * 2 + tid] = 0.5f * (bsm[tid] + bsm[2 + tid]);
}

// ---------------- host launch ----------------
extern "C" void kernel_launch(void* const* d_in, const int* in_sizes, int n_in,
                              void* d_out, int out_size) {
    const float* x_fc  = (const float*)d_in[0];
    const int*   adj   = (const int*)d_in[1];
    const float* lloc  = (const float*)d_in[2];
    const float* W1    = (const float*)d_in[3];
    const float* a1s   = (const float*)d_in[4];
    const float* a1d   = (const float*)d_in[5];
    const float* b1    = (const float*)d_in[6];
    const float* W2    = (const float*)d_in[7];
    const float* a2s   = (const float*)d_in[8];
    const float* a2d   = (const float*)d_in[9];
    const float* b2    = (const float*)d_in[10];
    const float* Wc    = (const float*)d_in[11];
    const float* Wl1   = (const float*)d_in[12];
    const float* bl1   = (const float*)d_in[13];
    const float* Wl2   = (const float*)d_in[14];
    const float* bl2   = (const float*)d_in[15];
    const float* Wg    = (const float*)d_in[16];
    const float* bg    = (const float*)d_in[17];
    const float* Wb    = (const float*)d_in[18];
    const float* bb    = (const float*)d_in[19];
    const float* Wgate = (const float*)d_in[20];
    const float* bgate = (const float*)d_in[21];
    const float* Ws1   = (const float*)d_in[22];
    const float* bs1   = (const float*)d_in[23];
    const float* Ws2   = (const float*)d_in[24];
    const float* bs2   = (const float*)d_in[25];
    float* outp = (float*)d_out;

    float *wh1, *hmid, *wh2, *h2, *part, *hsb;
    float *f1a, *f2a, *Ca, *Ba, *Da, *f1b, *f2b, *Cb2, *Bb2, *Db2;
    unsigned char* adj8;
    cudaGetSymbolAddress((void**)&wh1, g_wh1);
    cudaGetSymbolAddress((void**)&hmid, g_hmid);
    cudaGetSymbolAddress((void**)&wh2, g_wh2);
    cudaGetSymbolAddress((void**)&h2, g_h2);
    cudaGetSymbolAddress((void**)&f1a, g_f1a);
    cudaGetSymbolAddress((void**)&f2a, g_f2a);
    cudaGetSymbolAddress((void**)&Ca, g_Ca);
    cudaGetSymbolAddress((void**)&Ba, g_Ba);
    cudaGetSymbolAddress((void**)&Da, g_Da);
    cudaGetSymbolAddress((void**)&f1b, g_f1b);
    cudaGetSymbolAddress((void**)&f2b, g_f2b);
    cudaGetSymbolAddress((void**)&Cb2, g_Cb);
    cudaGetSymbolAddress((void**)&Bb2, g_Bb);
    cudaGetSymbolAddress((void**)&Db2, g_Db);
    cudaGetSymbolAddress((void**)&adj8, g_adj8);
    cudaGetSymbolAddress((void**)&part, g_part);
    cudaGetSymbolAddress((void**)&hsb, g_hs);

    // 0) pack adjacency to bytes (L2-resident afterwards)
    pack_adj_kernel<<<NNODE * NNODE / 4 / 256, 256>>>((const int4*)adj, (uchar4*)adj8,
                                                      NNODE * NNODE / 4);
    // 1) wh1 = x @ W1cat
    gemm1_kernel<<<dim3(NNODE / 32, 2), 128>>>(x_fc, W1, wh1);
    // 2) attention-1 features
    fcalc_kernel<<<(HEADS * NNODE) / 256, 256>>>(wh1, H1, H1P, a1s, a1d,
                                                 HEADS * NNODE, f1a, f2a, Ca, Ba, Da);
    // 3) GAT1 fused attention (j-split 8) -> partials; combine -> hmid
    //    NCOL=30, CXN=4 (CP4=32), TY=32, RPT=8 -> TI=256, 128 thr, grid (16,4,8)=512
    attn_kernel<30, 4, 32, 8, 8><<<dim3(NNODE / 256, HEADS, 8), 128>>>(
        wh1, H1, f1a, Ca, Ba, Da, f2a, adj8, part);
    combine_kernel<30, 32, 8, HEADS><<<(NNODE * HEADS * 30 + 255) / 256, 256>>>(
        part, b1, hmid, H1);
    // 4) wh2 = hmid @ W2
    gemm2_kernel<<<NNODE / 4, 256>>>(hmid, W2, wh2);
    // 5) attention-2 features
    fcalc_kernel<<<NNODE / 256, 256>>>(wh2, H2, H2, a2s, a2d,
                                       NNODE, f1b, f2b, Cb2, Bb2, Db2);
    // 6) GAT2 fused attention (j-split 16) -> partials; combine -> h2
    //    NCOL=50, CXN=8 (CP4=64), TY=16, RPT=8 -> TI=128, 128 thr, grid (32,1,16)=512
    attn_kernel<50, 8, 16, 8, 16><<<dim3(NNODE / 128, 1, 16), 128>>>(
        wh2, H2, f1b, Cb2, Bb2, Db2, f2b, adj8, part);
    combine_kernel<50, 64, 16, 1><<<(NNODE * H2 + 255) / 256, 256>>>(
        part, b2, h2, H2);
    // 7) FiLM + classifier -> logits in d_out[0..8191]
    film_kernel<<<NNODE / 128, 128>>>(h2, lloc, Wl1, bl1, Wl2, bl2,
                                      Wg, bg, Wb, bb, Wgate, bgate, Wc, outp);
    // 8) hemisphere bias
    hemi_dots_kernel<<<240, 128>>>(outp, Ws1, bs1, hsb);
    hemi_fin_kernel<<<1, 256>>>(outp, hsb, Ws2, bs2);
}

// round 10
// speedup vs baseline: 4.4390x; 1.2701x over previous
#include <cuda_runtime.h>
#include <cuda_bf16.h>
#include <cstdint>

#define NNODE 4096
#define FIN   4096
#define H1    120
#define HEADS 4
#define H1P   30
#define H2    50

// ---------------- scratch (static device globals; no allocation) ----------------
__device__ float g_wh1[NNODE * H1];
__device__ float g_hmid[NNODE * H1];
__device__ float g_wh2[NNODE * H2];
__device__ float g_h2[NNODE * H2];
__device__ float g_f1a[HEADS * NNODE], g_f2a[HEADS * NNODE];
__device__ float g_Ca[HEADS * NNODE], g_Ba[HEADS * NNODE], g_Da[HEADS * NNODE];
__device__ float g_f1b[NNODE], g_f2b[NNODE];
__device__ float g_Cb[NNODE], g_Bb[NNODE], g_Db[NNODE];
__device__ unsigned char g_adj8[NNODE * NNODE];     // 16MB packed adjacency
__device__ float g_part[4 * 8 * NNODE * 32];        // partials (gemm1 K-split / attn js)
__device__ float g_wtr[128 * FIN];                  // W1 transposed, K-major, rows 120-127 zero
__device__ float g_hs[240];                         // hemi hidden

__device__ __forceinline__ float leakyf(float x) { return fmaxf(x, 0.1f * x); }

// ---------------- pack adj int32 -> uint8 ----------------
__global__ void pack_adj_kernel(const int4* __restrict__ adj, uchar4* __restrict__ out, int n4) {
    int i = blockIdx.x * blockDim.x + threadIdx.x;
    if (i >= n4) return;
    int4 v = adj[i];
    out[i] = make_uchar4(v.x ? 1 : 0, v.y ? 1 : 0, v.z ? 1 : 0, v.w ? 1 : 0);
}

// ---------------- transpose W1 -> wtr[128][4096] (K-major B operand) ----------
__global__ void transpose_w1_kernel(const float* __restrict__ W1, float* __restrict__ wtr) {
    int idx = blockIdx.x * blockDim.x + threadIdx.x;  // 131072
    int c = idx >> 10;
    int k4 = (idx & 1023) * 4;
    float4 v = make_float4(0.f, 0.f, 0.f, 0.f);
    if (c < H1) {
        int h = c / 30, o = c % 30;
        const float* base = W1 + ((size_t)h * FIN) * H1P + o;
        v.x = base[(size_t)(k4 + 0) * H1P];
        v.y = base[(size_t)(k4 + 1) * H1P];
        v.z = base[(size_t)(k4 + 2) * H1P];
        v.w = base[(size_t)(k4 + 3) * H1P];
    }
    *(float4*)(wtr + (size_t)c * FIN + k4) = v;
}

// ---------------- GEMM1 via legacy mma.sync TF32, 3-way fp32 split ----------------
__device__ __forceinline__ void mma1688(float c[4], uint32_t a0, uint32_t a1,
                                        uint32_t a2, uint32_t a3,
                                        uint32_t b0, uint32_t b1) {
    asm volatile(
        "mma.sync.aligned.m16n8k8.row.col.f32.tf32.tf32.f32 "
        "{%0,%1,%2,%3}, {%4,%5,%6,%7}, {%8,%9}, {%0,%1,%2,%3};"
        : "+f"(c[0]), "+f"(c[1]), "+f"(c[2]), "+f"(c[3])
        : "r"(a0), "r"(a1), "r"(a2), "r"(a3), "r"(b0), "r"(b1));
}
__device__ __forceinline__ void split_bits(float v, uint32_t& hi, uint32_t& lo) {
    uint32_t h = __float_as_uint(v) & 0xFFFFE000u;
    hi = h;
    lo = __float_as_uint(v - __uint_as_float(h));
}

#define G1_BM 64
#define G1_LDS 36
// smem: A [64][36] floats, then B [128][36] floats, x2 stages
#define G1_ASZ (G1_BM * G1_LDS)
#define G1_BSZ (128 * G1_LDS)
#define G1_STAGE (G1_ASZ + G1_BSZ)

__global__ void __launch_bounds__(256, 1)
gemm1_mma_kernel(const float* __restrict__ x, const float* __restrict__ wtr,
                 float* __restrict__ part) {
    extern __shared__ float sm[];
    const int tid = threadIdx.x;
    const int wid = tid >> 5;
    const int lane = tid & 31;
    const int lq = lane >> 2, lr = lane & 3;
    const int warp_m = wid >> 1;       // 0..3
    const int warp_n = wid & 1;        // 0..1
    const int m0 = blockIdx.x * G1_BM;
    const int ks = blockIdx.y;
    const int k0base = ks * (FIN / 2);
    const int NT = (FIN / 2) / 32;     // 64 K-tiles of 32

    float acc[8][4];
#pragma unroll
    for (int nt = 0; nt < 8; nt++)
#pragma unroll
        for (int i = 0; i < 4; i++) acc[nt][i] = 0.f;

    // loaders: A 512 float4 units (2/thread), B 1024 units (4/thread)
    float4 aP[2], bP[4];
#pragma unroll
    for (int i = 0; i < 2; i++) {
        int u = tid + i * 256;
        int r = u >> 3, c4 = u & 7;
        aP[i] = *(const float4*)(x + (size_t)(m0 + r) * FIN + k0base + c4 * 4);
    }
#pragma unroll
    for (int i = 0; i < 4; i++) {
        int u = tid + i * 256;
        int r = u >> 3, c4 = u & 7;
        bP[i] = *(const float4*)(wtr + (size_t)r * FIN + k0base + c4 * 4);
    }

    for (int t = 0; t < NT; t++) {
        const int b = t & 1;
        float* As = sm + b * G1_STAGE;
        float* Bs = As + G1_ASZ;
#pragma unroll
        for (int i = 0; i < 2; i++) {
            int u = tid + i * 256;
            int r = u >> 3, c4 = u & 7;
            *(float4*)(As + r * G1_LDS + c4 * 4) = aP[i];
        }
#pragma unroll
        for (int i = 0; i < 4; i++) {
            int u = tid + i * 256;
            int r = u >> 3, c4 = u & 7;
            *(float4*)(Bs + r * G1_LDS + c4 * 4) = bP[i];
        }
        __syncthreads();
        if (t + 1 < NT) {
            int kn = k0base + (t + 1) * 32;
#pragma unroll
            for (int i = 0; i < 2; i++) {
                int u = tid + i * 256;
                int r = u >> 3, c4 = u & 7;
                aP[i] = *(const float4*)(x + (size_t)(m0 + r) * FIN + kn + c4 * 4);
            }
#pragma unroll
            for (int i = 0; i < 4; i++) {
                int u = tid + i * 256;
                int r = u >> 3, c4 = u & 7;
                bP[i] = *(const float4*)(wtr + (size_t)r * FIN + kn + c4 * 4);
            }
        }
#pragma unroll
        for (int k8 = 0; k8 < 4; k8++) {
            const int rowA = warp_m * 16 + lq;
            const int colA = k8 * 8 + lr;
            float a0f = As[rowA * G1_LDS + colA];
            float a1f = As[(rowA + 8) * G1_LDS + colA];
            float a2f = As[rowA * G1_LDS + colA + 4];
            float a3f = As[(rowA + 8) * G1_LDS + colA + 4];
            uint32_t ah[4], al[4];
            split_bits(a0f, ah[0], al[0]);
            split_bits(a1f, ah[1], al[1]);
            split_bits(a2f, ah[2], al[2]);
            split_bits(a3f, ah[3], al[3]);
#pragma unroll
            for (int nt = 0; nt < 8; nt++) {
                const int rowB = warp_n * 64 + nt * 8 + lq;
                float b0f = Bs[rowB * G1_LDS + k8 * 8 + lr];
                float b1f = Bs[rowB * G1_LDS + k8 * 8 + lr + 4];
                uint32_t bh0, bl0, bh1, bl1;
                split_bits(b0f, bh0, bl0);
                split_bits(b1f, bh1, bl1);
                mma1688(acc[nt], ah[0], ah[1], ah[2], ah[3], bh0, bh1);
                mma1688(acc[nt], al[0], al[1], al[2], al[3], bh0, bh1);
                mma1688(acc[nt], ah[0], ah[1], ah[2], ah[3], bl0, bl1);
            }
        }
        __syncthreads();
    }

    // epilogue: write partials [ks][row][120]
    const int row0 = m0 + warp_m * 16 + lq;
    float* base = part + ((size_t)ks * NNODE) * 120;
#pragma unroll
    for (int nt = 0; nt < 8; nt++) {
        int col = warp_n * 64 + nt * 8 + lr * 2;
        if (col < 120) {
            base[(size_t)row0 * 120 + col] = acc[nt][0];
            base[(size_t)row0 * 120 + col + 1] = acc[nt][1];
            base[(size_t)(row0 + 8) * 120 + col] = acc[nt][2];
            base[(size_t)(row0 + 8) * 120 + col + 1] = acc[nt][3];
        }
    }
}

// ---------------- combine gemm1 K-partials + attention-1 features ----------------
__global__ void fcalc_combine1_kernel(const float* __restrict__ part,
                                      const float* __restrict__ asrc,
                                      const float* __restrict__ adst,
                                      float* __restrict__ wh1,
                                      float* __restrict__ f1r, float* __restrict__ f2r,
                                      float* __restrict__ Cb, float* __restrict__ Bb,
                                      float* __restrict__ Db) {
    int g = blockIdx.x * blockDim.x + threadIdx.x;
    if (g >= HEADS * NNODE) return;
    int h = g >> 12;
    int n = g & 4095;
    const float* as_ = asrc + h * H1P;
    const float* ad_ = adst + h * H1P;
    float f1 = 0.f, f2 = 0.f;
#pragma unroll 6
    for (int o = 0; o < H1P; o++) {
        int c = h * H1P + o;
        float v = part[(size_t)n * 120 + c] + part[((size_t)NNODE + n) * 120 + c];
        wh1[(size_t)n * H1 + c] = v;
        f1 = fmaf(v, as_[o], f1);
        f2 = fmaf(v, ad_[o], f2);
    }
    f1r[g] = f1;
    f2r[g] = f2;
    Cb[g] = expf(fminf(-0.9f * f1, 70.f));
    Bb[g] = expf(fminf(f2, 70.f));
    Db[g] = expf(0.1f * fminf(f2, 70.f));
}

// ---------------- f1/f2 + factored exponentials (layer 2) ----------------
__global__ void fcalc_kernel(const float* __restrict__ wh, int ldwh, int ncol,
                             const float* __restrict__ asrc, const float* __restrict__ adst,
                             int total,
                             float* __restrict__ f1r, float* __restrict__ f2r,
                             float* __restrict__ Cb, float* __restrict__ Bb,
                             float* __restrict__ Db) {
    int g = blockIdx.x * blockDim.x + threadIdx.x;
    if (g >= total) return;
    int h = g >> 12;
    int n = g & 4095;
    const float* base = wh + (size_t)n * ldwh + h * ncol;
    const float* as_ = asrc + h * ncol;
    const float* ad_ = adst + h * ncol;
    float f1 = 0.f, f2 = 0.f;
    for (int o = 0; o < ncol; o++) {
        float v = base[o];
        f1 = fmaf(v, as_[o], f1);
        f2 = fmaf(v, ad_[o], f2);
    }
    f1r[g] = f1;
    f2r[g] = f2;
    Cb[g] = expf(fminf(-0.9f * f1, 70.f));
    Bb[g] = expf(fminf(f2, 70.f));
    Db[g] = expf(0.1f * fminf(f2, 70.f));
}

// ---------------- fused masked-softmax attention (factored exact softmax) -------
template <int NCOL, int CXN, int TY, int RPT, int JS>
__global__ void __launch_bounds__(CXN* TY, 3)
attn_kernel(const float* __restrict__ wh, int ldwh,
            const float* __restrict__ f1r,
            const float* __restrict__ Cb, const float* __restrict__ Bb,
            const float* __restrict__ Db, const float* __restrict__ f2r,
            const unsigned char* __restrict__ adj8,
            float* __restrict__ dst) {
    constexpr int TI = TY * RPT;
    constexpr int TJ = 32;
    constexpr int NTHR = CXN * TY;
    constexpr int CP4 = CXN * 8;
    constexpr int ZCOL = NCOL;
    constexpr int JQ = TJ / 4;
    constexpr int RSTEP = NTHR / JQ;

    const int h = blockIdx.y;
    const int i0 = blockIdx.x * TI;
    const int js = blockIdx.z;
    const int jbeg = js * (NNODE / JS);
    const int jend = jbeg + NNODE / JS;
    const int fo = h * NNODE;
    const int colofs = h * NCOL;

    __shared__ float ps[TI][TJ + 1];
    __shared__ float whs[TJ][CP4];
    __shared__ float f1s[TI], Cs[TI];

    const int tid = threadIdx.x;
    const int cx = tid % CXN;
    const int ty = tid / CXN;
    const int jq = tid % JQ;
    const int iofs = tid / JQ;

    for (int i = tid; i < TI; i += NTHR) {
        f1s[i] = f1r[fo + i0 + i];
        Cs[i] = Cb[fo + i0 + i];
    }

    float acc[RPT][8];
#pragma unroll
    for (int r = 0; r < RPT; r++)
#pragma unroll
        for (int k = 0; k < 8; k++) acc[r][k] = 0.f;

    for (int j0 = jbeg; j0 < jend; j0 += TJ) {
        __syncthreads();
        for (int idx = tid; idx < TJ * CP4; idx += NTHR) {
            int jj = idx / CP4, o = idx % CP4;
            float v;
            if (o < NCOL) v = wh[(size_t)(j0 + jj) * ldwh + colofs + o];
            else v = (o == ZCOL) ? 1.f : 0.f;
            whs[jj][o] = v;
        }
        {
            const int j = j0 + jq * 4;
            const float4 Bv = *(const float4*)(Bb + fo + j);
            const float4 Dv = *(const float4*)(Db + fo + j);
            const float4 f2v = *(const float4*)(f2r + fo + j);
#pragma unroll 4
            for (int ii = iofs; ii < TI; ii += RSTEP) {
                uchar4 a = *(const uchar4*)(adj8 + (size_t)(i0 + ii) * NNODE + j);
                float f1 = f1s[ii], C = Cs[ii];
                ps[ii][jq * 4 + 0] = a.x ? ((f1 + f2v.x >= 0.f) ? Bv.x : C * Dv.x) : 0.f;
                ps[ii][jq * 4 + 1] = a.y ? ((f1 + f2v.y >= 0.f) ? Bv.y : C * Dv.y) : 0.f;
                ps[ii][jq * 4 + 2] = a.z ? ((f1 + f2v.z >= 0.f) ? Bv.z : C * Dv.z) : 0.f;
                ps[ii][jq * 4 + 3] = a.w ? ((f1 + f2v.w >= 0.f) ? Bv.w : C * Dv.w) : 0.f;
            }
        }
        __syncthreads();
#pragma unroll 4
        for (int jj = 0; jj < TJ; jj++) {
            float4 wA = *(const float4*)&whs[jj][cx * 8];
            float4 wB = *(const float4*)&whs[jj][cx * 8 + 4];
#pragma unroll
            for (int r = 0; r < RPT; r++) {
                float p = ps[ty + TY * r][jj];
                acc[r][0] = fmaf(p, wA.x, acc[r][0]);
                acc[r][1] = fmaf(p, wA.y, acc[r][1]);
                acc[r][2] = fmaf(p, wA.z, acc[r][2]);
                acc[r][3] = fmaf(p, wA.w, acc[r][3]);
                acc[r][4] = fmaf(p, wB.x, acc[r][4]);
                acc[r][5] = fmaf(p, wB.y, acc[r][5]);
                acc[r][6] = fmaf(p, wB.z, acc[r][6]);
                acc[r][7] = fmaf(p, wB.w, acc[r][7]);
            }
        }
    }

#pragma unroll
    for (int r = 0; r < RPT; r++) {
        int row = i0 + ty + TY * r;
        float* p = dst + ((size_t)(h * JS + js) * NNODE + row) * CP4 + cx * 8;
        *(float4*)(p) = make_float4(acc[r][0], acc[r][1], acc[r][2], acc[r][3]);
        *(float4*)(p + 4) = make_float4(acc[r][4], acc[r][5], acc[r][6], acc[r][7]);
    }
}

// ---------------- combine partials -> leaky(sum/z + bias) ----------------
template <int NCOL, int CP4, int JS, int NH>
__global__ void combine_kernel(const float* __restrict__ part,
                               const float* __restrict__ bias,
                               float* __restrict__ out, int ldout) {
    int idx = blockIdx.x * blockDim.x + threadIdx.x;
    if (idx >= NNODE * NH * NCOL) return;
    int row = idx / (NH * NCOL);
    int rem = idx % (NH * NCOL);
    int h = rem / NCOL;
    int c = rem % NCOL;
    float s = 0.f, z = 0.f;
#pragma unroll
    for (int js = 0; js < JS; js++) {
        const float* p = part + ((size_t)(h * JS + js) * NNODE + row) * CP4;
        s += p[c];
        z += p[NCOL];
    }
    out[(size_t)row * ldout + h * NCOL + c] = leakyf(s / z + bias[h * NCOL + c]);
}

// ---------------- GEMM2: wh2 = hmid(4096x120) @ W2(120x50) ----------------
__global__ void gemm2_kernel(const float* __restrict__ hmid,
                             const float* __restrict__ W2,
                             float* __restrict__ wh2) {
    __shared__ float hs[4][120];
    const int n0 = blockIdx.x * 4;
    const int tid = threadIdx.x;
    for (int idx = tid; idx < 4 * 120; idx += blockDim.x)
        hs[idx / 120][idx % 120] = hmid[(size_t)(n0 + idx / 120) * H1 + (idx % 120)];
    __syncthreads();
    if (tid < 200) {
        int r = tid / 50, c = tid % 50;
        float acc = 0.f;
#pragma unroll 8
        for (int k = 0; k < 120; k++) acc = fmaf(hs[r][k], W2[k * 50 + c], acc);
        wh2[(size_t)(n0 + r) * H2 + c] = acc;
    }
}

// ---------------- FiLM + gating + classifier logits ----------------
__global__ void film_kernel(const float* __restrict__ h2,
                            const float* __restrict__ lloc,
                            const float* __restrict__ Wl1, const float* __restrict__ bl1,
                            const float* __restrict__ Wl2, const float* __restrict__ bl2,
                            const float* __restrict__ Wg, const float* __restrict__ bg,
                            const float* __restrict__ Wb, const float* __restrict__ bb,
                            const float* __restrict__ Wgate, const float* __restrict__ bgate,
                            const float* __restrict__ Wc,
                            float* __restrict__ outlogits) {
    int n = blockIdx.x * blockDim.x + threadIdx.x;
    if (n >= NNODE) return;
    float l[16];
#pragma unroll
    for (int k = 0; k < 16; k++) l[k] = lloc[n * 16 + k];
    float z1[32];
#pragma unroll
    for (int j = 0; j < 32; j++) {
        float a = bl1[j];
#pragma unroll
        for (int k = 0; k < 16; k++) a = fmaf(l[k], Wl1[j * 16 + k], a);
        z1[j] = leakyf(a);
    }
    float z2[32];
#pragma unroll
    for (int j = 0; j < 32; j++) {
        float a = bl2[j];
#pragma unroll
        for (int k = 0; k < 32; k++) a = fmaf(z1[k], Wl2[j * 32 + k], a);
        z2[j] = leakyf(a);
    }
    float ga = bgate[0];
#pragma unroll
    for (int k = 0; k < 32; k++) ga = fmaf(z2[k], Wgate[k], ga);
    float g = 1.f / (1.f + expf(-ga));
    float cov = fminf(fmaxf(l[15], 0.f), 1.f);
    g *= cov;

    float l0 = 0.f, l1 = 0.f;
    for (int c = 0; c < 50; c++) {
        float gm = bg[c], bt = bb[c];
#pragma unroll
        for (int k = 0; k < 32; k++) {
            gm = fmaf(z2[k], Wg[c * 32 + k], gm);
            bt = fmaf(z2[k], Wb[c * 32 + k], bt);
        }
        float hv = h2[(size_t)n * H2 + c];
        float hf = hv + g * fmaf(gm, hv, bt);
        l0 = fmaf(hf, Wc[c], l0);
        l1 = fmaf(hf, Wc[50 + c], l1);
    }
    outlogits[n * 2 + 0] = leakyf(l0);
    outlogits[n * 2 + 1] = leakyf(l1);
}

// ---------------- hemisphere SSDB ----------------
__global__ void hemi_dots_kernel(const float* __restrict__ out,
                                 const float* __restrict__ Ws1,
                                 const float* __restrict__ bs1,
                                 float* __restrict__ hs) {
    const int b = blockIdx.x;                // 0..239
    const int hemi = b / 120;
    const int cls = (b / 60) % 2;
    const int k = b % 60;
    const int tid = threadIdx.x;
    const float* lg = out + (size_t)hemi * 2048 * 2 + cls;
    const float* w = Ws1 + (size_t)k * 2048;
    float acc = 0.f;
    for (int m = tid; m < 2048; m += 128) acc = fmaf(lg[2 * m], w[m], acc);
#pragma unroll
    for (int off = 16; off; off >>= 1) acc += __shfl_xor_sync(0xffffffffu, acc, off);
    __shared__ float red[4];
    if ((tid & 31) == 0) red[tid >> 5] = acc;
    __syncthreads();
    if (tid == 0)
        hs[b] = leakyf(red[0] + red[1] + red[2] + red[3] + bs1[k]);
}

__global__ void hemi_fin_kernel(float* __restrict__ out,
                                const float* __restrict__ hs,
                                const float* __restrict__ Ws2,
                                const float* __restrict__ bs2) {
    __shared__ float bsm[4];
    const int tid = threadIdx.x;
    if (tid < 4) {
        int hemi = tid >> 1, cls = tid & 1;
        float acc = bs2[0];
#pragma unroll
        for (int k = 0; k < 60; k++) acc = fmaf(hs[hemi * 120 + cls * 60 + k], Ws2[k], acc);
        bsm[hemi * 2 + cls] = leakyf(acc);
    }
    __syncthreads();
    for (int idx = tid; idx < NNODE * 2; idx += blockDim.x) {
        int n = idx >> 1, cls = idx & 1;
        int hemi = (n >= 2048) ? 1 : 0;
        out[idx] += bsm[hemi * 2 + cls];
    }
    if (tid < 2) out[NNODE * 2 + tid] = 0.5f * (bsm[tid] + bsm[2 + tid]);
}

// ---------------- host launch ----------------
extern "C" void kernel_launch(void* const* d_in, const int* in_sizes, int n_in,
                              void* d_out, int out_size) {
    const float* x_fc  = (const float*)d_in[0];
    const int*   adj   = (const int*)d_in[1];
    const float* lloc  = (const float*)d_in[2];
    const float* W1    = (const float*)d_in[3];
    const float* a1s   = (const float*)d_in[4];
    const float* a1d   = (const float*)d_in[5];
    const float* b1    = (const float*)d_in[6];
    const float* W2    = (const float*)d_in[7];
    const float* a2s   = (const float*)d_in[8];
    const float* a2d   = (const float*)d_in[9];
    const float* b2    = (const float*)d_in[10];
    const float* Wc    = (const float*)d_in[11];
    const float* Wl1   = (const float*)d_in[12];
    const float* bl1   = (const float*)d_in[13];
    const float* Wl2   = (const float*)d_in[14];
    const float* bl2   = (const float*)d_in[15];
    const float* Wg    = (const float*)d_in[16];
    const float* bg    = (const float*)d_in[17];
    const float* Wb    = (const float*)d_in[18];
    const float* bb    = (const float*)d_in[19];
    const float* Wgate = (const float*)d_in[20];
    const float* bgate = (const float*)d_in[21];
    const float* Ws1   = (const float*)d_in[22];
    const float* bs1   = (const float*)d_in[23];
    const float* Ws2   = (const float*)d_in[24];
    const float* bs2   = (const float*)d_in[25];
    float* outp = (float*)d_out;

    float *wh1, *hmid, *wh2, *h2, *part, *hsb, *wtr;
    float *f1a, *f2a, *Ca, *Ba, *Da, *f1b, *f2b, *Cb2, *Bb2, *Db2;
    unsigned char* adj8;
    cudaGetSymbolAddress((void**)&wh1, g_wh1);
    cudaGetSymbolAddress((void**)&hmid, g_hmid);
    cudaGetSymbolAddress((void**)&wh2, g_wh2);
    cudaGetSymbolAddress((void**)&h2, g_h2);
    cudaGetSymbolAddress((void**)&f1a, g_f1a);
    cudaGetSymbolAddress((void**)&f2a, g_f2a);
    cudaGetSymbolAddress((void**)&Ca, g_Ca);
    cudaGetSymbolAddress((void**)&Ba, g_Ba);
    cudaGetSymbolAddress((void**)&Da, g_Da);
    cudaGetSymbolAddress((void**)&f1b, g_f1b);
    cudaGetSymbolAddress((void**)&f2b, g_f2b);
    cudaGetSymbolAddress((void**)&Cb2, g_Cb);
    cudaGetSymbolAddress((void**)&Bb2, g_Bb);
    cudaGetSymbolAddress((void**)&Db2, g_Db);
    cudaGetSymbolAddress((void**)&adj8, g_adj8);
    cudaGetSymbolAddress((void**)&part, g_part);
    cudaGetSymbolAddress((void**)&hsb, g_hs);
    cudaGetSymbolAddress((void**)&wtr, g_wtr);

    // 0) pack adjacency to bytes; transpose W1 to K-major
    pack_adj_kernel<<<NNODE * NNODE / 4 / 256, 256>>>((const int4*)adj, (uchar4*)adj8,
                                                      NNODE * NNODE / 4);
    transpose_w1_kernel<<<512, 256>>>(W1, wtr);
    // 1) wh1 partials via mma.sync TF32 x3 (K-split 2)
    cudaFuncSetAttribute(gemm1_mma_kernel, cudaFuncAttributeMaxDynamicSharedMemorySize,
                         2 * G1_STAGE * (int)sizeof(float));
    gemm1_mma_kernel<<<dim3(NNODE / G1_BM, 2), 256, 2 * G1_STAGE * sizeof(float)>>>(
        x_fc, wtr, part);
    // 2) combine K-partials -> wh1 + attention-1 features
    fcalc_combine1_kernel<<<(HEADS * NNODE) / 256, 256>>>(part, a1s, a1d, wh1,
                                                          f1a, f2a, Ca, Ba, Da);
    // 3) GAT1 fused attention (j-split 8) -> partials; combine -> hmid
    attn_kernel<30, 4, 32, 8, 8><<<dim3(NNODE / 256, HEADS, 8), 128>>>(
        wh1, H1, f1a, Ca, Ba, Da, f2a, adj8, part);
    combine_kernel<30, 32, 8, HEADS><<<(NNODE * HEADS * 30 + 255) / 256, 256>>>(
        part, b1, hmid, H1);
    // 4) wh2 = hmid @ W2
    gemm2_kernel<<<NNODE / 4, 256>>>(hmid, W2, wh2);
    // 5) attention-2 features
    fcalc_kernel<<<NNODE / 256, 256>>>(wh2, H2, H2, a2s, a2d,
                                       NNODE, f1b, f2b, Cb2, Bb2, Db2);
    // 6) GAT2 fused attention (j-split 16) -> partials; combine -> h2
    attn_kernel<50, 8, 16, 8, 16><<<dim3(NNODE / 128, 1, 16), 128>>>(
        wh2, H2, f1b, Cb2, Bb2, Db2, f2b, adj8, part);
    combine_kernel<50, 64, 16, 1><<<(NNODE * H2 + 255) / 256, 256>>>(
        part, b2, h2, H2);
    // 7) FiLM + classifier -> logits in d_out[0..8191]
    film_kernel<<<NNODE / 128, 128>>>(h2, lloc, Wl1, bl1, Wl2, bl2,
                                      Wg, bg, Wb, bb, Wgate, bgate, Wc, outp);
    // 8) hemisphere bias
    hemi_dots_kernel<<<240, 128>>>(outp, Ws1, bs1, hsb);
    hemi_fin_kernel<<<1, 256>>>(outp, hsb, Ws2, bs2);
}

// round 11
// speedup vs baseline: 5.0035x; 1.1272x over previous
#include <cuda_runtime.h>
#include <cuda_bf16.h>
#include <cstdint>

#define NNODE 4096
#define FIN   4096
#define H1    120
#define HEADS 4
#define H1P   30
#define H2    50

// ---------------- scratch (static device globals; no allocation) ----------------
__device__ float g_wh1[NNODE * H1];
__device__ float g_hmid[NNODE * H1];
__device__ float g_wh2[NNODE * H2];
__device__ float g_h2[NNODE * H2];
__device__ float g_f1a[HEADS * NNODE], g_f2a[HEADS * NNODE];
__device__ float g_Ca[HEADS * NNODE], g_Ba[HEADS * NNODE], g_Da[HEADS * NNODE];
__device__ float g_f1b[NNODE], g_f2b[NNODE];
__device__ float g_Cb[NNODE], g_Bb[NNODE], g_Db[NNODE];
__device__ unsigned char g_adj8[NNODE * NNODE];     // 16MB packed adjacency
__device__ float g_part[4 * 8 * NNODE * 32];        // 4.19M floats of partials
__device__ float g_wtr[128 * FIN];                  // W1 transposed, K-major
__device__ float g_hs[240];                         // hemi hidden

__device__ __forceinline__ float leakyf(float x) { return fmaxf(x, 0.1f * x); }

// ---------------- mma.sync helpers ----------------
__device__ __forceinline__ void mma1688(float c[4], uint32_t a0, uint32_t a1,
                                        uint32_t a2, uint32_t a3,
                                        uint32_t b0, uint32_t b1) {
    asm volatile(
        "mma.sync.aligned.m16n8k8.row.col.f32.tf32.tf32.f32 "
        "{%0,%1,%2,%3}, {%4,%5,%6,%7}, {%8,%9}, {%0,%1,%2,%3};"
        : "+f"(c[0]), "+f"(c[1]), "+f"(c[2]), "+f"(c[3])
        : "r"(a0), "r"(a1), "r"(a2), "r"(a3), "r"(b0), "r"(b1));
}
__device__ __forceinline__ void split_bits(float v, uint32_t& hi, uint32_t& lo) {
    uint32_t h = __float_as_uint(v) & 0xFFFFE000u;
    hi = h;
    lo = __float_as_uint(v - __uint_as_float(h));
}

// ---------------- pack adj int32 -> uint8 ----------------
__global__ void pack_adj_kernel(const int4* __restrict__ adj, uchar4* __restrict__ out, int n4) {
    int i = blockIdx.x * blockDim.x + threadIdx.x;
    if (i >= n4) return;
    int4 v = adj[i];
    out[i] = make_uchar4(v.x ? 1 : 0, v.y ? 1 : 0, v.z ? 1 : 0, v.w ? 1 : 0);
}

// ---------------- transpose W1 -> wtr[128][4096] ----------------
__global__ void transpose_w1_kernel(const float* __restrict__ W1, float* __restrict__ wtr) {
    int idx = blockIdx.x * blockDim.x + threadIdx.x;
    int c = idx >> 10;
    int k4 = (idx & 1023) * 4;
    float4 v = make_float4(0.f, 0.f, 0.f, 0.f);
    if (c < H1) {
        int h = c / 30, o = c % 30;
        const float* base = W1 + ((size_t)h * FIN) * H1P + o;
        v.x = base[(size_t)(k4 + 0) * H1P];
        v.y = base[(size_t)(k4 + 1) * H1P];
        v.z = base[(size_t)(k4 + 2) * H1P];
        v.w = base[(size_t)(k4 + 3) * H1P];
    }
    *(float4*)(wtr + (size_t)c * FIN + k4) = v;
}

// ---------------- GEMM1 via mma.sync TF32, 3-way fp32 split ----------------
#define G1_BM 64
#define G1_LDS 36
#define G1_ASZ (G1_BM * G1_LDS)
#define G1_BSZ (128 * G1_LDS)
#define G1_STAGE (G1_ASZ + G1_BSZ)

__global__ void __launch_bounds__(256, 1)
gemm1_mma_kernel(const float* __restrict__ x, const float* __restrict__ wtr,
                 float* __restrict__ part) {
    extern __shared__ float sm[];
    const int tid = threadIdx.x;
    const int wid = tid >> 5;
    const int lane = tid & 31;
    const int lq = lane >> 2, lr = lane & 3;
    const int warp_m = wid >> 1;
    const int warp_n = wid & 1;
    const int m0 = blockIdx.x * G1_BM;
    const int ks = blockIdx.y;
    const int k0base = ks * (FIN / 2);
    const int NT = (FIN / 2) / 32;

    float acc[8][4];
#pragma unroll
    for (int nt = 0; nt < 8; nt++)
#pragma unroll
        for (int i = 0; i < 4; i++) acc[nt][i] = 0.f;

    float4 aP[2], bP[4];
#pragma unroll
    for (int i = 0; i < 2; i++) {
        int u = tid + i * 256;
        int r = u >> 3, c4 = u & 7;
        aP[i] = *(const float4*)(x + (size_t)(m0 + r) * FIN + k0base + c4 * 4);
    }
#pragma unroll
    for (int i = 0; i < 4; i++) {
        int u = tid + i * 256;
        int r = u >> 3, c4 = u & 7;
        bP[i] = *(const float4*)(wtr + (size_t)r * FIN + k0base + c4 * 4);
    }

    for (int t = 0; t < NT; t++) {
        const int b = t & 1;
        float* As = sm + b * G1_STAGE;
        float* Bs = As + G1_ASZ;
#pragma unroll
        for (int i = 0; i < 2; i++) {
            int u = tid + i * 256;
            int r = u >> 3, c4 = u & 7;
            *(float4*)(As + r * G1_LDS + c4 * 4) = aP[i];
        }
#pragma unroll
        for (int i = 0; i < 4; i++) {
            int u = tid + i * 256;
            int r = u >> 3, c4 = u & 7;
            *(float4*)(Bs + r * G1_LDS + c4 * 4) = bP[i];
        }
        __syncthreads();
        if (t + 1 < NT) {
            int kn = k0base + (t + 1) * 32;
#pragma unroll
            for (int i = 0; i < 2; i++) {
                int u = tid + i * 256;
                int r = u >> 3, c4 = u & 7;
                aP[i] = *(const float4*)(x + (size_t)(m0 + r) * FIN + kn + c4 * 4);
            }
#pragma unroll
            for (int i = 0; i < 4; i++) {
                int u = tid + i * 256;
                int r = u >> 3, c4 = u & 7;
                bP[i] = *(const float4*)(wtr + (size_t)r * FIN + kn + c4 * 4);
            }
        }
#pragma unroll
        for (int k8 = 0; k8 < 4; k8++) {
            const int rowA = warp_m * 16 + lq;
            const int colA = k8 * 8 + lr;
            float a0f = As[rowA * G1_LDS + colA];
            float a1f = As[(rowA + 8) * G1_LDS + colA];
            float a2f = As[rowA * G1_LDS + colA + 4];
            float a3f = As[(rowA + 8) * G1_LDS + colA + 4];
            uint32_t ah[4], al[4];
            split_bits(a0f, ah[0], al[0]);
            split_bits(a1f, ah[1], al[1]);
            split_bits(a2f, ah[2], al[2]);
            split_bits(a3f, ah[3], al[3]);
#pragma unroll
            for (int nt = 0; nt < 8; nt++) {
                const int rowB = warp_n * 64 + nt * 8 + lq;
                float b0f = Bs[rowB * G1_LDS + k8 * 8 + lr];
                float b1f = Bs[rowB * G1_LDS + k8 * 8 + lr + 4];
                uint32_t bh0, bl0, bh1, bl1;
                split_bits(b0f, bh0, bl0);
                split_bits(b1f, bh1, bl1);
                mma1688(acc[nt], ah[0], ah[1], ah[2], ah[3], bh0, bh1);
                mma1688(acc[nt], al[0], al[1], al[2], al[3], bh0, bh1);
                mma1688(acc[nt], ah[0], ah[1], ah[2], ah[3], bl0, bl1);
            }
        }
        __syncthreads();
    }

    const int row0 = m0 + warp_m * 16 + lq;
    float* base = part + ((size_t)ks * NNODE) * 120;
#pragma unroll
    for (int nt = 0; nt < 8; nt++) {
        int col = warp_n * 64 + nt * 8 + lr * 2;
        if (col < 120) {
            base[(size_t)row0 * 120 + col] = acc[nt][0];
            base[(size_t)row0 * 120 + col + 1] = acc[nt][1];
            base[(size_t)(row0 + 8) * 120 + col] = acc[nt][2];
            base[(size_t)(row0 + 8) * 120 + col + 1] = acc[nt][3];
        }
    }
}

// ---------------- warp-per-(h,n): combine gemm1 K-partials + attn1 features ------
__global__ void fcalc_combine1_warp(const float* __restrict__ part,
                                    const float* __restrict__ asrc,
                                    const float* __restrict__ adst,
                                    float* __restrict__ wh1,
                                    float* __restrict__ f1r, float* __restrict__ f2r,
                                    float* __restrict__ Cb, float* __restrict__ Bb,
                                    float* __restrict__ Db) {
    int g = (blockIdx.x * blockDim.x + threadIdx.x) >> 5;  // 0..16383
    int lane = threadIdx.x & 31;
    int h = g >> 12;
    int n = g & 4095;
    float f1 = 0.f, f2 = 0.f;
    if (lane < H1P) {
        int c = h * H1P + lane;
        float v = part[(size_t)n * 120 + c] + part[((size_t)NNODE + n) * 120 + c];
        wh1[(size_t)n * H1 + c] = v;
        f1 = v * asrc[h * H1P + lane];
        f2 = v * adst[h * H1P + lane];
    }
#pragma unroll
    for (int off = 16; off; off >>= 1) {
        f1 += __shfl_xor_sync(0xffffffffu, f1, off);
        f2 += __shfl_xor_sync(0xffffffffu, f2, off);
    }
    if (lane == 0) {
        f1r[g] = f1;
        f2r[g] = f2;
        Cb[g] = expf(fminf(-0.9f * f1, 70.f));
        Bb[g] = expf(fminf(f2, 70.f));
        Db[g] = expf(0.1f * fminf(f2, 70.f));
    }
}

// ---------------- warp-per-n: layer-2 attention features ----------------
__global__ void fcalc2_warp(const float* __restrict__ wh2,
                            const float* __restrict__ asrc, const float* __restrict__ adst,
                            float* __restrict__ f1r, float* __restrict__ f2r,
                            float* __restrict__ Cb, float* __restrict__ Bb,
                            float* __restrict__ Db) {
    int n = (blockIdx.x * blockDim.x + threadIdx.x) >> 5;
    int lane = threadIdx.x & 31;
    float f1 = 0.f, f2 = 0.f;
#pragma unroll
    for (int o = lane; o < H2; o += 32) {
        float v = wh2[(size_t)n * H2 + o];
        f1 = fmaf(v, asrc[o], f1);
        f2 = fmaf(v, adst[o], f2);
    }
#pragma unroll
    for (int off = 16; off; off >>= 1) {
        f1 += __shfl_xor_sync(0xffffffffu, f1, off);
        f2 += __shfl_xor_sync(0xffffffffu, f2, off);
    }
    if (lane == 0) {
        f1r[n] = f1;
        f2r[n] = f2;
        Cb[n] = expf(fminf(-0.9f * f1, 70.f));
        Bb[n] = expf(fminf(f2, 70.f));
        Db[n] = expf(0.1f * fminf(f2, 70.f));
    }
}

// ---------------- tensor-core masked-softmax attention (3-split TF32) -----------
// p_ij = adj_ij ? ( (f1_i+f2_j >= 0) ? B_j : C_i * D_j ) : 0, built in registers
// directly in the m16n8k8 A-fragment layout. Z column (=1, tf32-exact) gives the
// exact softmax normalizer in the partials.
template <int NCOL, int NT, int NCOLP, int JS, int OSTR>
__global__ void __launch_bounds__(256)
attn_mma_kernel(const float* __restrict__ wh, int ldwh,
                const float* __restrict__ f1r,
                const float* __restrict__ Cb, const float* __restrict__ Bb,
                const float* __restrict__ Db, const float* __restrict__ f2r,
                const unsigned char* __restrict__ adj8,
                float* __restrict__ dst) {
    __shared__ float whH[32][NCOLP], whL[32][NCOLP];
    __shared__ unsigned char adjs[128][32];
    __shared__ float Bsm[32], Dsm[32], F2sm[32];

    const int tid = threadIdx.x;
    const int wid = tid >> 5;
    const int lane = tid & 31;
    const int lq = lane >> 2, lr = lane & 3;
    const int h = blockIdx.y;
    const int i0 = blockIdx.x * 128;
    const int js = blockIdx.z;
    const int jbeg = js * (NNODE / JS);
    const int jend = jbeg + NNODE / JS;
    const int fo = h * NNODE;
    const int colofs = h * NCOL;

    // per-lane row constants (rows r0 = wid*16+lq, r1 = r0+8)
    const int r0 = wid * 16 + lq;
    const float f1_0 = f1r[fo + i0 + r0];
    const float f1_1 = f1r[fo + i0 + r0 + 8];
    const float C_0 = Cb[fo + i0 + r0];
    const float C_1 = Cb[fo + i0 + r0 + 8];

    float acc[NT][4];
#pragma unroll
    for (int nt = 0; nt < NT; nt++)
#pragma unroll
        for (int i = 0; i < 4; i++) acc[nt][i] = 0.f;

    for (int j0 = jbeg; j0 < jend; j0 += 32) {
        __syncthreads();
        // adj tile 128x32 bytes, coalesced uchar4
#pragma unroll
        for (int u = tid; u < 1024; u += 256) {
            int row = u >> 3, c4 = u & 7;
            *(uchar4*)&adjs[row][c4 * 4] =
                *(const uchar4*)(adj8 + (size_t)(i0 + row) * NNODE + j0 + c4 * 4);
        }
        // WH tile split hi/lo; col NCOL = Z (1.0), cols > NCOL zero
        for (int u = tid; u < 32 * NT * 8; u += 256) {
            int j = u / (NT * 8), o = u % (NT * 8);
            float v;
            if (o < NCOL) v = wh[(size_t)(j0 + j) * ldwh + colofs + o];
            else v = (o == NCOL) ? 1.f : 0.f;
            float hi = __uint_as_float(__float_as_uint(v) & 0xFFFFE000u);
            whH[j][o] = hi;
            whL[j][o] = v - hi;
        }
        if (tid < 32) {
            Bsm[tid] = Bb[fo + j0 + tid];
            Dsm[tid] = Db[fo + j0 + tid];
            F2sm[tid] = f2r[fo + j0 + tid];
        }
        __syncthreads();
#pragma unroll
        for (int k8 = 0; k8 < 4; k8++) {
            const int jb = k8 * 8 + lr;
            float B0 = Bsm[jb], D0 = Dsm[jb], F0 = F2sm[jb];
            float B1 = Bsm[jb + 4], D1 = Dsm[jb + 4], F1 = F2sm[jb + 4];
            unsigned char a00 = adjs[r0][jb];
            unsigned char a10 = adjs[r0 + 8][jb];
            unsigned char a01 = adjs[r0][jb + 4];
            unsigned char a11 = adjs[r0 + 8][jb + 4];
            float p00 = a00 ? ((f1_0 + F0 >= 0.f) ? B0 : C_0 * D0) : 0.f;
            float p10 = a10 ? ((f1_1 + F0 >= 0.f) ? B0 : C_1 * D0) : 0.f;
            float p01 = a01 ? ((f1_0 + F1 >= 0.f) ? B1 : C_0 * D1) : 0.f;
            float p11 = a11 ? ((f1_1 + F1 >= 0.f) ? B1 : C_1 * D1) : 0.f;
            uint32_t ah[4], al[4];
            split_bits(p00, ah[0], al[0]);
            split_bits(p10, ah[1], al[1]);
            split_bits(p01, ah[2], al[2]);
            split_bits(p11, ah[3], al[3]);
#pragma unroll
            for (int nt = 0; nt < NT; nt++) {
                const int cn = nt * 8 + lq;
                float b0 = whH[jb][cn], b1 = whH[jb + 4][cn];
                uint32_t bh0 = __float_as_uint(b0);
                uint32_t bh1 = __float_as_uint(b1);
                uint32_t bl0 = __float_as_uint(whL[jb][cn]);
                uint32_t bl1 = __float_as_uint(whL[jb + 4][cn]);
                mma1688(acc[nt], ah[0], ah[1], ah[2], ah[3], bh0, bh1);
                mma1688(acc[nt], al[0], al[1], al[2], al[3], bh0, bh1);
                mma1688(acc[nt], ah[0], ah[1], ah[2], ah[3], bl0, bl1);
            }
        }
    }

    // epilogue: write partials [(h*JS+js)][row][OSTR]
    const size_t rbase = ((size_t)(h * JS + js) * NNODE + i0 + r0) * OSTR;
#pragma unroll
    for (int nt = 0; nt < NT; nt++) {
        int col = nt * 8 + 2 * lr;
        *(float2*)(dst + rbase + col) = make_float2(acc[nt][0], acc[nt][1]);
        *(float2*)(dst + rbase + (size_t)8 * OSTR + col) = make_float2(acc[nt][2], acc[nt][3]);
    }
}

// ---------------- combine partials -> leaky(sum/z + bias) ----------------
template <int NCOL, int CP4, int JS, int NH>
__global__ void combine_kernel(const float* __restrict__ part,
                               const float* __restrict__ bias,
                               float* __restrict__ out, int ldout) {
    int idx = blockIdx.x * blockDim.x + threadIdx.x;
    if (idx >= NNODE * NH * NCOL) return;
    int row = idx / (NH * NCOL);
    int rem = idx % (NH * NCOL);
    int h = rem / NCOL;
    int c = rem % NCOL;
    float s = 0.f, z = 0.f;
#pragma unroll
    for (int js = 0; js < JS; js++) {
        const float* p = part + ((size_t)(h * JS + js) * NNODE + row) * CP4;
        s += p[c];
        z += p[NCOL];
    }
    out[(size_t)row * ldout + h * NCOL + c] = leakyf(s / z + bias[h * NCOL + c]);
}

// ---------------- GEMM2: wh2 = hmid(4096x120) @ W2(120x50) ----------------
__global__ void gemm2_kernel(const float* __restrict__ hmid,
                             const float* __restrict__ W2,
                             float* __restrict__ wh2) {
    __shared__ float hs[4][120];
    const int n0 = blockIdx.x * 4;
    const int tid = threadIdx.x;
    for (int idx = tid; idx < 4 * 120; idx += blockDim.x)
        hs[idx / 120][idx % 120] = hmid[(size_t)(n0 + idx / 120) * H1 + (idx % 120)];
    __syncthreads();
    if (tid < 200) {
        int r = tid / 50, c = tid % 50;
        float acc = 0.f;
#pragma unroll 8
        for (int k = 0; k < 120; k++) acc = fmaf(hs[r][k], W2[k * 50 + c], acc);
        wh2[(size_t)(n0 + r) * H2 + c] = acc;
    }
}

// ---------------- FiLM + gating + classifier logits ----------------
__global__ void film_kernel(const float* __restrict__ h2,
                            const float* __restrict__ lloc,
                            const float* __restrict__ Wl1, const float* __restrict__ bl1,
                            const float* __restrict__ Wl2, const float* __restrict__ bl2,
                            const float* __restrict__ Wg, const float* __restrict__ bg,
                            const float* __restrict__ Wb, const float* __restrict__ bb,
                            const float* __restrict__ Wgate, const float* __restrict__ bgate,
                            const float* __restrict__ Wc,
                            float* __restrict__ outlogits) {
    int n = blockIdx.x * blockDim.x + threadIdx.x;
    if (n >= NNODE) return;
    float l[16];
#pragma unroll
    for (int k = 0; k < 16; k++) l[k] = lloc[n * 16 + k];
    float z1[32];
#pragma unroll
    for (int j = 0; j < 32; j++) {
        float a = bl1[j];
#pragma unroll
        for (int k = 0; k < 16; k++) a = fmaf(l[k], Wl1[j * 16 + k], a);
        z1[j] = leakyf(a);
    }
    float z2[32];
#pragma unroll
    for (int j = 0; j < 32; j++) {
        float a = bl2[j];
#pragma unroll
        for (int k = 0; k < 32; k++) a = fmaf(z1[k], Wl2[j * 32 + k], a);
        z2[j] = leakyf(a);
    }
    float ga = bgate[0];
#pragma unroll
    for (int k = 0; k < 32; k++) ga = fmaf(z2[k], Wgate[k], ga);
    float g = 1.f / (1.f + expf(-ga));
    float cov = fminf(fmaxf(l[15], 0.f), 1.f);
    g *= cov;

    float l0 = 0.f, l1 = 0.f;
    for (int c = 0; c < 50; c++) {
        float gm = bg[c], bt = bb[c];
#pragma unroll
        for (int k = 0; k < 32; k++) {
            gm = fmaf(z2[k], Wg[c * 32 + k], gm);
            bt = fmaf(z2[k], Wb[c * 32 + k], bt);
        }
        float hv = h2[(size_t)n * H2 + c];
        float hf = hv + g * fmaf(gm, hv, bt);
        l0 = fmaf(hf, Wc[c], l0);
        l1 = fmaf(hf, Wc[50 + c], l1);
    }
    outlogits[n * 2 + 0] = leakyf(l0);
    outlogits[n * 2 + 1] = leakyf(l1);
}

// ---------------- hemisphere SSDB ----------------
__global__ void hemi_dots_kernel(const float* __restrict__ out,
                                 const float* __restrict__ Ws1,
                                 const float* __restrict__ bs1,
                                 float* __restrict__ hs) {
    const int b = blockIdx.x;
    const int hemi = b / 120;
    const int cls = (b / 60) % 2;
    const int k = b % 60;
    const int tid = threadIdx.x;
    const float* lg = out + (size_t)hemi * 2048 * 2 + cls;
    const float* w = Ws1 + (size_t)k * 2048;
    float acc = 0.f;
    for (int m = tid; m < 2048; m += 128) acc = fmaf(lg[2 * m], w[m], acc);
#pragma unroll
    for (int off = 16; off; off >>= 1) acc += __shfl_xor_sync(0xffffffffu, acc, off);
    __shared__ float red[4];
    if ((tid & 31) == 0) red[tid >> 5] = acc;
    __syncthreads();
    if (tid == 0)
        hs[b] = leakyf(red[0] + red[1] + red[2] + red[3] + bs1[k]);
}

__global__ void hemi_fin_kernel(float* __restrict__ out,
                                const float* __restrict__ hs,
                                const float* __restrict__ Ws2,
                                const float* __restrict__ bs2) {
    __shared__ float bsm[4];
    const int tid = threadIdx.x;
    if (tid < 4) {
        int hemi = tid >> 1, cls = tid & 1;
        float acc = bs2[0];
#pragma unroll
        for (int k = 0; k < 60; k++) acc = fmaf(hs[hemi * 120 + cls * 60 + k], Ws2[k], acc);
        bsm[hemi * 2 + cls] = leakyf(acc);
    }
    __syncthreads();
    for (int idx = tid; idx < NNODE * 2; idx += blockDim.x) {
        int n = idx >> 1, cls = idx & 1;
        int hemi = (n >= 2048) ? 1 : 0;
        out[idx] += bsm[hemi * 2 + cls];
    }
    if (tid < 2) out[NNODE * 2 + tid] = 0.5f * (bsm[tid] + bsm[2 + tid]);
}

// ---------------- host launch ----------------
extern "C" void kernel_launch(void* const* d_in, const int* in_sizes, int n_in,
                              void* d_out, int out_size) {
    const float* x_fc  = (const float*)d_in[0];
    const int*   adj   = (const int*)d_in[1];
    const float* lloc  = (const float*)d_in[2];
    const float* W1    = (const float*)d_in[3];
    const float* a1s   = (const float*)d_in[4];
    const float* a1d   = (const float*)d_in[5];
    const float* b1    = (const float*)d_in[6];
    const float* W2    = (const float*)d_in[7];
    const float* a2s   = (const float*)d_in[8];
    const float* a2d   = (const float*)d_in[9];
    const float* b2    = (const float*)d_in[10];
    const float* Wc    = (const float*)d_in[11];
    const float* Wl1   = (const float*)d_in[12];
    const float* bl1   = (const float*)d_in[13];
    const float* Wl2   = (const float*)d_in[14];
    const float* bl2   = (const float*)d_in[15];
    const float* Wg    = (const float*)d_in[16];
    const float* bg    = (const float*)d_in[17];
    const float* Wb    = (const float*)d_in[18];
    const float* bb    = (const float*)d_in[19];
    const float* Wgate = (const float*)d_in[20];
    const float* bgate = (const float*)d_in[21];
    const float* Ws1   = (const float*)d_in[22];
    const float* bs1   = (const float*)d_in[23];
    const float* Ws2   = (const float*)d_in[24];
    const float* bs2   = (const float*)d_in[25];
    float* outp = (float*)d_out;

    float *wh1, *hmid, *wh2, *h2, *part, *hsb, *wtr;
    float *f1a, *f2a, *Ca, *Ba, *Da, *f1b, *f2b, *Cb2, *Bb2, *Db2;
    unsigned char* adj8;
    cudaGetSymbolAddress((void**)&wh1, g_wh1);
    cudaGetSymbolAddress((void**)&hmid, g_hmid);
    cudaGetSymbolAddress((void**)&wh2, g_wh2);
    cudaGetSymbolAddress((void**)&h2, g_h2);
    cudaGetSymbolAddress((void**)&f1a, g_f1a);
    cudaGetSymbolAddress((void**)&f2a, g_f2a);
    cudaGetSymbolAddress((void**)&Ca, g_Ca);
    cudaGetSymbolAddress((void**)&Ba, g_Ba);
    cudaGetSymbolAddress((void**)&Da, g_Da);
    cudaGetSymbolAddress((void**)&f1b, g_f1b);
    cudaGetSymbolAddress((void**)&f2b, g_f2b);
    cudaGetSymbolAddress((void**)&Cb2, g_Cb);
    cudaGetSymbolAddress((void**)&Bb2, g_Bb);
    cudaGetSymbolAddress((void**)&Db2, g_Db);
    cudaGetSymbolAddress((void**)&adj8, g_adj8);
    cudaGetSymbolAddress((void**)&part, g_part);
    cudaGetSymbolAddress((void**)&hsb, g_hs);
    cudaGetSymbolAddress((void**)&wtr, g_wtr);

    // 0) pack adjacency; transpose W1
    pack_adj_kernel<<<NNODE * NNODE / 4 / 256, 256>>>((const int4*)adj, (uchar4*)adj8,
                                                      NNODE * NNODE / 4);
    transpose_w1_kernel<<<512, 256>>>(W1, wtr);
    // 1) wh1 partials via mma.sync TF32 x3 (K-split 2)
    cudaFuncSetAttribute(gemm1_mma_kernel, cudaFuncAttributeMaxDynamicSharedMemorySize,
                         2 * G1_STAGE * (int)sizeof(float));
    gemm1_mma_kernel<<<dim3(NNODE / G1_BM, 2), 256, 2 * G1_STAGE * sizeof(float)>>>(
        x_fc, wtr, part);
    // 2) combine K-partials -> wh1 + attn1 features (warp-per-(h,n))
    fcalc_combine1_warp<<<HEADS * NNODE * 32 / 256, 256>>>(part, a1s, a1d, wh1,
                                                           f1a, f2a, Ca, Ba, Da);
    // 3) GAT1 tensor-core attention (JS=4) -> partials; combine -> hmid
    attn_mma_kernel<30, 4, 40, 4, 32><<<dim3(NNODE / 128, HEADS, 4), 256>>>(
        wh1, H1, f1a, Ca, Ba, Da, f2a, adj8, part);
    combine_kernel<30, 32, 4, HEADS><<<(NNODE * HEADS * 30 + 255) / 256, 256>>>(
        part, b1, hmid, H1);
    // 4) wh2 = hmid @ W2
    gemm2_kernel<<<NNODE / 4, 256>>>(hmid, W2, wh2);
    // 5) attn2 features (warp-per-n)
    fcalc2_warp<<<NNODE * 32 / 256, 256>>>(wh2, a2s, a2d, f1b, f2b, Cb2, Bb2, Db2);
    // 6) GAT2 tensor-core attention (JS=16) -> partials; combine -> h2
    attn_mma_kernel<50, 7, 56, 16, 64><<<dim3(NNODE / 128, 1, 16), 256>>>(
        wh2, H2, f1b, Cb2, Bb2, Db2, f2b, adj8, part);
    combine_kernel<50, 64, 16, 1><<<(NNODE * H2 + 255) / 256, 256>>>(
        part, b2, h2, H2);
    // 7) FiLM + classifier -> logits
    film_kernel<<<NNODE / 128, 128>>>(h2, lloc, Wl1, bl1, Wl2, bl2,
                                      Wg, bg, Wb, bb, Wgate, bgate, Wc, outp);
    // 8) hemisphere bias
    hemi_dots_kernel<<<240, 128>>>(outp, Ws1, bs1, hsb);
    hemi_fin_kernel<<<1, 256>>>(outp, hsb, Ws2, bs2);
}

// round 13
// speedup vs baseline: 5.6069x; 1.1206x over previous
#include <cuda_runtime.h>
#include <cuda_bf16.h>
#include <cstdint>

#define NNODE 4096
#define FIN   4096
#define H1    120
#define HEADS 4
#define H1P   30
#define H2    50

// ---------------- scratch (static device globals; no allocation) ----------------
__device__ float g_wh1[NNODE * H1];
__device__ float g_hmid[NNODE * H1];
__device__ float g_wh2[NNODE * H2];
__device__ float g_h2[NNODE * H2];
__device__ float g_f1a[HEADS * NNODE], g_f2a[HEADS * NNODE];
__device__ float g_Ca[HEADS * NNODE], g_Ba[HEADS * NNODE], g_Da[HEADS * NNODE];
__device__ float g_f1b[NNODE], g_f2b[NNODE];
__device__ float g_Cb[NNODE], g_Bb[NNODE], g_Db[NNODE];
__device__ unsigned char g_adj8[NNODE * NNODE];     // 16MB packed adjacency
__device__ float g_part[4 * 8 * NNODE * 32];        // 4.19M floats of partials
__device__ float g_wtr[128 * FIN];                  // W1 transposed, K-major
__device__ float g_hs[240];                         // hemi hidden

__device__ __forceinline__ float leakyf(float x) { return fmaxf(x, 0.1f * x); }

// ---------------- mma.sync helpers ----------------
__device__ __forceinline__ void mma1688(float c[4], uint32_t a0, uint32_t a1,
                                        uint32_t a2, uint32_t a3,
                                        uint32_t b0, uint32_t b1) {
    asm volatile(
        "mma.sync.aligned.m16n8k8.row.col.f32.tf32.tf32.f32 "
        "{%0,%1,%2,%3}, {%4,%5,%6,%7}, {%8,%9}, {%0,%1,%2,%3};"
        : "+f"(c[0]), "+f"(c[1]), "+f"(c[2]), "+f"(c[3])
        : "r"(a0), "r"(a1), "r"(a2), "r"(a3), "r"(b0), "r"(b1));
}
__device__ __forceinline__ void split_bits(float v, uint32_t& hi, uint32_t& lo) {
    uint32_t h = __float_as_uint(v) & 0xFFFFE000u;
    hi = h;
    lo = __float_as_uint(v - __uint_as_float(h));
}

// ---------------- pack adj int32 -> uint8 ----------------
__global__ void pack_adj_kernel(const int4* __restrict__ adj, uchar4* __restrict__ out, int n4) {
    int i = blockIdx.x * blockDim.x + threadIdx.x;
    if (i >= n4) return;
    int4 v = adj[i];
    out[i] = make_uchar4(v.x ? 1 : 0, v.y ? 1 : 0, v.z ? 1 : 0, v.w ? 1 : 0);
}

// ---------------- transpose W1 -> wtr[128][4096] ----------------
__global__ void transpose_w1_kernel(const float* __restrict__ W1, float* __restrict__ wtr) {
    int idx = blockIdx.x * blockDim.x + threadIdx.x;
    int c = idx >> 10;
    int k4 = (idx & 1023) * 4;
    float4 v = make_float4(0.f, 0.f, 0.f, 0.f);
    if (c < H1) {
        int h = c / 30, o = c % 30;
        const float* base = W1 + ((size_t)h * FIN) * H1P + o;
        v.x = base[(size_t)(k4 + 0) * H1P];
        v.y = base[(size_t)(k4 + 1) * H1P];
        v.z = base[(size_t)(k4 + 2) * H1P];
        v.w = base[(size_t)(k4 + 3) * H1P];
    }
    *(float4*)(wtr + (size_t)c * FIN + k4) = v;
}

// ---------------- GEMM1 via mma.sync TF32, 3-way fp32 split ----------------
#define G1_BM 64
#define G1_LDS 36
#define G1_ASZ (G1_BM * G1_LDS)
#define G1_BSZ (128 * G1_LDS)
#define G1_STAGE (G1_ASZ + G1_BSZ)

__global__ void __launch_bounds__(256, 1)
gemm1_mma_kernel(const float* __restrict__ x, const float* __restrict__ wtr,
                 float* __restrict__ part) {
    extern __shared__ float sm[];
    const int tid = threadIdx.x;
    const int wid = tid >> 5;
    const int lane = tid & 31;
    const int lq = lane >> 2, lr = lane & 3;
    const int warp_m = wid >> 1;
    const int warp_n = wid & 1;
    const int m0 = blockIdx.x * G1_BM;
    const int ks = blockIdx.y;
    const int k0base = ks * (FIN / 2);
    const int NT = (FIN / 2) / 32;

    float acc[8][4];
#pragma unroll
    for (int nt = 0; nt < 8; nt++)
#pragma unroll
        for (int i = 0; i < 4; i++) acc[nt][i] = 0.f;

    float4 aP[2], bP[4];
#pragma unroll
    for (int i = 0; i < 2; i++) {
        int u = tid + i * 256;
        int r = u >> 3, c4 = u & 7;
        aP[i] = *(const float4*)(x + (size_t)(m0 + r) * FIN + k0base + c4 * 4);
    }
#pragma unroll
    for (int i = 0; i < 4; i++) {
        int u = tid + i * 256;
        int r = u >> 3, c4 = u & 7;
        bP[i] = *(const float4*)(wtr + (size_t)r * FIN + k0base + c4 * 4);
    }

    for (int t = 0; t < NT; t++) {
        const int b = t & 1;
        float* As = sm + b * G1_STAGE;
        float* Bs = As + G1_ASZ;
#pragma unroll
        for (int i = 0; i < 2; i++) {
            int u = tid + i * 256;
            int r = u >> 3, c4 = u & 7;
            *(float4*)(As + r * G1_LDS + c4 * 4) = aP[i];
        }
#pragma unroll
        for (int i = 0; i < 4; i++) {
            int u = tid + i * 256;
            int r = u >> 3, c4 = u & 7;
            *(float4*)(Bs + r * G1_LDS + c4 * 4) = bP[i];
        }
        __syncthreads();
        if (t + 1 < NT) {
            int kn = k0base + (t + 1) * 32;
#pragma unroll
            for (int i = 0; i < 2; i++) {
                int u = tid + i * 256;
                int r = u >> 3, c4 = u & 7;
                aP[i] = *(const float4*)(x + (size_t)(m0 + r) * FIN + kn + c4 * 4);
            }
#pragma unroll
            for (int i = 0; i < 4; i++) {
                int u = tid + i * 256;
                int r = u >> 3, c4 = u & 7;
                bP[i] = *(const float4*)(wtr + (size_t)r * FIN + kn + c4 * 4);
            }
        }
#pragma unroll
        for (int k8 = 0; k8 < 4; k8++) {
            const int rowA = warp_m * 16 + lq;
            const int colA = k8 * 8 + lr;
            float a0f = As[rowA * G1_LDS + colA];
            float a1f = As[(rowA + 8) * G1_LDS + colA];
            float a2f = As[rowA * G1_LDS + colA + 4];
            float a3f = As[(rowA + 8) * G1_LDS + colA + 4];
            uint32_t ah[4], al[4];
            split_bits(a0f, ah[0], al[0]);
            split_bits(a1f, ah[1], al[1]);
            split_bits(a2f, ah[2], al[2]);
            split_bits(a3f, ah[3], al[3]);
#pragma unroll
            for (int nt = 0; nt < 8; nt++) {
                const int rowB = warp_n * 64 + nt * 8 + lq;
                float b0f = Bs[rowB * G1_LDS + k8 * 8 + lr];
                float b1f = Bs[rowB * G1_LDS + k8 * 8 + lr + 4];
                uint32_t bh0, bl0, bh1, bl1;
                split_bits(b0f, bh0, bl0);
                split_bits(b1f, bh1, bl1);
                mma1688(acc[nt], ah[0], ah[1], ah[2], ah[3], bh0, bh1);
                mma1688(acc[nt], al[0], al[1], al[2], al[3], bh0, bh1);
                mma1688(acc[nt], ah[0], ah[1], ah[2], ah[3], bl0, bl1);
            }
        }
        __syncthreads();
    }

    const int row0 = m0 + warp_m * 16 + lq;
    float* base = part + ((size_t)ks * NNODE) * 120;
#pragma unroll
    for (int nt = 0; nt < 8; nt++) {
        int col = warp_n * 64 + nt * 8 + lr * 2;
        if (col < 120) {
            base[(size_t)row0 * 120 + col] = acc[nt][0];
            base[(size_t)row0 * 120 + col + 1] = acc[nt][1];
            base[(size_t)(row0 + 8) * 120 + col] = acc[nt][2];
            base[(size_t)(row0 + 8) * 120 + col + 1] = acc[nt][3];
        }
    }
}

// ---------------- warp-per-(h,n): combine gemm1 K-partials + attn1 features ------
__global__ void fcalc_combine1_warp(const float* __restrict__ part,
                                    const float* __restrict__ asrc,
                                    const float* __restrict__ adst,
                                    float* __restrict__ wh1,
                                    float* __restrict__ f1r, float* __restrict__ f2r,
                                    float* __restrict__ Cb, float* __restrict__ Bb,
                                    float* __restrict__ Db) {
    int g = (blockIdx.x * blockDim.x + threadIdx.x) >> 5;  // 0..16383
    int lane = threadIdx.x & 31;
    int h = g >> 12;
    int n = g & 4095;
    float f1 = 0.f, f2 = 0.f;
    if (lane < H1P) {
        int c = h * H1P + lane;
        float v = part[(size_t)n * 120 + c] + part[((size_t)NNODE + n) * 120 + c];
        wh1[(size_t)n * H1 + c] = v;
        f1 = v * asrc[h * H1P + lane];
        f2 = v * adst[h * H1P + lane];
    }
#pragma unroll
    for (int off = 16; off; off >>= 1) {
        f1 += __shfl_xor_sync(0xffffffffu, f1, off);
        f2 += __shfl_xor_sync(0xffffffffu, f2, off);
    }
    if (lane == 0) {
        f1r[g] = f1;
        f2r[g] = f2;
        Cb[g] = expf(fminf(-0.9f * f1, 70.f));
        Bb[g] = expf(fminf(f2, 70.f));
        Db[g] = expf(0.1f * fminf(f2, 70.f));
    }
}

// ---------------- tensor-core masked-softmax attention (3-split TF32) -----------
// Double-buffered tiles, single sync/tile, p-fragments prebuilt in registers.
template <int NCOL, int NT, int NCOLP, int JS, int OSTR>
__global__ void __launch_bounds__(256, 2)
attn_mma_kernel(const float* __restrict__ wh, int ldwh,
                const float* __restrict__ f1r,
                const float* __restrict__ Cb, const float* __restrict__ Bb,
                const float* __restrict__ Db, const float* __restrict__ f2r,
                const unsigned char* __restrict__ adj8,
                float* __restrict__ dst) {
    __shared__ float whH[2][32][NCOLP], whL[2][32][NCOLP];
    __shared__ unsigned char adjs[2][128][32];
    __shared__ float BDF[2][3][32];  // [B, D, F2]

    const int tid = threadIdx.x;
    const int wid = tid >> 5;
    const int lane = tid & 31;
    const int lq = lane >> 2, lr = lane & 3;
    const int h = blockIdx.y;
    const int i0 = blockIdx.x * 128;
    const int js = blockIdx.z;
    const int jbeg = js * (NNODE / JS);
    const int ntiles = (NNODE / JS) / 32;
    const int fo = h * NNODE;
    const int colofs = h * NCOL;

    const int r0 = wid * 16 + lq;
    const float f1_0 = f1r[fo + i0 + r0];
    const float f1_1 = f1r[fo + i0 + r0 + 8];
    const float C_0 = Cb[fo + i0 + r0];
    const float C_1 = Cb[fo + i0 + r0 + 8];

    float acc[NT][4];
#pragma unroll
    for (int nt = 0; nt < NT; nt++)
#pragma unroll
        for (int i = 0; i < 4; i++) acc[nt][i] = 0.f;

    uchar4 a_pf[4];
    float w_pf[NT];
    float bdf_pf = 0.f;

    auto prefetch = [&](int j0) {
#pragma unroll
        for (int i = 0; i < 4; i++) {
            int u = tid + i * 256;
            int row = u >> 3, c4 = u & 7;
            a_pf[i] = *(const uchar4*)(adj8 + (size_t)(i0 + row) * NNODE + j0 + c4 * 4);
        }
#pragma unroll
        for (int i = 0; i < NT; i++) {
            int u = tid + i * 256;
            int j = u / (NT * 8), o = u % (NT * 8);
            float v;
            if (o < NCOL) v = wh[(size_t)(j0 + j) * ldwh + colofs + o];
            else v = (o == NCOL) ? 1.f : 0.f;
            w_pf[i] = v;
        }
        if (tid < 96) {
            int which = tid >> 5, jj = tid & 31;
            const float* src = (which == 0) ? Bb : (which == 1) ? Db : f2r;
            bdf_pf = src[fo + j0 + jj];
        }
    };
    auto store_tile = [&](int b) {
#pragma unroll
        for (int i = 0; i < 4; i++) {
            int u = tid + i * 256;
            int row = u >> 3, c4 = u & 7;
            *(uchar4*)&adjs[b][row][c4 * 4] = a_pf[i];
        }
#pragma unroll
        for (int i = 0; i < NT; i++) {
            int u = tid + i * 256;
            int j = u / (NT * 8), o = u % (NT * 8);
            float v = w_pf[i];
            float hi = __uint_as_float(__float_as_uint(v) & 0xFFFFE000u);
            whH[b][j][o] = hi;
            whL[b][j][o] = v - hi;
        }
        if (tid < 96) BDF[b][tid >> 5][tid & 31] = bdf_pf;
    };

    prefetch(jbeg);
    store_tile(0);
    __syncthreads();

    for (int t = 0; t < ntiles; t++) {
        const int b = t & 1;
        if (t + 1 < ntiles) prefetch(jbeg + (t + 1) * 32);

        // ---- phase 1: build all p-fragments for this tile (registers) ----
        uint32_t ah[4][4], al[4][4];
#pragma unroll
        for (int k8 = 0; k8 < 4; k8++) {
            uint2 rowT = *(const uint2*)&adjs[b][r0][k8 * 8];
            uint2 rowU = *(const uint2*)&adjs[b][r0 + 8][k8 * 8];
            unsigned a00 = (rowT.x >> (lr * 8)) & 0xFF;
            unsigned a01 = (rowT.y >> (lr * 8)) & 0xFF;
            unsigned a10 = (rowU.x >> (lr * 8)) & 0xFF;
            unsigned a11 = (rowU.y >> (lr * 8)) & 0xFF;
            int jb = k8 * 8 + lr;
            float B0 = BDF[b][0][jb], D0 = BDF[b][1][jb], F0 = BDF[b][2][jb];
            float B1 = BDF[b][0][jb + 4], D1 = BDF[b][1][jb + 4], F1 = BDF[b][2][jb + 4];
            float p00 = a00 ? ((f1_0 + F0 >= 0.f) ? B0 : C_0 * D0) : 0.f;
            float p10 = a10 ? ((f1_1 + F0 >= 0.f) ? B0 : C_1 * D0) : 0.f;
            float p01 = a01 ? ((f1_0 + F1 >= 0.f) ? B1 : C_0 * D1) : 0.f;
            float p11 = a11 ? ((f1_1 + F1 >= 0.f) ? B1 : C_1 * D1) : 0.f;
            split_bits(p00, ah[k8][0], al[k8][0]);
            split_bits(p10, ah[k8][1], al[k8][1]);
            split_bits(p01, ah[k8][2], al[k8][2]);
            split_bits(p11, ah[k8][3], al[k8][3]);
        }
        // ---- phase 2: uninterrupted mma stream ----
#pragma unroll
        for (int k8 = 0; k8 < 4; k8++) {
            const int jb = k8 * 8 + lr;
#pragma unroll
            for (int nt = 0; nt < NT; nt++) {
                const int cn = nt * 8 + lq;
                uint32_t bh0 = __float_as_uint(whH[b][jb][cn]);
                uint32_t bh1 = __float_as_uint(whH[b][jb + 4][cn]);
                uint32_t bl0 = __float_as_uint(whL[b][jb][cn]);
                uint32_t bl1 = __float_as_uint(whL[b][jb + 4][cn]);
                mma1688(acc[nt], ah[k8][0], ah[k8][1], ah[k8][2], ah[k8][3], bh0, bh1);
                mma1688(acc[nt], al[k8][0], al[k8][1], al[k8][2], al[k8][3], bh0, bh1);
                mma1688(acc[nt], ah[k8][0], ah[k8][1], ah[k8][2], ah[k8][3], bl0, bl1);
            }
        }
        if (t + 1 < ntiles) {
            store_tile(b ^ 1);
            __syncthreads();
        }
    }

    // epilogue: write partials [(h*JS+js)][row][OSTR]
    const size_t rbase = ((size_t)(h * JS + js) * NNODE + i0 + r0) * OSTR;
#pragma unroll
    for (int nt = 0; nt < NT; nt++) {
        int col = nt * 8 + 2 * lr;
        *(float2*)(dst + rbase + col) = make_float2(acc[nt][0], acc[nt][1]);
        *(float2*)(dst + rbase + (size_t)8 * OSTR + col) = make_float2(acc[nt][2], acc[nt][3]);
    }
}

// ---------------- combine partials -> leaky(sum/z + bias) ----------------
template <int NCOL, int CP4, int JS, int NH>
__global__ void combine_kernel(const float* __restrict__ part,
                               const float* __restrict__ bias,
                               float* __restrict__ out, int ldout) {
    int idx = blockIdx.x * blockDim.x + threadIdx.x;
    if (idx >= NNODE * NH * NCOL) return;
    int row = idx / (NH * NCOL);
    int rem = idx % (NH * NCOL);
    int h = rem / NCOL;
    int c = rem % NCOL;
    float s = 0.f, z = 0.f;
#pragma unroll
    for (int js = 0; js < JS; js++) {
        const float* p = part + ((size_t)(h * JS + js) * NNODE + row) * CP4;
        s += p[c];
        z += p[NCOL];
    }
    out[(size_t)row * ldout + h * NCOL + c] = leakyf(s / z + bias[h * NCOL + c]);
}

// ---------------- GEMM2 + fused attn2 features ----------------
__global__ void gemm2_fused_kernel(const float* __restrict__ hmid,
                                   const float* __restrict__ W2,
                                   const float* __restrict__ a2s,
                                   const float* __restrict__ a2d,
                                   float* __restrict__ wh2,
                                   float* __restrict__ f1r, float* __restrict__ f2r,
                                   float* __restrict__ Cb, float* __restrict__ Bb,
                                   float* __restrict__ Db) {
    __shared__ float hs[4][120];
    __shared__ float sacc[4][50];
    const int n0 = blockIdx.x * 4;
    const int tid = threadIdx.x;
    for (int idx = tid; idx < 4 * 120; idx += blockDim.x)
        hs[idx / 120][idx % 120] = hmid[(size_t)(n0 + idx / 120) * H1 + (idx % 120)];
    __syncthreads();
    if (tid < 200) {
        int r = tid / 50, c = tid % 50;
        float acc = 0.f;
#pragma unroll 8
        for (int k = 0; k < 120; k++) acc = fmaf(hs[r][k], W2[k * 50 + c], acc);
        wh2[(size_t)(n0 + r) * H2 + c] = acc;
        sacc[r][c] = acc;
    }
    __syncthreads();
    if (tid < 4) {
        float f1 = 0.f, f2 = 0.f;
#pragma unroll 10
        for (int c = 0; c < 50; c++) {
            float v = sacc[tid][c];
            f1 = fmaf(v, a2s[c], f1);
            f2 = fmaf(v, a2d[c], f2);
        }
        int n = n0 + tid;
        f1r[n] = f1;
        f2r[n] = f2;
        Cb[n] = expf(fminf(-0.9f * f1, 70.f));
        Bb[n] = expf(fminf(f2, 70.f));
        Db[n] = expf(0.1f * fminf(f2, 70.f));
    }
}

// ---------------- FiLM + gating + classifier logits ----------------
__global__ void film_kernel(const float* __restrict__ h2,
                            const float* __restrict__ lloc,
                            const float* __restrict__ Wl1, const float* __restrict__ bl1,
                            const float* __restrict__ Wl2, const float* __restrict__ bl2,
                            const float* __restrict__ Wg, const float* __restrict__ bg,
                            const float* __restrict__ Wb, const float* __restrict__ bb,
                            const float* __restrict__ Wgate, const float* __restrict__ bgate,
                            const float* __restrict__ Wc,
                            float* __restrict__ outlogits) {
    int n = blockIdx.x * blockDim.x + threadIdx.x;
    if (n >= NNODE) return;
    float l[16];
#pragma unroll
    for (int k = 0; k < 16; k++) l[k] = lloc[n * 16 + k];
    float z1[32];
#pragma unroll
    for (int j = 0; j < 32; j++) {
        float a = bl1[j];
#pragma unroll
        for (int k = 0; k < 16; k++) a = fmaf(l[k], Wl1[j * 16 + k], a);
        z1[j] = leakyf(a);
    }
    float z2[32];
#pragma unroll
    for (int j = 0; j < 32; j++) {
        float a = bl2[j];
#pragma unroll
        for (int k = 0; k < 32; k++) a = fmaf(z1[k], Wl2[j * 32 + k], a);
        z2[j] = leakyf(a);
    }
    float ga = bgate[0];
#pragma unroll
    for (int k = 0; k < 32; k++) ga = fmaf(z2[k], Wgate[k], ga);
    float g = 1.f / (1.f + expf(-ga));
    float cov = fminf(fmaxf(l[15], 0.f), 1.f);
    g *= cov;

    float l0 = 0.f, l1 = 0.f;
    for (int c = 0; c < 50; c++) {
        float gm = bg[c], bt = bb[c];
#pragma unroll
        for (int k = 0; k < 32; k++) {
            gm = fmaf(z2[k], Wg[c * 32 + k], gm);
            bt = fmaf(z2[k], Wb[c * 32 + k], bt);
        }
        float hv = h2[(size_t)n * H2 + c];
        float hf = hv + g * fmaf(gm, hv, bt);
        l0 = fmaf(hf, Wc[c], l0);
        l1 = fmaf(hf, Wc[50 + c], l1);
    }
    outlogits[n * 2 + 0] = leakyf(l0);
    outlogits[n * 2 + 1] = leakyf(l1);
}

// ---------------- hemisphere SSDB ----------------
__global__ void hemi_dots_kernel(const float* __restrict__ out,
                                 const float* __restrict__ Ws1,
                                 const float* __restrict__ bs1,
                                 float* __restrict__ hs) {
    const int b = blockIdx.x;
    const int hemi = b / 120;
    const int cls = (b / 60) % 2;
    const int k = b % 60;
    const int tid = threadIdx.x;
    const float* lg = out + (size_t)hemi * 2048 * 2 + cls;
    const float* w = Ws1 + (size_t)k * 2048;
    float acc = 0.f;
    for (int m = tid; m < 2048; m += 128) acc = fmaf(lg[2 * m], w[m], acc);
#pragma unroll
    for (int off = 16; off; off >>= 1) acc += __shfl_xor_sync(0xffffffffu, acc, off);
    __shared__ float red[4];
    if ((tid & 31) == 0) red[tid >> 5] = acc;
    __syncthreads();
    if (tid == 0)
        hs[b] = leakyf(red[0] + red[1] + red[2] + red[3] + bs1[k]);
}

__global__ void hemi_fin_kernel(float* __restrict__ out,
                                const float* __restrict__ hs,
                                const float* __restrict__ Ws2,
                                const float* __restrict__ bs2) {
    __shared__ float bsm[4];
    const int tid = threadIdx.x;
    if (tid < 4) {
        int hemi = tid >> 1, cls = tid & 1;
        float acc = bs2[0];
#pragma unroll
        for (int k = 0; k < 60; k++) acc = fmaf(hs[hemi * 120 + cls * 60 + k], Ws2[k], acc);
        bsm[hemi * 2 + cls] = leakyf(acc);
    }
    __syncthreads();
    for (int idx = tid; idx < NNODE * 2; idx += blockDim.x) {
        int n = idx >> 1, cls = idx & 1;
        int hemi = (n >= 2048) ? 1 : 0;
        out[idx] += bsm[hemi * 2 + cls];
    }
    if (tid < 2) out[NNODE * 2 + tid] = 0.5f * (bsm[tid] + bsm[2 + tid]);
}

// ---------------- host launch ----------------
extern "C" void kernel_launch(void* const* d_in, const int* in_sizes, int n_in,
                              void* d_out, int out_size) {
    const float* x_fc  = (const float*)d_in[0];
    const int*   adj   = (const int*)d_in[1];
    const float* lloc  = (const float*)d_in[2];
    const float* W1    = (const float*)d_in[3];
    const float* a1s   = (const float*)d_in[4];
    const float* a1d   = (const float*)d_in[5];
    const float* b1    = (const float*)d_in[6];
    const float* W2    = (const float*)d_in[7];
    const float* a2s   = (const float*)d_in[8];
    const float* a2d   = (const float*)d_in[9];
    const float* b2    = (const float*)d_in[10];
    const float* Wc    = (const float*)d_in[11];
    const float* Wl1   = (const float*)d_in[12];
    const float* bl1   = (const float*)d_in[13];
    const float* Wl2   = (const float*)d_in[14];
    const float* bl2   = (const float*)d_in[15];
    const float* Wg    = (const float*)d_in[16];
    const float* bg    = (const float*)d_in[17];
    const float* Wb    = (const float*)d_in[18];
    const float* bb    = (const float*)d_in[19];
    const float* Wgate = (const float*)d_in[20];
    const float* bgate = (const float*)d_in[21];
    const float* Ws1   = (const float*)d_in[22];
    const float* bs1   = (const float*)d_in[23];
    const float* Ws2   = (const float*)d_in[24];
    const float* bs2   = (const float*)d_in[25];
    float* outp = (float*)d_out;

    float *wh1, *hmid, *wh2, *h2, *part, *hsb, *wtr;
    float *f1a, *f2a, *Ca, *Ba, *Da, *f1b, *f2b, *Cb2, *Bb2, *Db2;
    unsigned char* adj8;
    cudaGetSymbolAddress((void**)&wh1, g_wh1);
    cudaGetSymbolAddress((void**)&hmid, g_hmid);
    cudaGetSymbolAddress((void**)&wh2, g_wh2);
    cudaGetSymbolAddress((void**)&h2, g_h2);
    cudaGetSymbolAddress((void**)&f1a, g_f1a);
    cudaGetSymbolAddress((void**)&f2a, g_f2a);
    cudaGetSymbolAddress((void**)&Ca, g_Ca);
    cudaGetSymbolAddress((void**)&Ba, g_Ba);
    cudaGetSymbolAddress((void**)&Da, g_Da);
    cudaGetSymbolAddress((void**)&f1b, g_f1b);
    cudaGetSymbolAddress((void**)&f2b, g_f2b);
    cudaGetSymbolAddress((void**)&Cb2, g_Cb);
    cudaGetSymbolAddress((void**)&Bb2, g_Bb);
    cudaGetSymbolAddress((void**)&Db2, g_Db);
    cudaGetSymbolAddress((void**)&adj8, g_adj8);
    cudaGetSymbolAddress((void**)&part, g_part);
    cudaGetSymbolAddress((void**)&hsb, g_hs);
    cudaGetSymbolAddress((void**)&wtr, g_wtr);

    // 0) pack adjacency; transpose W1
    pack_adj_kernel<<<NNODE * NNODE / 4 / 256, 256>>>((const int4*)adj, (uchar4*)adj8,
                                                      NNODE * NNODE / 4);
    transpose_w1_kernel<<<512, 256>>>(W1, wtr);
    // 1) wh1 partials via mma.sync TF32 x3 (K-split 2)
    cudaFuncSetAttribute(gemm1_mma_kernel, cudaFuncAttributeMaxDynamicSharedMemorySize,
                         2 * G1_STAGE * (int)sizeof(float));
    gemm1_mma_kernel<<<dim3(NNODE / G1_BM, 2), 256, 2 * G1_STAGE * sizeof(float)>>>(
        x_fc, wtr, part);
    // 2) combine K-partials -> wh1 + attn1 features
    fcalc_combine1_warp<<<HEADS * NNODE * 32 / 256, 256>>>(part, a1s, a1d, wh1,
                                                           f1a, f2a, Ca, Ba, Da);
    // 3) GAT1 tensor-core attention (JS=8) -> partials; combine -> hmid
    attn_mma_kernel<30, 4, 40, 8, 32><<<dim3(NNODE / 128, HEADS, 8), 256>>>(
        wh1, H1, f1a, Ca, Ba, Da, f2a, adj8, part);
    combine_kernel<30, 32, 8, HEADS><<<(NNODE * HEADS * 30 + 255) / 256, 256>>>(
        part, b1, hmid, H1);
    // 4) wh2 = hmid @ W2 (+ fused attn2 features)
    gemm2_fused_kernel<<<NNODE / 4, 256>>>(hmid, W2, a2s, a2d, wh2,
                                           f1b, f2b, Cb2, Bb2, Db2);
    // 5) GAT2 tensor-core attention (JS=16) -> partials; combine -> h2
    attn_mma_kernel<50, 7, 56, 16, 64><<<dim3(NNODE / 128, 1, 16), 256>>>(
        wh2, H2, f1b, Cb2, Bb2, Db2, f2b, adj8, part);
    combine_kernel<50, 64, 16, 1><<<(NNODE * H2 + 255) / 256, 256>>>(
        part, b2, h2, H2);
    // 6) FiLM + classifier -> logits
    film_kernel<<<NNODE / 128, 128>>>(h2, lloc, Wl1, bl1, Wl2, bl2,
                                      Wg, bg, Wb, bb, Wgate, bgate, Wc, outp);
    // 7) hemisphere bias
    hemi_dots_kernel<<<240, 128>>>(outp, Ws1, bs1, hsb);
    hemi_fin_kernel<<<1, 256>>>(outp, hsb, Ws2, bs2);
}

// round 15
// speedup vs baseline: 6.1050x; 1.0888x over previous
#include <cuda_runtime.h>
#include <cuda_bf16.h>
#include <cstdint>

#define NNODE 4096
#define FIN   4096
#define H1    120
#define HEADS 4
#define H1P   30
#define H2    50

// ---------------- scratch (static device globals; no allocation) ----------------
__device__ float g_wh1[NNODE * H1];
__device__ float g_hmid[NNODE * H1];
__device__ float g_wh2[NNODE * H2];
__device__ float g_h2[NNODE * H2];
__device__ float g_f1a[HEADS * NNODE], g_f2a[HEADS * NNODE];
__device__ float g_Ca[HEADS * NNODE], g_Ba[HEADS * NNODE], g_Da[HEADS * NNODE];
__device__ float g_f1b[NNODE], g_f2b[NNODE];
__device__ float g_Cb[NNODE], g_Bb[NNODE], g_Db[NNODE];
__device__ unsigned char g_adj8[NNODE * NNODE];     // 16MB packed adjacency
__device__ float g_part[4 * 8 * NNODE * 32];        // partials
__device__ float g_wtr[128 * FIN];                  // W1 transposed, K-major
__device__ float g_hs[240];                         // hemi hidden

__device__ __forceinline__ float leakyf(float x) { return fmaxf(x, 0.1f * x); }

// ---------------- mma.sync helpers ----------------
__device__ __forceinline__ void mma1688(float c[4], uint32_t a0, uint32_t a1,
                                        uint32_t a2, uint32_t a3,
                                        uint32_t b0, uint32_t b1) {
    asm volatile(
        "mma.sync.aligned.m16n8k8.row.col.f32.tf32.tf32.f32 "
        "{%0,%1,%2,%3}, {%4,%5,%6,%7}, {%8,%9}, {%0,%1,%2,%3};"
        : "+f"(c[0]), "+f"(c[1]), "+f"(c[2]), "+f"(c[3])
        : "r"(a0), "r"(a1), "r"(a2), "r"(a3), "r"(b0), "r"(b1));
}
__device__ __forceinline__ void mma_bf16(float c[4], uint32_t a0, uint32_t a1,
                                         uint32_t a2, uint32_t a3,
                                         uint32_t b0, uint32_t b1) {
    asm volatile(
        "mma.sync.aligned.m16n8k16.row.col.f32.bf16.bf16.f32 "
        "{%0,%1,%2,%3}, {%4,%5,%6,%7}, {%8,%9}, {%0,%1,%2,%3};"
        : "+f"(c[0]), "+f"(c[1]), "+f"(c[2]), "+f"(c[3])
        : "r"(a0), "r"(a1), "r"(a2), "r"(a3), "r"(b0), "r"(b1));
}
__device__ __forceinline__ void split_bits(float v, uint32_t& hi, uint32_t& lo) {
    uint32_t h = __float_as_uint(v) & 0xFFFFE000u;
    hi = h;
    lo = __float_as_uint(v - __uint_as_float(h));
}
// pack truncated-bf16 of (x, y) -> bf16x2 (low half = x)
__device__ __forceinline__ uint32_t packhi(float x, float y) {
    return __byte_perm(__float_as_uint(x), __float_as_uint(y), 0x7632);
}
__device__ __forceinline__ float trunc_res(float v) {
    return v - __uint_as_float(__float_as_uint(v) & 0xFFFF0000u);
}

// ---------------- fused prep: pack adj + transpose W1 ----------------
__global__ void prep_kernel(const int4* __restrict__ adj, uchar4* __restrict__ adj8,
                            const float* __restrict__ W1, float* __restrict__ wtr) {
    int bid = blockIdx.x;
    if (bid < 16384) {
        int i = bid * 256 + threadIdx.x;
        int4 v = adj[i];
        adj8[i] = make_uchar4(v.x ? 1 : 0, v.y ? 1 : 0, v.z ? 1 : 0, v.w ? 1 : 0);
    } else {
        int idx = (bid - 16384) * 256 + threadIdx.x;  // < 131072
        int c = idx >> 10;
        int k4 = (idx & 1023) * 4;
        float4 v = make_float4(0.f, 0.f, 0.f, 0.f);
        if (c < H1) {
            int h = c / 30, o = c % 30;
            const float* base = W1 + ((size_t)h * FIN) * H1P + o;
            v.x = base[(size_t)(k4 + 0) * H1P];
            v.y = base[(size_t)(k4 + 1) * H1P];
            v.z = base[(size_t)(k4 + 2) * H1P];
            v.w = base[(size_t)(k4 + 3) * H1P];
        }
        *(float4*)(wtr + (size_t)c * FIN + k4) = v;
    }
}

// ---------------- GEMM1 via mma.sync TF32, 3-way fp32 split ----------------
#define G1_BM 64
#define G1_LDS 36
#define G1_ASZ (G1_BM * G1_LDS)
#define G1_BSZ (128 * G1_LDS)
#define G1_STAGE (G1_ASZ + G1_BSZ)

__global__ void __launch_bounds__(256, 1)
gemm1_mma_kernel(const float* __restrict__ x, const float* __restrict__ wtr,
                 float* __restrict__ part) {
    extern __shared__ float sm[];
    const int tid = threadIdx.x;
    const int wid = tid >> 5;
    const int lane = tid & 31;
    const int lq = lane >> 2, lr = lane & 3;
    const int warp_m = wid >> 1;
    const int warp_n = wid & 1;
    const int m0 = blockIdx.x * G1_BM;
    const int ks = blockIdx.y;
    const int k0base = ks * (FIN / 2);
    const int NT = (FIN / 2) / 32;

    float acc[8][4];
#pragma unroll
    for (int nt = 0; nt < 8; nt++)
#pragma unroll
        for (int i = 0; i < 4; i++) acc[nt][i] = 0.f;

    float4 aP[2], bP[4];
#pragma unroll
    for (int i = 0; i < 2; i++) {
        int u = tid + i * 256;
        int r = u >> 3, c4 = u & 7;
        aP[i] = *(const float4*)(x + (size_t)(m0 + r) * FIN + k0base + c4 * 4);
    }
#pragma unroll
    for (int i = 0; i < 4; i++) {
        int u = tid + i * 256;
        int r = u >> 3, c4 = u & 7;
        bP[i] = *(const float4*)(wtr + (size_t)r * FIN + k0base + c4 * 4);
    }

    for (int t = 0; t < NT; t++) {
        const int b = t & 1;
        float* As = sm + b * G1_STAGE;
        float* Bs = As + G1_ASZ;
#pragma unroll
        for (int i = 0; i < 2; i++) {
            int u = tid + i * 256;
            int r = u >> 3, c4 = u & 7;
            *(float4*)(As + r * G1_LDS + c4 * 4) = aP[i];
        }
#pragma unroll
        for (int i = 0; i < 4; i++) {
            int u = tid + i * 256;
            int r = u >> 3, c4 = u & 7;
            *(float4*)(Bs + r * G1_LDS + c4 * 4) = bP[i];
        }
        __syncthreads();
        if (t + 1 < NT) {
            int kn = k0base + (t + 1) * 32;
#pragma unroll
            for (int i = 0; i < 2; i++) {
                int u = tid + i * 256;
                int r = u >> 3, c4 = u & 7;
                aP[i] = *(const float4*)(x + (size_t)(m0 + r) * FIN + kn + c4 * 4);
            }
#pragma unroll
            for (int i = 0; i < 4; i++) {
                int u = tid + i * 256;
                int r = u >> 3, c4 = u & 7;
                bP[i] = *(const float4*)(wtr + (size_t)r * FIN + kn + c4 * 4);
            }
        }
#pragma unroll
        for (int k8 = 0; k8 < 4; k8++) {
            const int rowA = warp_m * 16 + lq;
            const int colA = k8 * 8 + lr;
            float a0f = As[rowA * G1_LDS + colA];
            float a1f = As[(rowA + 8) * G1_LDS + colA];
            float a2f = As[rowA * G1_LDS + colA + 4];
            float a3f = As[(rowA + 8) * G1_LDS + colA + 4];
            uint32_t ah[4], al[4];
            split_bits(a0f, ah[0], al[0]);
            split_bits(a1f, ah[1], al[1]);
            split_bits(a2f, ah[2], al[2]);
            split_bits(a3f, ah[3], al[3]);
#pragma unroll
            for (int nt = 0; nt < 8; nt++) {
                const int rowB = warp_n * 64 + nt * 8 + lq;
                float b0f = Bs[rowB * G1_LDS + k8 * 8 + lr];
                float b1f = Bs[rowB * G1_LDS + k8 * 8 + lr + 4];
                uint32_t bh0, bl0, bh1, bl1;
                split_bits(b0f, bh0, bl0);
                split_bits(b1f, bh1, bl1);
                mma1688(acc[nt], ah[0], ah[1], ah[2], ah[3], bh0, bh1);
                mma1688(acc[nt], al[0], al[1], al[2], al[3], bh0, bh1);
                mma1688(acc[nt], ah[0], ah[1], ah[2], ah[3], bl0, bl1);
            }
        }
        __syncthreads();
    }

    const int row0 = m0 + warp_m * 16 + lq;
    float* base = part + ((size_t)ks * NNODE) * 120;
#pragma unroll
    for (int nt = 0; nt < 8; nt++) {
        int col = warp_n * 64 + nt * 8 + lr * 2;
        if (col < 120) {
            base[(size_t)row0 * 120 + col] = acc[nt][0];
            base[(size_t)row0 * 120 + col + 1] = acc[nt][1];
            base[(size_t)(row0 + 8) * 120 + col] = acc[nt][2];
            base[(size_t)(row0 + 8) * 120 + col + 1] = acc[nt][3];
        }
    }
}

// ---------------- warp-per-(h,n): combine gemm1 K-partials + attn1 features ------
__global__ void fcalc_combine1_warp(const float* __restrict__ part,
                                    const float* __restrict__ asrc,
                                    const float* __restrict__ adst,
                                    float* __restrict__ wh1,
                                    float* __restrict__ f1r, float* __restrict__ f2r,
                                    float* __restrict__ Cb, float* __restrict__ Bb,
                                    float* __restrict__ Db) {
    int g = (blockIdx.x * blockDim.x + threadIdx.x) >> 5;  // 0..16383
    int lane = threadIdx.x & 31;
    int h = g >> 12;
    int n = g & 4095;
    float f1 = 0.f, f2 = 0.f;
    if (lane < H1P) {
        int c = h * H1P + lane;
        float v = part[(size_t)n * 120 + c] + part[((size_t)NNODE + n) * 120 + c];
        wh1[(size_t)n * H1 + c] = v;
        f1 = v * asrc[h * H1P + lane];
        f2 = v * adst[h * H1P + lane];
    }
#pragma unroll
    for (int off = 16; off; off >>= 1) {
        f1 += __shfl_xor_sync(0xffffffffu, f1, off);
        f2 += __shfl_xor_sync(0xffffffffu, f2, off);
    }
    if (lane == 0) {
        f1r[g] = f1;
        f2r[g] = f2;
        Cb[g] = expf(fminf(-0.9f * f1, 70.f));
        Bb[g] = expf(fminf(f2, 70.f));
        Db[g] = expf(0.1f * fminf(f2, 70.f));
    }
}

// ---------------- bf16 tensor-core masked-softmax attention (2x2 split) ---------
// p = adj ? ((f1+f2>=0) ? B : C*D) : 0; P = P0+P1, W = W0+W1 (bf16 truncation);
// acc = P0W0 + P0W1 + P1W0 (dropped terms <= 2^-16 * sum p|w| since p >= 0).
// Z column (1.0, exact) carries the softmax normalizer in the partials.
template <int NCOL, int NT, int NTC, int JS, int OSTR>
__global__ void __launch_bounds__(256, 2)
attn_bf16_kernel(const float* __restrict__ wh, int ldwh,
                 const float* __restrict__ f1r,
                 const float* __restrict__ Cb, const float* __restrict__ Bb,
                 const float* __restrict__ Db, const float* __restrict__ f2r,
                 const unsigned char* __restrict__ adj8,
                 float* __restrict__ dst) {
    constexpr int NITEM = (16 * NTC) / 256;
    // whP[buf][kstep][lr][cn_swizzled][4 words {b0h,b0l,b1h,b1l}]
    __shared__ uint32_t whP[2][2][4][NTC][4];
    __shared__ unsigned char adjs[2][128][32];
    __shared__ float BDF[2][3][32];  // B, D, F2 per tile-j

    const int tid = threadIdx.x;
    const int wid = tid >> 5;
    const int lane = tid & 31;
    const int lq = lane >> 2, lr = lane & 3;
    const int h = blockIdx.y;
    const int i0 = blockIdx.x * 128;
    const int js = blockIdx.z;
    const int jbeg = js * (NNODE / JS);
    const int ntiles = (NNODE / JS) / 32;
    const int fo = h * NNODE;
    const int colofs = h * NCOL;

    const int r0 = wid * 16 + lq;
    const float f1_0 = f1r[fo + i0 + r0];
    const float f1_1 = f1r[fo + i0 + r0 + 8];
    const float C_0 = Cb[fo + i0 + r0];
    const float C_1 = Cb[fo + i0 + r0 + 8];

    float acc[NT][4];
#pragma unroll
    for (int nt = 0; nt < NT; nt++)
#pragma unroll
        for (int i = 0; i < 4; i++) acc[nt][i] = 0.f;

    uchar4 a_pf[4];
    float w1_pf[NITEM], w2_pf[NITEM];
    float bdf_pf = 0.f;

    auto prefetch = [&](int j0) {
#pragma unroll
        for (int i = 0; i < 4; i++) {
            int u = tid + i * 256;
            int row = u >> 3, c4 = u & 7;
            a_pf[i] = *(const uchar4*)(adj8 + (size_t)(i0 + row) * NNODE + j0 + c4 * 4);
        }
#pragma unroll
        for (int i = 0; i < NITEM; i++) {
            int u = tid + i * 256;
            int m = u / NTC, cn = u % NTC;
            float v1, v2;
            if (cn < NCOL) {
                v1 = wh[(size_t)(j0 + 2 * m) * ldwh + colofs + cn];
                v2 = wh[(size_t)(j0 + 2 * m + 1) * ldwh + colofs + cn];
            } else {
                v1 = (cn == NCOL) ? 1.f : 0.f;
                v2 = v1;
            }
            w1_pf[i] = v1;
            w2_pf[i] = v2;
        }
        if (tid < 96) {
            int which = tid >> 5, jj = tid & 31;
            const float* src = (which == 0) ? Bb : (which == 1) ? Db : f2r;
            bdf_pf = src[fo + j0 + jj];
        }
    };
    auto store_tile = [&](int b) {
#pragma unroll
        for (int i = 0; i < 4; i++) {
            int u = tid + i * 256;
            int row = u >> 3, c4 = u & 7;
            *(uchar4*)&adjs[b][row][c4 * 4] = a_pf[i];
        }
#pragma unroll
        for (int i = 0; i < NITEM; i++) {
            int u = tid + i * 256;
            int m = u / NTC, cn = u % NTC;
            int ks = m >> 3, mm = m & 7;
            int lr_s = mm & 3, z = mm >> 2;
            uint32_t hi = packhi(w1_pf[i], w2_pf[i]);
            uint32_t lo = packhi(trunc_res(w1_pf[i]), trunc_res(w2_pf[i]));
            *(uint2*)&whP[b][ks][lr_s][cn ^ (2 * lr_s)][2 * z] = make_uint2(hi, lo);
        }
        if (tid < 96) BDF[b][tid >> 5][tid & 31] = bdf_pf;
    };

    prefetch(jbeg);
    store_tile(0);
    __syncthreads();

    for (int t = 0; t < ntiles; t++) {
        const int b = t & 1;
        if (t + 1 < ntiles) prefetch(jbeg + (t + 1) * 32);

#pragma unroll
        for (int ks = 0; ks < 2; ks++) {
            const int jb = ks * 16 + 2 * lr;  // tile-local j of this lane's first pair
            unsigned t0 = *(const unsigned short*)&adjs[b][r0][jb];
            unsigned t1 = *(const unsigned short*)&adjs[b][r0][jb + 8];
            unsigned u0 = *(const unsigned short*)&adjs[b][r0 + 8][jb];
            unsigned u1 = *(const unsigned short*)&adjs[b][r0 + 8][jb + 8];
            float2 Bv0 = *(const float2*)&BDF[b][0][jb];
            float2 Bv1 = *(const float2*)&BDF[b][0][jb + 8];
            float2 Dv0 = *(const float2*)&BDF[b][1][jb];
            float2 Dv1 = *(const float2*)&BDF[b][1][jb + 8];
            float2 Fv0 = *(const float2*)&BDF[b][2][jb];
            float2 Fv1 = *(const float2*)&BDF[b][2][jb + 8];

            auto mkp = [](unsigned a, float f1, float C, float B, float D, float F) {
                float v = (f1 + F >= 0.f) ? B : C * D;
                return a ? v : 0.f;
            };
            float p00 = mkp(t0 & 0xFF, f1_0, C_0, Bv0.x, Dv0.x, Fv0.x);
            float p01 = mkp(t0 >> 8, f1_0, C_0, Bv0.y, Dv0.y, Fv0.y);
            float p02 = mkp(t1 & 0xFF, f1_0, C_0, Bv1.x, Dv1.x, Fv1.x);
            float p03 = mkp(t1 >> 8, f1_0, C_0, Bv1.y, Dv1.y, Fv1.y);
            float p10 = mkp(u0 & 0xFF, f1_1, C_1, Bv0.x, Dv0.x, Fv0.x);
            float p11 = mkp(u0 >> 8, f1_1, C_1, Bv0.y, Dv0.y, Fv0.y);
            float p12 = mkp(u1 & 0xFF, f1_1, C_1, Bv1.x, Dv1.x, Fv1.x);
            float p13 = mkp(u1 >> 8, f1_1, C_1, Bv1.y, Dv1.y, Fv1.y);

            uint32_t a0h = packhi(p00, p01), a1h = packhi(p10, p11);
            uint32_t a2h = packhi(p02, p03), a3h = packhi(p12, p13);
            uint32_t a0l = packhi(trunc_res(p00), trunc_res(p01));
            uint32_t a1l = packhi(trunc_res(p10), trunc_res(p11));
            uint32_t a2l = packhi(trunc_res(p02), trunc_res(p03));
            uint32_t a3l = packhi(trunc_res(p12), trunc_res(p13));

#pragma unroll
            for (int nt = 0; nt < NT; nt++) {
                const int cn = nt * 8 + lq;
                uint4 w = *(const uint4*)&whP[b][ks][lr][cn ^ (2 * lr)][0];
                // w = {b0h, b0l, b1h, b1l}
                mma_bf16(acc[nt], a0h, a1h, a2h, a3h, w.x, w.z);  // P0 @ W0
                mma_bf16(acc[nt], a0l, a1l, a2l, a3l, w.x, w.z);  // P1 @ W0
                mma_bf16(acc[nt], a0h, a1h, a2h, a3h, w.y, w.w);  // P0 @ W1
            }
        }
        if (t + 1 < ntiles) {
            store_tile(b ^ 1);
            __syncthreads();
        }
    }

    // epilogue: write partials [(h*JS+js)][row][OSTR]
    const size_t rbase = ((size_t)(h * JS + js) * NNODE + i0 + r0) * OSTR;
#pragma unroll
    for (int nt = 0; nt < NT; nt++) {
        int col = nt * 8 + 2 * lr;
        *(float2*)(dst + rbase + col) = make_float2(acc[nt][0], acc[nt][1]);
        *(float2*)(dst + rbase + (size_t)8 * OSTR + col) = make_float2(acc[nt][2], acc[nt][3]);
    }
}

// ---------------- combine partials -> leaky(sum/z + bias) ----------------
template <int NCOL, int CP4, int JS, int NH>
__global__ void combine_kernel(const float* __restrict__ part,
                               const float* __restrict__ bias,
                               float* __restrict__ out, int ldout) {
    int idx = blockIdx.x * blockDim.x + threadIdx.x;
    if (idx >= NNODE * NH * NCOL) return;
    int row = idx / (NH * NCOL);
    int rem = idx % (NH * NCOL);
    int h = rem / NCOL;
    int c = rem % NCOL;
    float s = 0.f, z = 0.f;
#pragma unroll
    for (int js = 0; js < JS; js++) {
        const float* p = part + ((size_t)(h * JS + js) * NNODE + row) * CP4;
        s += p[c];
        z += p[NCOL];
    }
    out[(size_t)row * ldout + h * NCOL + c] = leakyf(s / z + bias[h * NCOL + c]);
}

// ---------------- GEMM2 + fused attn2 features ----------------
__global__ void gemm2_fused_kernel(const float* __restrict__ hmid,
                                   const float* __restrict__ W2,
                                   const float* __restrict__ a2s,
                                   const float* __restrict__ a2d,
                                   float* __restrict__ wh2,
                                   float* __restrict__ f1r, float* __restrict__ f2r,
                                   float* __restrict__ Cb, float* __restrict__ Bb,
                                   float* __restrict__ Db) {
    __shared__ float hs[4][120];
    __shared__ float sacc[4][50];
    const int n0 = blockIdx.x * 4;
    const int tid = threadIdx.x;
    for (int idx = tid; idx < 4 * 120; idx += blockDim.x)
        hs[idx / 120][idx % 120] = hmid[(size_t)(n0 + idx / 120) * H1 + (idx % 120)];
    __syncthreads();
    if (tid < 200) {
        int r = tid / 50, c = tid % 50;
        float acc = 0.f;
#pragma unroll 8
        for (int k = 0; k < 120; k++) acc = fmaf(hs[r][k], W2[k * 50 + c], acc);
        wh2[(size_t)(n0 + r) * H2 + c] = acc;
        sacc[r][c] = acc;
    }
    __syncthreads();
    if (tid < 4) {
        float f1 = 0.f, f2 = 0.f;
#pragma unroll 10
        for (int c = 0; c < 50; c++) {
            float v = sacc[tid][c];
            f1 = fmaf(v, a2s[c], f1);
            f2 = fmaf(v, a2d[c], f2);
        }
        int n = n0 + tid;
        f1r[n] = f1;
        f2r[n] = f2;
        Cb[n] = expf(fminf(-0.9f * f1, 70.f));
        Bb[n] = expf(fminf(f2, 70.f));
        Db[n] = expf(0.1f * fminf(f2, 70.f));
    }
}

// ---------------- FiLM + gating + classifier logits ----------------
__global__ void film_kernel(const float* __restrict__ h2,
                            const float* __restrict__ lloc,
                            const float* __restrict__ Wl1, const float* __restrict__ bl1,
                            const float* __restrict__ Wl2, const float* __restrict__ bl2,
                            const float* __restrict__ Wg, const float* __restrict__ bg,
                            const float* __restrict__ Wb, const float* __restrict__ bb,
                            const float* __restrict__ Wgate, const float* __restrict__ bgate,
                            const float* __restrict__ Wc,
                            float* __restrict__ outlogits) {
    int n = blockIdx.x * blockDim.x + threadIdx.x;
    if (n >= NNODE) return;
    float l[16];
#pragma unroll
    for (int k = 0; k < 16; k++) l[k] = lloc[n * 16 + k];
    float z1[32];
#pragma unroll
    for (int j = 0; j < 32; j++) {
        float a = bl1[j];
#pragma unroll
        for (int k = 0; k < 16; k++) a = fmaf(l[k], Wl1[j * 16 + k], a);
        z1[j] = leakyf(a);
    }
    float z2[32];
#pragma unroll
    for (int j = 0; j < 32; j++) {
        float a = bl2[j];
#pragma unroll
        for (int k = 0; k < 32; k++) a = fmaf(z1[k], Wl2[j * 32 + k], a);
        z2[j] = leakyf(a);
    }
    float ga = bgate[0];
#pragma unroll
    for (int k = 0; k < 32; k++) ga = fmaf(z2[k], Wgate[k], ga);
    float g = 1.f / (1.f + expf(-ga));
    float cov = fminf(fmaxf(l[15], 0.f), 1.f);
    g *= cov;

    float l0 = 0.f, l1 = 0.f;
    for (int c = 0; c < 50; c++) {
        float gm = bg[c], bt = bb[c];
#pragma unroll
        for (int k = 0; k < 32; k++) {
            gm = fmaf(z2[k], Wg[c * 32 + k], gm);
            bt = fmaf(z2[k], Wb[c * 32 + k], bt);
        }
        float hv = h2[(size_t)n * H2 + c];
        float hf = hv + g * fmaf(gm, hv, bt);
        l0 = fmaf(hf, Wc[c], l0);
        l1 = fmaf(hf, Wc[50 + c], l1);
    }
    outlogits[n * 2 + 0] = leakyf(l0);
    outlogits[n * 2 + 1] = leakyf(l1);
}

// ---------------- hemisphere SSDB ----------------
__global__ void hemi_dots_kernel(const float* __restrict__ out,
                                 const float* __restrict__ Ws1,
                                 const float* __restrict__ bs1,
                                 float* __restrict__ hs) {
    const int b = blockIdx.x;
    const int hemi = b / 120;
    const int cls = (b / 60) % 2;
    const int k = b % 60;
    const int tid = threadIdx.x;
    const float* lg = out + (size_t)hemi * 2048 * 2 + cls;
    const float* w = Ws1 + (size_t)k * 2048;
    float acc = 0.f;
    for (int m = tid; m < 2048; m += 128) acc = fmaf(lg[2 * m], w[m], acc);
#pragma unroll
    for (int off = 16; off; off >>= 1) acc += __shfl_xor_sync(0xffffffffu, acc, off);
    __shared__ float red[4];
    if ((tid & 31) == 0) red[tid >> 5] = acc;
    __syncthreads();
    if (tid == 0)
        hs[b] = leakyf(red[0] + red[1] + red[2] + red[3] + bs1[k]);
}

__global__ void hemi_fin_kernel(float* __restrict__ out,
                                const float* __restrict__ hs,
                                const float* __restrict__ Ws2,
                                const float* __restrict__ bs2) {
    __shared__ float bsm[4];
    const int tid = threadIdx.x;
    if (tid < 4) {
        int hemi = tid >> 1, cls = tid & 1;
        float acc = bs2[0];
#pragma unroll
        for (int k = 0; k < 60; k++) acc = fmaf(hs[hemi * 120 + cls * 60 + k], Ws2[k], acc);
        bsm[hemi * 2 + cls] = leakyf(acc);
    }
    __syncthreads();
    for (int idx = tid; idx < NNODE * 2; idx += blockDim.x) {
        int n = idx >> 1, cls = idx & 1;
        int hemi = (n >= 2048) ? 1 : 0;
        out[idx] += bsm[hemi * 2 + cls];
    }
    if (tid < 2) out[NNODE * 2 + tid] = 0.5f * (bsm[tid] + bsm[2 + tid]);
}

// ---------------- host launch ----------------
extern "C" void kernel_launch(void* const* d_in, const int* in_sizes, int n_in,
                              void* d_out, int out_size) {
    const float* x_fc  = (const float*)d_in[0];
    const int*   adj   = (const int*)d_in[1];
    const float* lloc  = (const float*)d_in[2];
    const float* W1    = (const float*)d_in[3];
    const float* a1s   = (const float*)d_in[4];
    const float* a1d   = (const float*)d_in[5];
    const float* b1    = (const float*)d_in[6];
    const float* W2    = (const float*)d_in[7];
    const float* a2s   = (const float*)d_in[8];
    const float* a2d   = (const float*)d_in[9];
    const float* b2    = (const float*)d_in[10];
    const float* Wc    = (const float*)d_in[11];
    const float* Wl1   = (const float*)d_in[12];
    const float* bl1   = (const float*)d_in[13];
    const float* Wl2   = (const float*)d_in[14];
    const float* bl2   = (const float*)d_in[15];
    const float* Wg    = (const float*)d_in[16];
    const float* bg    = (const float*)d_in[17];
    const float* Wb    = (const float*)d_in[18];
    const float* bb    = (const float*)d_in[19];
    const float* Wgate = (const float*)d_in[20];
    const float* bgate = (const float*)d_in[21];
    const float* Ws1   = (const float*)d_in[22];
    const float* bs1   = (const float*)d_in[23];
    const float* Ws2   = (const float*)d_in[24];
    const float* bs2   = (const float*)d_in[25];
    float* outp = (float*)d_out;

    float *wh1, *hmid, *wh2, *h2, *part, *hsb, *wtr;
    float *f1a, *f2a, *Ca, *Ba, *Da, *f1b, *f2b, *Cb2, *Bb2, *Db2;
    unsigned char* adj8;
    cudaGetSymbolAddress((void**)&wh1, g_wh1);
    cudaGetSymbolAddress((void**)&hmid, g_hmid);
    cudaGetSymbolAddress((void**)&wh2, g_wh2);
    cudaGetSymbolAddress((void**)&h2, g_h2);
    cudaGetSymbolAddress((void**)&f1a, g_f1a);
    cudaGetSymbolAddress((void**)&f2a, g_f2a);
    cudaGetSymbolAddress((void**)&Ca, g_Ca);
    cudaGetSymbolAddress((void**)&Ba, g_Ba);
    cudaGetSymbolAddress((void**)&Da, g_Da);
    cudaGetSymbolAddress((void**)&f1b, g_f1b);
    cudaGetSymbolAddress((void**)&f2b, g_f2b);
    cudaGetSymbolAddress((void**)&Cb2, g_Cb);
    cudaGetSymbolAddress((void**)&Bb2, g_Bb);
    cudaGetSymbolAddress((void**)&Db2, g_Db);
    cudaGetSymbolAddress((void**)&adj8, g_adj8);
    cudaGetSymbolAddress((void**)&part, g_part);
    cudaGetSymbolAddress((void**)&hsb, g_hs);
    cudaGetSymbolAddress((void**)&wtr, g_wtr);

    // 1) fused prep (pack adj + transpose W1)
    prep_kernel<<<16384 + 512, 256>>>((const int4*)adj, (uchar4*)adj8, W1, wtr);
    // 2) wh1 partials via mma.sync TF32 x3 (K-split 2)
    cudaFuncSetAttribute(gemm1_mma_kernel, cudaFuncAttributeMaxDynamicSharedMemorySize,
                         2 * G1_STAGE * (int)sizeof(float));
    gemm1_mma_kernel<<<dim3(NNODE / G1_BM, 2), 256, 2 * G1_STAGE * sizeof(float)>>>(
        x_fc, wtr, part);
    // 3) combine K-partials -> wh1 + attn1 features
    fcalc_combine1_warp<<<HEADS * NNODE * 32 / 256, 256>>>(part, a1s, a1d, wh1,
                                                           f1a, f2a, Ca, Ba, Da);
    // 4) GAT1 bf16 tensor-core attention (JS=8) -> partials; combine -> hmid
    attn_bf16_kernel<30, 4, 32, 8, 32><<<dim3(NNODE / 128, HEADS, 8), 256>>>(
        wh1, H1, f1a, Ca, Ba, Da, f2a, adj8, part);
    combine_kernel<30, 32, 8, HEADS><<<(NNODE * HEADS * 30 + 255) / 256, 256>>>(
        part, b1, hmid, H1);
    // 5) wh2 = hmid @ W2 (+ fused attn2 features)
    gemm2_fused_kernel<<<NNODE / 4, 256>>>(hmid, W2, a2s, a2d, wh2,
                                           f1b, f2b, Cb2, Bb2, Db2);
    // 6) GAT2 bf16 tensor-core attention (JS=16) -> partials; combine -> h2
    attn_bf16_kernel<50, 7, 64, 16, 64><<<dim3(NNODE / 128, 1, 16), 256>>>(
        wh2, H2, f1b, Cb2, Bb2, Db2, f2b, adj8, part);
    combine_kernel<50, 64, 16, 1><<<(NNODE * H2 + 255) / 256, 256>>>(
        part, b2, h2, H2);
    // 7) FiLM + classifier -> logits
    film_kernel<<<NNODE / 128, 128>>>(h2, lloc, Wl1, bl1, Wl2, bl2,
                                      Wg, bg, Wb, bb, Wgate, bgate, Wc, outp);
    // 8) hemisphere bias
    hemi_dots_kernel<<<240, 128>>>(outp, Ws1, bs1, hsb);
    hemi_fin_kernel<<<1, 256>>>(outp, hsb, Ws2, bs2);
}

// round 17
// speedup vs baseline: 6.7340x; 1.1030x over previous
#include <cuda_runtime.h>
#include <cuda_bf16.h>
#include <cstdint>

#define NNODE 4096
#define FIN   4096
#define H1    120
#define HEADS 4
#define H1P   30
#define H2    50

// ---------------- scratch (static device globals; no allocation) ----------------
__device__ float g_wh1[NNODE * H1];
__device__ float g_hmid[NNODE * H1];
__device__ float g_wh2[NNODE * H2];
__device__ float g_h2[NNODE * H2];
__device__ float g_f1a[HEADS * NNODE], g_f2a[HEADS * NNODE];
__device__ float g_Ca[HEADS * NNODE], g_Ba[HEADS * NNODE], g_Da[HEADS * NNODE];
__device__ float g_f1b[NNODE], g_f2b[NNODE];
__device__ float g_Cb[NNODE], g_Bb[NNODE], g_Db[NNODE];
__device__ unsigned char g_adj8[NNODE * NNODE];   // 16MB packed adjacency
__device__ float g_part[4 * 8 * NNODE * 32];      // partials
__device__ float g_wtr[128 * FIN];                // W1 transposed, K-major
__device__ uint4 g_whp1[HEADS * 128 * 8 * 32];    // attn1 packed WH (2MB)
__device__ uint4 g_whp2[128 * 8 * 64];            // attn2 packed WH (1MB)
__device__ float g_hs[240];                       // hemi hidden

__device__ __forceinline__ float leakyf(float x) { return fmaxf(x, 0.1f * x); }

// ---------------- mma.sync / pack helpers ----------------
__device__ __forceinline__ void mma1688(float c[4], uint32_t a0, uint32_t a1,
                                        uint32_t a2, uint32_t a3,
                                        uint32_t b0, uint32_t b1) {
    asm volatile(
        "mma.sync.aligned.m16n8k8.row.col.f32.tf32.tf32.f32 "
        "{%0,%1,%2,%3}, {%4,%5,%6,%7}, {%8,%9}, {%0,%1,%2,%3};"
        : "+f"(c[0]), "+f"(c[1]), "+f"(c[2]), "+f"(c[3])
        : "r"(a0), "r"(a1), "r"(a2), "r"(a3), "r"(b0), "r"(b1));
}
__device__ __forceinline__ void mma_bf16(float c[4], uint32_t a0, uint32_t a1,
                                         uint32_t a2, uint32_t a3,
                                         uint32_t b0, uint32_t b1) {
    asm volatile(
        "mma.sync.aligned.m16n8k16.row.col.f32.bf16.bf16.f32 "
        "{%0,%1,%2,%3}, {%4,%5,%6,%7}, {%8,%9}, {%0,%1,%2,%3};"
        : "+f"(c[0]), "+f"(c[1]), "+f"(c[2]), "+f"(c[3])
        : "r"(a0), "r"(a1), "r"(a2), "r"(a3), "r"(b0), "r"(b1));
}
__device__ __forceinline__ void split_bits(float v, uint32_t& hi, uint32_t& lo) {
    uint32_t h = __float_as_uint(v) & 0xFFFFE000u;
    hi = h;
    lo = __float_as_uint(v - __uint_as_float(h));
}
__device__ __forceinline__ uint32_t packhi(float x, float y) {
    return __byte_perm(__float_as_uint(x), __float_as_uint(y), 0x7632);
}
__device__ __forceinline__ float trunc_res(float v) {
    return v - __uint_as_float(__float_as_uint(v) & 0xFFFF0000u);
}

#define CP16(dst_u32, src_ptr) \
    asm volatile("cp.async.cg.shared.global [%0], [%1], 16;" \
                 :: "r"(dst_u32), "l"(src_ptr) : "memory")
#define CP_COMMIT() asm volatile("cp.async.commit_group;" ::: "memory")
#define CP_WAIT1() asm volatile("cp.async.wait_group 1;" ::: "memory")
#define CP_WAIT0() asm volatile("cp.async.wait_group 0;" ::: "memory")

// ---------------- fused prep: pack adj + transpose W1 ----------------
__global__ void prep_kernel(const int4* __restrict__ adj, uchar4* __restrict__ adj8,
                            const float* __restrict__ W1, float* __restrict__ wtr) {
    int bid = blockIdx.x;
    if (bid < 16384) {
        int i = bid * 256 + threadIdx.x;
        int4 v = adj[i];
        adj8[i] = make_uchar4(v.x ? 1 : 0, v.y ? 1 : 0, v.z ? 1 : 0, v.w ? 1 : 0);
    } else {
        int idx = (bid - 16384) * 256 + threadIdx.x;
        int c = idx >> 10;
        int k4 = (idx & 1023) * 4;
        float4 v = make_float4(0.f, 0.f, 0.f, 0.f);
        if (c < H1) {
            int h = c / 30, o = c % 30;
            const float* base = W1 + ((size_t)h * FIN) * H1P + o;
            v.x = base[(size_t)(k4 + 0) * H1P];
            v.y = base[(size_t)(k4 + 1) * H1P];
            v.z = base[(size_t)(k4 + 2) * H1P];
            v.w = base[(size_t)(k4 + 3) * H1P];
        }
        *(float4*)(wtr + (size_t)c * FIN + k4) = v;
    }
}

// ---------------- GEMM1 via mma.sync TF32, 3-way fp32 split ----------------
#define G1_BM 64
#define G1_LDS 36
#define G1_ASZ (G1_BM * G1_LDS)
#define G1_BSZ (128 * G1_LDS)
#define G1_STAGE (G1_ASZ + G1_BSZ)

__global__ void __launch_bounds__(256, 1)
gemm1_mma_kernel(const float* __restrict__ x, const float* __restrict__ wtr,
                 float* __restrict__ part) {
    extern __shared__ float sm[];
    const int tid = threadIdx.x;
    const int wid = tid >> 5;
    const int lane = tid & 31;
    const int lq = lane >> 2, lr = lane & 3;
    const int warp_m = wid >> 1;
    const int warp_n = wid & 1;
    const int m0 = blockIdx.x * G1_BM;
    const int ks = blockIdx.y;
    const int k0base = ks * (FIN / 2);
    const int NT = (FIN / 2) / 32;

    float acc[8][4];
#pragma unroll
    for (int nt = 0; nt < 8; nt++)
#pragma unroll
        for (int i = 0; i < 4; i++) acc[nt][i] = 0.f;

    float4 aP[2], bP[4];
#pragma unroll
    for (int i = 0; i < 2; i++) {
        int u = tid + i * 256;
        int r = u >> 3, c4 = u & 7;
        aP[i] = *(const float4*)(x + (size_t)(m0 + r) * FIN + k0base + c4 * 4);
    }
#pragma unroll
    for (int i = 0; i < 4; i++) {
        int u = tid + i * 256;
        int r = u >> 3, c4 = u & 7;
        bP[i] = *(const float4*)(wtr + (size_t)r * FIN + k0base + c4 * 4);
    }

    for (int t = 0; t < NT; t++) {
        const int b = t & 1;
        float* As = sm + b * G1_STAGE;
        float* Bs = As + G1_ASZ;
#pragma unroll
        for (int i = 0; i < 2; i++) {
            int u = tid + i * 256;
            int r = u >> 3, c4 = u & 7;
            *(float4*)(As + r * G1_LDS + c4 * 4) = aP[i];
        }
#pragma unroll
        for (int i = 0; i < 4; i++) {
            int u = tid + i * 256;
            int r = u >> 3, c4 = u & 7;
            *(float4*)(Bs + r * G1_LDS + c4 * 4) = bP[i];
        }
        __syncthreads();
        if (t + 1 < NT) {
            int kn = k0base + (t + 1) * 32;
#pragma unroll
            for (int i = 0; i < 2; i++) {
                int u = tid + i * 256;
                int r = u >> 3, c4 = u & 7;
                aP[i] = *(const float4*)(x + (size_t)(m0 + r) * FIN + kn + c4 * 4);
            }
#pragma unroll
            for (int i = 0; i < 4; i++) {
                int u = tid + i * 256;
                int r = u >> 3, c4 = u & 7;
                bP[i] = *(const float4*)(wtr + (size_t)r * FIN + kn + c4 * 4);
            }
        }
#pragma unroll
        for (int k8 = 0; k8 < 4; k8++) {
            const int rowA = warp_m * 16 + lq;
            const int colA = k8 * 8 + lr;
            float a0f = As[rowA * G1_LDS + colA];
            float a1f = As[(rowA + 8) * G1_LDS + colA];
            float a2f = As[rowA * G1_LDS + colA + 4];
            float a3f = As[(rowA + 8) * G1_LDS + colA + 4];
            uint32_t ah[4], al[4];
            split_bits(a0f, ah[0], al[0]);
            split_bits(a1f, ah[1], al[1]);
            split_bits(a2f, ah[2], al[2]);
            split_bits(a3f, ah[3], al[3]);
#pragma unroll
            for (int nt = 0; nt < 8; nt++) {
                const int rowB = warp_n * 64 + nt * 8 + lq;
                float b0f = Bs[rowB * G1_LDS + k8 * 8 + lr];
                float b1f = Bs[rowB * G1_LDS + k8 * 8 + lr + 4];
                uint32_t bh0, bl0, bh1, bl1;
                split_bits(b0f, bh0, bl0);
                split_bits(b1f, bh1, bl1);
                mma1688(acc[nt], ah[0], ah[1], ah[2], ah[3], bh0, bh1);
                mma1688(acc[nt], al[0], al[1], al[2], al[3], bh0, bh1);
                mma1688(acc[nt], ah[0], ah[1], ah[2], ah[3], bl0, bl1);
            }
        }
        __syncthreads();
    }

    const int row0 = m0 + warp_m * 16 + lq;
    float* base = part + ((size_t)ks * NNODE) * 120;
#pragma unroll
    for (int nt = 0; nt < 8; nt++) {
        int col = warp_n * 64 + nt * 8 + lr * 2;
        if (col < 120) {
            base[(size_t)row0 * 120 + col] = acc[nt][0];
            base[(size_t)row0 * 120 + col + 1] = acc[nt][1];
            base[(size_t)(row0 + 8) * 120 + col] = acc[nt][2];
            base[(size_t)(row0 + 8) * 120 + col + 1] = acc[nt][3];
        }
    }
}

// ---------------- warp-per-(h,n): combine gemm1 K-partials + attn1 features ------
__global__ void fcalc_combine1_warp(const float* __restrict__ part,
                                    const float* __restrict__ asrc,
                                    const float* __restrict__ adst,
                                    float* __restrict__ wh1,
                                    float* __restrict__ f1r, float* __restrict__ f2r,
                                    float* __restrict__ Cb, float* __restrict__ Bb,
                                    float* __restrict__ Db) {
    int g = (blockIdx.x * blockDim.x + threadIdx.x) >> 5;
    int lane = threadIdx.x & 31;
    int h = g >> 12;
    int n = g & 4095;
    float f1 = 0.f, f2 = 0.f;
    if (lane < H1P) {
        int c = h * H1P + lane;
        float v = part[(size_t)n * 120 + c] + part[((size_t)NNODE + n) * 120 + c];
        wh1[(size_t)n * H1 + c] = v;
        f1 = v * asrc[h * H1P + lane];
        f2 = v * adst[h * H1P + lane];
    }
#pragma unroll
    for (int off = 16; off; off >>= 1) {
        f1 += __shfl_xor_sync(0xffffffffu, f1, off);
        f2 += __shfl_xor_sync(0xffffffffu, f2, off);
    }
    if (lane == 0) {
        f1r[g] = f1;
        f2r[g] = f2;
        Cb[g] = expf(fminf(-0.9f * f1, 70.f));
        Bb[g] = expf(fminf(f2, 70.f));
        Db[g] = expf(0.1f * fminf(f2, 70.f));
    }
}

// ---------------- pack WH into fragment-ready bf16 hi/lo tables ----------------
// layout per (h, tile): [ks(2)][lr(4)][cn_swizzled(NTC)] uint4 {b0h, b0l, b1h, b1l}
// b0 pair = tile rows (16ks + 2lr, +1), b1 pair = (16ks + 8 + 2lr, +1), col cn.
template <int NCOL, int NTC, int NH>
__global__ void wh_pack_kernel(const float* __restrict__ wh, int ldwh,
                               uint4* __restrict__ out) {
    int idx = blockIdx.x * blockDim.x + threadIdx.x;  // NH*128*2*4*NTC
    int cn = idx % NTC;
    int lr = (idx / NTC) & 3;
    int ks = (idx / (NTC * 4)) & 1;
    int tile = (idx / (NTC * 8)) & 127;
    int h = idx / (NTC * 8 * 128);
    int colofs = h * NCOL;
    int jb0 = tile * 32 + ks * 16 + 2 * lr;
    float v00, v01, v10, v11;
    if (cn < NCOL) {
        v00 = wh[(size_t)jb0 * ldwh + colofs + cn];
        v01 = wh[(size_t)(jb0 + 1) * ldwh + colofs + cn];
        v10 = wh[(size_t)(jb0 + 8) * ldwh + colofs + cn];
        v11 = wh[(size_t)(jb0 + 9) * ldwh + colofs + cn];
    } else {
        v00 = v01 = v10 = v11 = (cn == NCOL) ? 1.f : 0.f;
    }
    uint4 w;
    w.x = packhi(v00, v01);
    w.y = packhi(trunc_res(v00), trunc_res(v01));
    w.z = packhi(v10, v11);
    w.w = packhi(trunc_res(v10), trunc_res(v11));
    out[(((size_t)(h * 128 + tile) * 2 + ks) * 4 + lr) * NTC + (cn ^ (2 * lr))] = w;
}

// ---------------- bf16 tensor-core attention: cp.async 3-stage pipeline ---------
// p = adj ? ((f1+f2>=0) ? B : C*D) : 0; 2x2 bf16 split (P0W0+P1W0+P0W1).
// Z column (1.0, exact) carries the softmax normalizer.
template <int NCOL, int NT, int NTC, int JS, int OSTR>
__global__ void __launch_bounds__(256)
attn_cp_kernel(const uint4* __restrict__ whp,
               const float* __restrict__ f1r,
               const float* __restrict__ Cb, const float* __restrict__ Bb,
               const float* __restrict__ Db, const float* __restrict__ f2r,
               const unsigned char* __restrict__ adj8,
               float* __restrict__ dst) {
    constexpr int WCNT = 8 * NTC;  // uint4 per tile of packed WH
    __shared__ uint4 whP[3][2][4][NTC];          // [buf][ks][lr][cn]
    __shared__ unsigned char adjs[3][128][32];
    __shared__ float BDF[3][3][32];

    const int tid = threadIdx.x;
    const int wid = tid >> 5;
    const int lane = tid & 31;
    const int lq = lane >> 2, lr = lane & 3;
    const int h = blockIdx.y;
    const int i0 = blockIdx.x * 128;
    const int js = blockIdx.z;
    const int jbeg = js * (NNODE / JS);
    const int tile0 = jbeg >> 5;
    const int ntiles = (NNODE / JS) / 32;
    const int fo = h * NNODE;

    const int r0 = wid * 16 + lq;
    const float f1_0 = f1r[fo + i0 + r0];
    const float f1_1 = f1r[fo + i0 + r0 + 8];
    const float C_0 = Cb[fo + i0 + r0];
    const float C_1 = Cb[fo + i0 + r0 + 8];

    float acc[NT][4];
#pragma unroll
    for (int nt = 0; nt < NT; nt++)
#pragma unroll
        for (int i = 0; i < 4; i++) acc[nt][i] = 0.f;

    auto issue_tile = [&](int t) {
        const int buf = t % 3;
        const int j0 = jbeg + t * 32;
        // packed WH (coalesced, contiguous)
        const uint4* g = whp + (size_t)(h * 128 + tile0 + t) * WCNT;
        uint32_t s_wh = (uint32_t)__cvta_generic_to_shared(&whP[buf][0][0][0]);
#pragma unroll
        for (int i = 0; i < WCNT / 256; i++) {
            int u = tid + i * 256;
            CP16(s_wh + u * 16, g + u);
        }
        // adjacency rows
        uint32_t s_adj = (uint32_t)__cvta_generic_to_shared(&adjs[buf][0][0]);
        CP16(s_adj + tid * 16,
             adj8 + (size_t)(i0 + (tid >> 1)) * NNODE + j0 + (tid & 1) * 16);
        // B/D/F2
        if (tid < 24) {
            int which = tid >> 3, q = tid & 7;
            const float* src = (which == 0) ? Bb : (which == 1) ? Db : f2r;
            uint32_t s_bdf = (uint32_t)__cvta_generic_to_shared(&BDF[buf][which][q * 4]);
            CP16(s_bdf, src + fo + j0 + q * 4);
        }
        CP_COMMIT();
    };

    issue_tile(0);
    if (1 < ntiles) issue_tile(1);

    for (int t = 0; t < ntiles; t++) {
        const int b = t % 3;
        if (t + 1 < ntiles) CP_WAIT1();
        else CP_WAIT0();
        __syncthreads();  // data visible + all warps done with buf being re-issued
        if (t + 2 < ntiles) issue_tile(t + 2);

#pragma unroll
        for (int ks = 0; ks < 2; ks++) {
            const int jb = ks * 16 + 2 * lr;
            unsigned t0 = *(const unsigned short*)&adjs[b][r0][jb];
            unsigned t1 = *(const unsigned short*)&adjs[b][r0][jb + 8];
            unsigned u0 = *(const unsigned short*)&adjs[b][r0 + 8][jb];
            unsigned u1 = *(const unsigned short*)&adjs[b][r0 + 8][jb + 8];
            float2 Bv0 = *(const float2*)&BDF[b][0][jb];
            float2 Bv1 = *(const float2*)&BDF[b][0][jb + 8];
            float2 Dv0 = *(const float2*)&BDF[b][1][jb];
            float2 Dv1 = *(const float2*)&BDF[b][1][jb + 8];
            float2 Fv0 = *(const float2*)&BDF[b][2][jb];
            float2 Fv1 = *(const float2*)&BDF[b][2][jb + 8];

            auto mkp = [](unsigned a, float f1, float C, float B, float D, float F) {
                float v = (f1 + F >= 0.f) ? B : C * D;
                return a ? v : 0.f;
            };
            float p00 = mkp(t0 & 0xFF, f1_0, C_0, Bv0.x, Dv0.x, Fv0.x);
            float p01 = mkp(t0 >> 8, f1_0, C_0, Bv0.y, Dv0.y, Fv0.y);
            float p02 = mkp(t1 & 0xFF, f1_0, C_0, Bv1.x, Dv1.x, Fv1.x);
            float p03 = mkp(t1 >> 8, f1_0, C_0, Bv1.y, Dv1.y, Fv1.y);
            float p10 = mkp(u0 & 0xFF, f1_1, C_1, Bv0.x, Dv0.x, Fv0.x);
            float p11 = mkp(u0 >> 8, f1_1, C_1, Bv0.y, Dv0.y, Fv0.y);
            float p12 = mkp(u1 & 0xFF, f1_1, C_1, Bv1.x, Dv1.x, Fv1.x);
            float p13 = mkp(u1 >> 8, f1_1, C_1, Bv1.y, Dv1.y, Fv1.y);

            uint32_t a0h = packhi(p00, p01), a1h = packhi(p10, p11);
            uint32_t a2h = packhi(p02, p03), a3h = packhi(p12, p13);
            uint32_t a0l = packhi(trunc_res(p00), trunc_res(p01));
            uint32_t a1l = packhi(trunc_res(p10), trunc_res(p11));
            uint32_t a2l = packhi(trunc_res(p02), trunc_res(p03));
            uint32_t a3l = packhi(trunc_res(p12), trunc_res(p13));

#pragma unroll
            for (int nt = 0; nt < NT; nt++) {
                const int cn = nt * 8 + lq;
                uint4 w = whP[b][ks][lr][cn ^ (2 * lr)];
                mma_bf16(acc[nt], a0h, a1h, a2h, a3h, w.x, w.z);  // P0 @ W0
                mma_bf16(acc[nt], a0l, a1l, a2l, a3l, w.x, w.z);  // P1 @ W0
                mma_bf16(acc[nt], a0h, a1h, a2h, a3h, w.y, w.w);  // P0 @ W1
            }
        }
        __syncthreads();  // all warps done with buf b before it is re-issued
    }

    const size_t rbase = ((size_t)(h * JS + js) * NNODE + i0 + r0) * OSTR;
#pragma unroll
    for (int nt = 0; nt < NT; nt++) {
        int col = nt * 8 + 2 * lr;
        *(float2*)(dst + rbase + col) = make_float2(acc[nt][0], acc[nt][1]);
        *(float2*)(dst + rbase + (size_t)8 * OSTR + col) = make_float2(acc[nt][2], acc[nt][3]);
    }
}

// ---------------- combine partials -> leaky(sum/z + bias) ----------------
template <int NCOL, int CP4, int JS, int NH>
__global__ void combine_kernel(const float* __restrict__ part,
                               const float* __restrict__ bias,
                               float* __restrict__ out, int ldout) {
    int idx = blockIdx.x * blockDim.x + threadIdx.x;
    if (idx >= NNODE * NH * NCOL) return;
    int row = idx / (NH * NCOL);
    int rem = idx % (NH * NCOL);
    int h = rem / NCOL;
    int c = rem % NCOL;
    float s = 0.f, z = 0.f;
#pragma unroll
    for (int js = 0; js < JS; js++) {
        const float* p = part + ((size_t)(h * JS + js) * NNODE + row) * CP4;
        s += p[c];
        z += p[NCOL];
    }
    out[(size_t)row * ldout + h * NCOL + c] = leakyf(s / z + bias[h * NCOL + c]);
}

// ---------------- GEMM2 + fused attn2 features ----------------
__global__ void gemm2_fused_kernel(const float* __restrict__ hmid,
                                   const float* __restrict__ W2,
                                   const float* __restrict__ a2s,
                                   const float* __restrict__ a2d,
                                   float* __restrict__ wh2,
                                   float* __restrict__ f1r, float* __restrict__ f2r,
                                   float* __restrict__ Cb, float* __restrict__ Bb,
                                   float* __restrict__ Db) {
    __shared__ float hs[4][120];
    __shared__ float sacc[4][50];
    const int n0 = blockIdx.x * 4;
    const int tid = threadIdx.x;
    for (int idx = tid; idx < 4 * 120; idx += blockDim.x)
        hs[idx / 120][idx % 120] = hmid[(size_t)(n0 + idx / 120) * H1 + (idx % 120)];
    __syncthreads();
    if (tid < 200) {
        int r = tid / 50, c = tid % 50;
        float acc = 0.f;
#pragma unroll 8
        for (int k = 0; k < 120; k++) acc = fmaf(hs[r][k], W2[k * 50 + c], acc);
        wh2[(size_t)(n0 + r) * H2 + c] = acc;
        sacc[r][c] = acc;
    }
    __syncthreads();
    if (tid < 4) {
        float f1 = 0.f, f2 = 0.f;
#pragma unroll 10
        for (int c = 0; c < 50; c++) {
            float v = sacc[tid][c];
            f1 = fmaf(v, a2s[c], f1);
            f2 = fmaf(v, a2d[c], f2);
        }
        int n = n0 + tid;
        f1r[n] = f1;
        f2r[n] = f2;
        Cb[n] = expf(fminf(-0.9f * f1, 70.f));
        Bb[n] = expf(fminf(f2, 70.f));
        Db[n] = expf(0.1f * fminf(f2, 70.f));
    }
}

// ---------------- FiLM + gating + classifier logits ----------------
__global__ void film_kernel(const float* __restrict__ h2,
                            const float* __restrict__ lloc,
                            const float* __restrict__ Wl1, const float* __restrict__ bl1,
                            const float* __restrict__ Wl2, const float* __restrict__ bl2,
                            const float* __restrict__ Wg, const float* __restrict__ bg,
                            const float* __restrict__ Wb, const float* __restrict__ bb,
                            const float* __restrict__ Wgate, const float* __restrict__ bgate,
                            const float* __restrict__ Wc,
                            float* __restrict__ outlogits) {
    int n = blockIdx.x * blockDim.x + threadIdx.x;
    if (n >= NNODE) return;
    float l[16];
#pragma unroll
    for (int k = 0; k < 16; k++) l[k] = lloc[n * 16 + k];
    float z1[32];
#pragma unroll
    for (int j = 0; j < 32; j++) {
        float a = bl1[j];
#pragma unroll
        for (int k = 0; k < 16; k++) a = fmaf(l[k], Wl1[j * 16 + k], a);
        z1[j] = leakyf(a);
    }
    float z2[32];
#pragma unroll
    for (int j = 0; j < 32; j++) {
        float a = bl2[j];
#pragma unroll
        for (int k = 0; k < 32; k++) a = fmaf(z1[k], Wl2[j * 32 + k], a);
        z2[j] = leakyf(a);
    }
    float ga = bgate[0];
#pragma unroll
    for (int k = 0; k < 32; k++) ga = fmaf(z2[k], Wgate[k], ga);
    float g = 1.f / (1.f + expf(-ga));
    float cov = fminf(fmaxf(l[15], 0.f), 1.f);
    g *= cov;

    float l0 = 0.f, l1 = 0.f;
    for (int c = 0; c < 50; c++) {
        float gm = bg[c], bt = bb[c];
#pragma unroll
        for (int k = 0; k < 32; k++) {
            gm = fmaf(z2[k], Wg[c * 32 + k], gm);
            bt = fmaf(z2[k], Wb[c * 32 + k], bt);
        }
        float hv = h2[(size_t)n * H2 + c];
        float hf = hv + g * fmaf(gm, hv, bt);
        l0 = fmaf(hf, Wc[c], l0);
        l1 = fmaf(hf, Wc[50 + c], l1);
    }
    outlogits[n * 2 + 0] = leakyf(l0);
    outlogits[n * 2 + 1] = leakyf(l1);
}

// ---------------- hemisphere SSDB ----------------
__global__ void hemi_dots_kernel(const float* __restrict__ out,
                                 const float* __restrict__ Ws1,
                                 const float* __restrict__ bs1,
                                 float* __restrict__ hs) {
    const int b = blockIdx.x;
    const int hemi = b / 120;
    const int cls = (b / 60) % 2;
    const int k = b % 60;
    const int tid = threadIdx.x;
    const float* lg = out + (size_t)hemi * 2048 * 2 + cls;
    const float* w = Ws1 + (size_t)k * 2048;
    float acc = 0.f;
    for (int m = tid; m < 2048; m += 128) acc = fmaf(lg[2 * m], w[m], acc);
#pragma unroll
    for (int off = 16; off; off >>= 1) acc += __shfl_xor_sync(0xffffffffu, acc, off);
    __shared__ float red[4];
    if ((tid & 31) == 0) red[tid >> 5] = acc;
    __syncthreads();
    if (tid == 0)
        hs[b] = leakyf(red[0] + red[1] + red[2] + red[3] + bs1[k]);
}

__global__ void hemi_fin_kernel(float* __restrict__ out,
                                const float* __restrict__ hs,
                                const float* __restrict__ Ws2,
                                const float* __restrict__ bs2) {
    __shared__ float bsm[4];
    const int tid = threadIdx.x;
    if (tid < 4) {
        int hemi = tid >> 1, cls = tid & 1;
        float acc = bs2[0];
#pragma unroll
        for (int k = 0; k < 60; k++) acc = fmaf(hs[hemi * 120 + cls * 60 + k], Ws2[k], acc);
        bsm[hemi * 2 + cls] = leakyf(acc);
    }
    __syncthreads();
    for (int idx = tid; idx < NNODE * 2; idx += blockDim.x) {
        int n = idx >> 1, cls = idx & 1;
        int hemi = (n >= 2048) ? 1 : 0;
        out[idx] += bsm[hemi * 2 + cls];
    }
    if (tid < 2) out[NNODE * 2 + tid] = 0.5f * (bsm[tid] + bsm[2 + tid]);
}

// ---------------- host launch ----------------
extern "C" void kernel_launch(void* const* d_in, const int* in_sizes, int n_in,
                              void* d_out, int out_size) {
    const float* x_fc  = (const float*)d_in[0];
    const int*   adj   = (const int*)d_in[1];
    const float* lloc  = (const float*)d_in[2];
    const float* W1    = (const float*)d_in[3];
    const float* a1s   = (const float*)d_in[4];
    const float* a1d   = (const float*)d_in[5];
    const float* b1    = (const float*)d_in[6];
    const float* W2    = (const float*)d_in[7];
    const float* a2s   = (const float*)d_in[8];
    const float* a2d   = (const float*)d_in[9];
    const float* b2    = (const float*)d_in[10];
    const float* Wc    = (const float*)d_in[11];
    const float* Wl1   = (const float*)d_in[12];
    const float* bl1   = (const float*)d_in[13];
    const float* Wl2   = (const float*)d_in[14];
    const float* bl2   = (const float*)d_in[15];
    const float* Wg    = (const float*)d_in[16];
    const float* bg    = (const float*)d_in[17];
    const float* Wb    = (const float*)d_in[18];
    const float* bb    = (const float*)d_in[19];
    const float* Wgate = (const float*)d_in[20];
    const float* bgate = (const float*)d_in[21];
    const float* Ws1   = (const float*)d_in[22];
    const float* bs1   = (const float*)d_in[23];
    const float* Ws2   = (const float*)d_in[24];
    const float* bs2   = (const float*)d_in[25];
    float* outp = (float*)d_out;

    float *wh1, *hmid, *wh2, *h2, *part, *hsb, *wtr;
    float *f1a, *f2a, *Ca, *Ba, *Da, *f1b, *f2b, *Cb2, *Bb2, *Db2;
    unsigned char* adj8;
    uint4 *whp1, *whp2;
    cudaGetSymbolAddress((void**)&wh1, g_wh1);
    cudaGetSymbolAddress((void**)&hmid, g_hmid);
    cudaGetSymbolAddress((void**)&wh2, g_wh2);
    cudaGetSymbolAddress((void**)&h2, g_h2);
    cudaGetSymbolAddress((void**)&f1a, g_f1a);
    cudaGetSymbolAddress((void**)&f2a, g_f2a);
    cudaGetSymbolAddress((void**)&Ca, g_Ca);
    cudaGetSymbolAddress((void**)&Ba, g_Ba);
    cudaGetSymbolAddress((void**)&Da, g_Da);
    cudaGetSymbolAddress((void**)&f1b, g_f1b);
    cudaGetSymbolAddress((void**)&f2b, g_f2b);
    cudaGetSymbolAddress((void**)&Cb2, g_Cb);
    cudaGetSymbolAddress((void**)&Bb2, g_Bb);
    cudaGetSymbolAddress((void**)&Db2, g_Db);
    cudaGetSymbolAddress((void**)&adj8, g_adj8);
    cudaGetSymbolAddress((void**)&part, g_part);
    cudaGetSymbolAddress((void**)&hsb, g_hs);
    cudaGetSymbolAddress((void**)&wtr, g_wtr);
    cudaGetSymbolAddress((void**)&whp1, g_whp1);
    cudaGetSymbolAddress((void**)&whp2, g_whp2);

    // 1) fused prep (pack adj + transpose W1)
    prep_kernel<<<16384 + 512, 256>>>((const int4*)adj, (uchar4*)adj8, W1, wtr);
    // 2) wh1 partials via mma.sync TF32 x3 (K-split 2)
    cudaFuncSetAttribute(gemm1_mma_kernel, cudaFuncAttributeMaxDynamicSharedMemorySize,
                         2 * G1_STAGE * (int)sizeof(float));
    gemm1_mma_kernel<<<dim3(NNODE / G1_BM, 2), 256, 2 * G1_STAGE * sizeof(float)>>>(
        x_fc, wtr, part);
    // 3) combine K-partials -> wh1 + attn1 features
    fcalc_combine1_warp<<<HEADS * NNODE * 32 / 256, 256>>>(part, a1s, a1d, wh1,
                                                           f1a, f2a, Ca, Ba, Da);
    // 4) pack wh1 -> fragment tables
    wh_pack_kernel<30, 32, HEADS><<<HEADS * 128 * 8 * 32 / 256, 256>>>(wh1, H1, whp1);
    // 5) GAT1 attention (cp.async pipeline, JS=8) -> partials; combine -> hmid
    attn_cp_kernel<30, 4, 32, 8, 32><<<dim3(NNODE / 128, HEADS, 8), 256>>>(
        whp1, f1a, Ca, Ba, Da, f2a, adj8, part);
    combine_kernel<30, 32, 8, HEADS><<<(NNODE * HEADS * 30 + 255) / 256, 256>>>(
        part, b1, hmid, H1);
    // 6) wh2 = hmid @ W2 (+ fused attn2 features)
    gemm2_fused_kernel<<<NNODE / 4, 256>>>(hmid, W2, a2s, a2d, wh2,
                                           f1b, f2b, Cb2, Bb2, Db2);
    // 7) pack wh2 -> fragment tables
    wh_pack_kernel<50, 64, 1><<<128 * 8 * 64 / 256, 256>>>(wh2, H2, whp2);
    // 8) GAT2 attention (cp.async pipeline, JS=16) -> partials; combine -> h2
    attn_cp_kernel<50, 7, 64, 16, 64><<<dim3(NNODE / 128, 1, 16), 256>>>(
        whp2, f1b, Cb2, Bb2, Db2, f2b, adj8, part);
    combine_kernel<50, 64, 16, 1><<<(NNODE * H2 + 255) / 256, 256>>>(
        part, b2, h2, H2);
    // 9) FiLM + classifier -> logits
    film_kernel<<<NNODE / 128, 128>>>(h2, lloc, Wl1, bl1, Wl2, bl2,
                                      Wg, bg, Wb, bb, Wgate, bgate, Wc, outp);
    // 10) hemisphere bias
    hemi_dots_kernel<<<240, 128>>>(outp, Ws1, bs1, hsb);
    hemi_fin_kernel<<<1, 256>>>(outp, hsb, Ws2, bs2);
}